// round 8
// baseline (speedup 1.0000x reference)
#include <cuda_runtime.h>
#include <cstdint>

#define EMB 64
#define NN_MAX 50000
#define NSCAN 50176          // 49 * 1024
#define NE_MAX 800000
#define NE_PAD (NE_MAX + 64)

// ---------------- scratch (static device memory; no allocations) ----------------
__device__ __align__(128) float g_h  [NN_MAX * EMB];
__device__ __align__(128) float g_Pab[NN_MAX * 128];   // [Pa | Pb] per node
__device__ __align__(128) float g_agg[NN_MAX * EMB];   // zero at launch entry (invariant)
__device__ int g_is64;

// sort scratch
__device__ int   g_cnt [NSCAN];
__device__ int   g_inc [NSCAN];
__device__ int   g_cur [NSCAN];
__device__ int   g_bsum[64];
__device__ __align__(128) int   g_srcS[NE_PAD];
__device__ __align__(128) int   g_dstS[NE_PAD];
__device__ __align__(128) float g_eaS [NE_PAD * 6];

// ---------------- helpers ------------------------------------------------------
__device__ __forceinline__ uint32_t f32_to_tf32(float f) {
    uint32_t u;
    asm("cvt.rna.tf32.f32 %0, %1;" : "=r"(u) : "f"(f));
    return u;
}
__device__ __forceinline__ void mma_tf32(float* c, const uint32_t* a, const uint32_t* b) {
    asm volatile(
        "mma.sync.aligned.m16n8k8.row.col.f32.tf32.tf32.f32 "
        "{%0,%1,%2,%3}, {%4,%5,%6,%7}, {%8,%9}, {%0,%1,%2,%3};"
        : "+f"(c[0]), "+f"(c[1]), "+f"(c[2]), "+f"(c[3])
        : "r"(a[0]), "r"(a[1]), "r"(a[2]), "r"(a[3]), "r"(b[0]), "r"(b[1]));
}

// ---------------- detect whether edge_index is int64 or int32 ----------------
__global__ void detect_idx_kernel(const unsigned int* __restrict__ p)
{
    if (threadIdx.x == 0 && blockIdx.x == 0) {
        unsigned int v = 0;
#pragma unroll
        for (int k = 0; k < 64; k++) v |= p[2 * k + 1];
        g_is64 = (v == 0) ? 1 : 0;
    }
}

// ---------------- counting sort by dst ----------------------------------------
__global__ void hist_kernel(const void* __restrict__ ei, int E)
{
    const int is64 = g_is64;
    for (long long e = (long long)blockIdx.x * blockDim.x + threadIdx.x; e < E;
         e += (long long)gridDim.x * blockDim.x) {
        int dst = is64 ? (int)((const long long*)ei)[(long long)E + e]
                       : ((const int*)ei)[(long long)E + e];
        atomicAdd(&g_cnt[dst], 1);
    }
}

__global__ __launch_bounds__(1024) void scan1_kernel()
{
    const int t = threadIdx.x, b = blockIdx.x;
    const int i = b * 1024 + t;
    const int lane = t & 31, wid = t >> 5;
    int x = g_cnt[i];
#pragma unroll
    for (int s = 1; s < 32; s <<= 1) {
        int u = __shfl_up_sync(0xffffffffu, x, s);
        if (lane >= s) x += u;
    }
    __shared__ int ws[32];
    if (lane == 31) ws[wid] = x;
    __syncthreads();
    if (wid == 0) {
        int y = ws[lane];
#pragma unroll
        for (int s = 1; s < 32; s <<= 1) {
            int u = __shfl_up_sync(0xffffffffu, y, s);
            if (lane >= s) y += u;
        }
        ws[lane] = y;
    }
    __syncthreads();
    int inc = x + (wid ? ws[wid - 1] : 0);
    g_inc[i] = inc;
    if (t == 1023) g_bsum[b] = inc;
}

__global__ void scan2_kernel(int nb)
{
    if (threadIdx.x == 0 && blockIdx.x == 0) {
        int run = 0;
        for (int b = 0; b < nb; b++) { int t = g_bsum[b]; g_bsum[b] = run; run += t; }
    }
}

__global__ __launch_bounds__(1024) void scan3_kernel()
{
    const int i = blockIdx.x * 1024 + threadIdx.x;
    g_cur[i] = g_inc[i] - g_cnt[i] + g_bsum[blockIdx.x];
}

__global__ void scatter_kernel(const void* __restrict__ ei,
                               const float* __restrict__ eattr, int E)
{
    const int is64 = g_is64;
    for (long long e = (long long)blockIdx.x * blockDim.x + threadIdx.x; e < E;
         e += (long long)gridDim.x * blockDim.x) {
        int src, dst;
        if (is64) {
            src = (int)((const long long*)ei)[e];
            dst = (int)((const long long*)ei)[(long long)E + e];
        } else {
            src = ((const int*)ei)[e];
            dst = ((const int*)ei)[(long long)E + e];
        }
        int pos = atomicAdd(&g_cur[dst], 1);
        g_srcS[pos] = src;
        g_dstS[pos] = dst;
#pragma unroll
        for (int q = 0; q < 6; q++) g_eaS[(long long)pos * 6 + q] = eattr[e * 6 + q];
    }
}

// ---------------- proj8: h = x(Mx128) @ W(128x64) + b  (fp32 SIMT 8x8) ---------
__global__ __launch_bounds__(128)
void proj8(const float* __restrict__ x, const float* __restrict__ W,
           const float* __restrict__ b, float* __restrict__ C, int M)
{
    __shared__ __align__(16) float sA[16 * 128];
    __shared__ __align__(16) float sW[16 * 100];

    const int tid = threadIdx.x;
    const int rg = tid >> 3, cg = tid & 7;
    const int r0 = rg * 8, c0 = cg * 8;
    const long long row0 = (long long)blockIdx.x * 128;

    float acc[8][8];
#pragma unroll
    for (int j = 0; j < 8; j++) {
        float bv = b[c0 + j];
#pragma unroll
        for (int i = 0; i < 8; i++) acc[i][j] = bv;
    }

    for (int kc = 0; kc < 128; kc += 16) {
        // stage A: thread = row
        {
            const long long grow = row0 + tid;
#pragma unroll
            for (int q = 0; q < 4; q++) {
                float4 v = make_float4(0.f, 0.f, 0.f, 0.f);
                if (grow < M) v = *(const float4*)(x + grow * 128 + kc + 4 * q);
                sA[(4 * q + 0) * 128 + tid] = v.x;
                sA[(4 * q + 1) * 128 + tid] = v.y;
                sA[(4 * q + 2) * 128 + tid] = v.z;
                sA[(4 * q + 3) * 128 + tid] = v.w;
            }
        }
        // stage W: 256 float4, 2 per thread
#pragma unroll
        for (int s = 0; s < 2; s++) {
            const int f = tid * 2 + s;
            const int kk = f >> 4, n4 = (f & 15) * 4;
            float4 v = *(const float4*)(W + (long long)(kc + kk) * 64 + n4);
            *(float4*)&sW[kk * 100 + 12 * (n4 >> 3) + (n4 & 4)] = v;
        }
        __syncthreads();
#pragma unroll
        for (int kk = 0; kk < 16; kk++) {
            float4 a0 = *(const float4*)&sA[kk * 128 + r0];
            float4 a1 = *(const float4*)&sA[kk * 128 + r0 + 4];
            float4 w0 = *(const float4*)&sW[kk * 100 + 12 * cg];
            float4 w1 = *(const float4*)&sW[kk * 100 + 12 * cg + 4];
            float ar[8] = {a0.x, a0.y, a0.z, a0.w, a1.x, a1.y, a1.z, a1.w};
            float wr[8] = {w0.x, w0.y, w0.z, w0.w, w1.x, w1.y, w1.z, w1.w};
#pragma unroll
            for (int i = 0; i < 8; i++)
#pragma unroll
                for (int j = 0; j < 8; j++)
                    acc[i][j] = fmaf(ar[i], wr[j], acc[i][j]);
        }
        __syncthreads();
    }

#pragma unroll
    for (int i = 0; i < 8; i++) {
        const long long row = row0 + r0 + i;
        if (row < M) {
            *(float4*)(C + row * 64 + c0)     = make_float4(acc[i][0], acc[i][1], acc[i][2], acc[i][3]);
            *(float4*)(C + row * 64 + c0 + 4) = make_float4(acc[i][4], acc[i][5], acc[i][6], acc[i][7]);
        }
    }
}

// ---------------- dual8: Pab = [h@W1a + b1 | h@W1b]  (fp32 SIMT 8x8) -----------
__global__ __launch_bounds__(256)
void dual8(const float* __restrict__ h, const float* __restrict__ W1,
           const float* __restrict__ b1, float* __restrict__ Pab, int M)
{
    __shared__ __align__(16) float sA[16 * 128];
    __shared__ __align__(16) float sW[16 * 192];

    const int tid = threadIdx.x;
    const int rg = tid >> 4, cg = tid & 15;
    const int r0 = rg * 8, c0 = cg * 8;
    const long long row0 = (long long)blockIdx.x * 128;

    float acc[8][8];
#pragma unroll
    for (int j = 0; j < 8; j++) {
        float bv = (c0 < 64) ? b1[c0 + j] : 0.0f;
#pragma unroll
        for (int i = 0; i < 8; i++) acc[i][j] = bv;
    }

    for (int kc = 0; kc < 64; kc += 16) {
        // stage A: r = tid&127, half = tid>>7
        {
            const int r = tid & 127, half = tid >> 7;
            const long long grow = row0 + r;
#pragma unroll
            for (int q = 0; q < 2; q++) {
                float4 v = make_float4(0.f, 0.f, 0.f, 0.f);
                if (grow < M) v = *(const float4*)(h + grow * 64 + kc + 8 * half + 4 * q);
                const int k = 8 * half + 4 * q;
                sA[(k + 0) * 128 + r] = v.x;
                sA[(k + 1) * 128 + r] = v.y;
                sA[(k + 2) * 128 + r] = v.z;
                sA[(k + 3) * 128 + r] = v.w;
            }
        }
        // stage W: 512 float4, 2 per thread
#pragma unroll
        for (int s = 0; s < 2; s++) {
            const int f = tid * 2 + s;
            const int kk = f >> 5, n4 = (f & 31) * 4;
            float4 v;
            if (n4 < 64) v = *(const float4*)(W1 + (long long)(kc + kk) * 64 + n4);
            else         v = *(const float4*)(W1 + (long long)(64 + kc + kk) * 64 + (n4 - 64));
            *(float4*)&sW[kk * 192 + 12 * (n4 >> 3) + (n4 & 4)] = v;
        }
        __syncthreads();
#pragma unroll
        for (int kk = 0; kk < 16; kk++) {
            float4 a0 = *(const float4*)&sA[kk * 128 + r0];
            float4 a1 = *(const float4*)&sA[kk * 128 + r0 + 4];
            float4 w0 = *(const float4*)&sW[kk * 192 + 12 * cg];
            float4 w1 = *(const float4*)&sW[kk * 192 + 12 * cg + 4];
            float ar[8] = {a0.x, a0.y, a0.z, a0.w, a1.x, a1.y, a1.z, a1.w};
            float wr[8] = {w0.x, w0.y, w0.z, w0.w, w1.x, w1.y, w1.z, w1.w};
#pragma unroll
            for (int i = 0; i < 8; i++)
#pragma unroll
                for (int j = 0; j < 8; j++)
                    acc[i][j] = fmaf(ar[i], wr[j], acc[i][j]);
        }
        __syncthreads();
    }

#pragma unroll
    for (int i = 0; i < 8; i++) {
        const long long row = row0 + r0 + i;
        if (row < M) {
            *(float4*)(Pab + row * 128 + c0)     = make_float4(acc[i][0], acc[i][1], acc[i][2], acc[i][3]);
            *(float4*)(Pab + row * 128 + c0 + 4) = make_float4(acc[i][4], acc[i][5], acc[i][6], acc[i][7]);
        }
    }
}

// ---------------- update8: h += relu(relu([h|agg]@U1+b1)@U2+b2) (fp32 8x8) -----
// Zeroes agg after reading (restores launch-entry invariant).
__global__ __launch_bounds__(128)
void update8(const float* __restrict__ h_in, const float* __restrict__ U1,
             const float* __restrict__ b1, const float* __restrict__ U2,
             const float* __restrict__ b2, float* agg,
             float* __restrict__ h_out, int M)
{
    extern __shared__ __align__(16) char smem[];
    float* sA  = (float*)smem;              // 16 x 128        (8192 B)
    float* sW  = (float*)(smem + 8192);     // 16 x 100        (6400 B)
    float* sU1 = (float*)(smem + 14592);    // 128 x 68        (34816 B)

    const int tid = threadIdx.x;
    const int rg = tid >> 3, cg = tid & 7;
    const int r0 = rg * 8, c0 = cg * 8;
    const long long row0 = (long long)blockIdx.x * 128;

    // phase 1: u1 = relu([h|agg] @ U1 + b1)
    float acc[8][8];
#pragma unroll
    for (int j = 0; j < 8; j++) {
        float bv = b1[c0 + j];
#pragma unroll
        for (int i = 0; i < 8; i++) acc[i][j] = bv;
    }

#pragma unroll
    for (int p = 0; p < 2; p++) {
        const float* A = p ? agg : h_in;
        for (int kc = 0; kc < 64; kc += 16) {
            {
                const long long grow = row0 + tid;
#pragma unroll
                for (int q = 0; q < 4; q++) {
                    float4 v = make_float4(0.f, 0.f, 0.f, 0.f);
                    if (grow < M) {
                        v = *(const float4*)(A + grow * 64 + kc + 4 * q);
                        if (p == 1)
                            *(float4*)(agg + grow * 64 + kc + 4 * q) =
                                make_float4(0.f, 0.f, 0.f, 0.f);
                    }
                    sA[(4 * q + 0) * 128 + tid] = v.x;
                    sA[(4 * q + 1) * 128 + tid] = v.y;
                    sA[(4 * q + 2) * 128 + tid] = v.z;
                    sA[(4 * q + 3) * 128 + tid] = v.w;
                }
            }
#pragma unroll
            for (int s = 0; s < 2; s++) {
                const int f = tid * 2 + s;
                const int kk = f >> 4, n4 = (f & 15) * 4;
                float4 v = *(const float4*)(U1 + (long long)(p * 64 + kc + kk) * 64 + n4);
                *(float4*)&sW[kk * 100 + 12 * (n4 >> 3) + (n4 & 4)] = v;
            }
            __syncthreads();
#pragma unroll
            for (int kk = 0; kk < 16; kk++) {
                float4 a0 = *(const float4*)&sA[kk * 128 + r0];
                float4 a1 = *(const float4*)&sA[kk * 128 + r0 + 4];
                float4 w0 = *(const float4*)&sW[kk * 100 + 12 * cg];
                float4 w1 = *(const float4*)&sW[kk * 100 + 12 * cg + 4];
                float ar[8] = {a0.x, a0.y, a0.z, a0.w, a1.x, a1.y, a1.z, a1.w};
                float wr[8] = {w0.x, w0.y, w0.z, w0.w, w1.x, w1.y, w1.z, w1.w};
#pragma unroll
                for (int i = 0; i < 8; i++)
#pragma unroll
                    for (int j = 0; j < 8; j++)
                        acc[i][j] = fmaf(ar[i], wr[j], acc[i][j]);
            }
            __syncthreads();
        }
    }

    // u1 = relu(acc) -> sU1 row-major (stride 68)
#pragma unroll
    for (int i = 0; i < 8; i++) {
        *(float4*)&sU1[(r0 + i) * 68 + c0] =
            make_float4(fmaxf(acc[i][0], 0.f), fmaxf(acc[i][1], 0.f),
                        fmaxf(acc[i][2], 0.f), fmaxf(acc[i][3], 0.f));
        *(float4*)&sU1[(r0 + i) * 68 + c0 + 4] =
            make_float4(fmaxf(acc[i][4], 0.f), fmaxf(acc[i][5], 0.f),
                        fmaxf(acc[i][6], 0.f), fmaxf(acc[i][7], 0.f));
    }

    // phase 2: acc2 = u1 @ U2 + b2
    float acc2[8][8];
#pragma unroll
    for (int j = 0; j < 8; j++) {
        float bv = b2[c0 + j];
#pragma unroll
        for (int i = 0; i < 8; i++) acc2[i][j] = bv;
    }

    for (int kc = 0; kc < 64; kc += 16) {
#pragma unroll
        for (int s = 0; s < 2; s++) {
            const int f = tid * 2 + s;
            const int kk = f >> 4, n4 = (f & 15) * 4;
            float4 v = *(const float4*)(U2 + (long long)(kc + kk) * 64 + n4);
            *(float4*)&sW[kk * 100 + 12 * (n4 >> 3) + (n4 & 4)] = v;
        }
        __syncthreads();
#pragma unroll
        for (int kk = 0; kk < 16; kk++) {
            float ar[8];
#pragma unroll
            for (int i = 0; i < 8; i++) ar[i] = sU1[(r0 + i) * 68 + kc + kk];
            float4 w0 = *(const float4*)&sW[kk * 100 + 12 * cg];
            float4 w1 = *(const float4*)&sW[kk * 100 + 12 * cg + 4];
            float wr[8] = {w0.x, w0.y, w0.z, w0.w, w1.x, w1.y, w1.z, w1.w};
#pragma unroll
            for (int i = 0; i < 8; i++)
#pragma unroll
                for (int j = 0; j < 8; j++)
                    acc2[i][j] = fmaf(ar[i], wr[j], acc2[i][j]);
        }
        __syncthreads();
    }

#pragma unroll
    for (int i = 0; i < 8; i++) {
        const long long row = row0 + r0 + i;
        if (row < M) {
            float4 h0 = *(const float4*)(h_out + row * 64 + c0);
            float4 h1 = *(const float4*)(h_out + row * 64 + c0 + 4);
            h0.x += fmaxf(acc2[i][0], 0.f); h0.y += fmaxf(acc2[i][1], 0.f);
            h0.z += fmaxf(acc2[i][2], 0.f); h0.w += fmaxf(acc2[i][3], 0.f);
            h1.x += fmaxf(acc2[i][4], 0.f); h1.y += fmaxf(acc2[i][5], 0.f);
            h1.z += fmaxf(acc2[i][6], 0.f); h1.w += fmaxf(acc2[i][7], 0.f);
            *(float4*)(h_out + row * 64 + c0)     = h0;
            *(float4*)(h_out + row * 64 + c0 + 4) = h1;
        }
    }
}

// ---------------- edge kernel: sorted edges, tf32 mma, segmented-scan scatter --
#define A_STRIDE 68
#define W_STRIDE 72
__global__ __launch_bounds__(256, 2)
void edge_kernel_mma(const float* __restrict__ Pab,
                     const float* __restrict__ W1c,   // 6 x 64
                     const float* __restrict__ W2,    // 64 x 64 (k x n)
                     const float* __restrict__ b2,    // 64
                     float* __restrict__ agg, int E)
{
    extern __shared__ __align__(16) char smem[];
    uint32_t* sA   = (uint32_t*)smem;                       // 8 warps x 32 x 68
    uint32_t* sW2  = (uint32_t*)(smem + 69632);             // 64 x 72 (tf32)
    float*    sW1c = (float*)(smem + 88064);                // 6 x 64
    float*    sB2  = (float*)(smem + 89600);                // 64
    float*    sEa  = (float*)(smem + 89856);                // 8 warps x 192

    const int tid = threadIdx.x;
    const int w   = tid >> 5;
    const int l   = tid & 31;

    for (int i = tid; i < 64 * 64; i += 256) {
        int k = i >> 6, n = i & 63;
        sW2[k * W_STRIDE + n] = f32_to_tf32(W2[i]);
    }
    for (int i = tid; i < 384; i += 256) sW1c[i] = W1c[i];
    if (tid < 64) sB2[tid] = b2[tid];
    __syncthreads();

    uint32_t* myA  = sA + w * 32 * A_STRIDE;
    float*    myF  = (float*)myA;
    float*    myEa = sEa + w * 192;
    const int gw = blockIdx.x * 8 + w;
    const int nW = gridDim.x * 8;
    const int nChunks = (E + 31) >> 5;

    const int lg = l >> 2;
    const int lt = l & 3;
    const int er = l >> 3;
    const int c4 = (l & 7) * 4;

    unsigned lm_le;
    asm("mov.u32 %0, %%lanemask_le;" : "=r"(lm_le));

    for (int ch = gw; ch < nChunks; ch += nW) {
        const long long e0 = (long long)ch << 5;
        const long long eg = e0 + l;
        const bool valid = eg < E;

        int src = 0, dst = -1;
        if (valid) {
            src = g_srcS[eg];
            dst = g_dstS[eg];
        }
        {
            const float4* gsrc = (const float4*)(g_eaS + e0 * 6);
            if (l < 16) {
                *(float4*)(myEa + 4 * l)        = gsrc[l];
                *(float4*)(myEa + 4 * (l + 16)) = gsrc[l + 16];
                *(float4*)(myEa + 4 * (l + 32)) = gsrc[l + 32];
            }
        }
        __syncwarp();

#pragma unroll
        for (int it = 0; it < 8; it++) {
            const int e = 4 * it + er;
            const int de = __shfl_sync(0xffffffffu, dst, e);
            const int se = __shfl_sync(0xffffffffu, src, e);
            const bool ev = (e0 + e) < E;
            const float* par = Pab + (long long)de * 128;
            const float* pbr = Pab + (long long)se * 128 + 64;
#pragma unroll
            for (int h = 0; h < 2; h++) {
                const int c = c4 + 32 * h;
                float v0 = 0.f, v1 = 0.f, v2 = 0.f, v3 = 0.f;
                if (ev) {
                    float4 a = *(const float4*)(par + c);
                    float4 b = *(const float4*)(pbr + c);
                    v0 = a.x + b.x; v1 = a.y + b.y; v2 = a.z + b.z; v3 = a.w + b.w;
#pragma unroll
                    for (int q = 0; q < 6; q++) {
                        float  eq = myEa[e * 6 + q];
                        float4 wv = *(const float4*)(sW1c + q * 64 + c);
                        v0 = fmaf(eq, wv.x, v0);
                        v1 = fmaf(eq, wv.y, v1);
                        v2 = fmaf(eq, wv.z, v2);
                        v3 = fmaf(eq, wv.w, v3);
                    }
                }
                uint32_t r0 = f32_to_tf32(fmaxf(v0, 0.f));
                uint32_t r1 = f32_to_tf32(fmaxf(v1, 0.f));
                uint32_t r2 = f32_to_tf32(fmaxf(v2, 0.f));
                uint32_t r3 = f32_to_tf32(fmaxf(v3, 0.f));
                *(uint4*)(myA + e * A_STRIDE + c) = make_uint4(r0, r1, r2, r3);
            }
        }
        __syncwarp();

        float acc[2][8][4];
#pragma unroll
        for (int g = 0; g < 2; g++)
#pragma unroll
            for (int j = 0; j < 8; j++)
#pragma unroll
                for (int q = 0; q < 4; q++) acc[g][j][q] = 0.0f;

#pragma unroll
        for (int s = 0; s < 8; s++) {
            const int k0 = 8 * s;
            uint32_t bf[8][2];
#pragma unroll
            for (int j = 0; j < 8; j++) {
                bf[j][0] = sW2[(k0 + lt)     * W_STRIDE + 8 * j + lg];
                bf[j][1] = sW2[(k0 + lt + 4) * W_STRIDE + 8 * j + lg];
            }
            uint32_t af[2][4];
#pragma unroll
            for (int g = 0; g < 2; g++) {
                const uint32_t* base = myA + (16 * g + lg) * A_STRIDE + k0 + lt;
                af[g][0] = base[0];
                af[g][1] = base[8 * A_STRIDE];
                af[g][2] = base[4];
                af[g][3] = base[8 * A_STRIDE + 4];
            }
#pragma unroll
            for (int g = 0; g < 2; g++)
#pragma unroll
                for (int j = 0; j < 8; j++)
                    mma_tf32(acc[g][j], af[g], bf[j]);
        }
        __syncwarp();

#pragma unroll
        for (int g = 0; g < 2; g++)
#pragma unroll
            for (int h = 0; h < 2; h++) {
                const int row = 16 * g + 8 * h + lg;
#pragma unroll
                for (int j = 0; j < 8; j++)
                    *(float2*)(myF + row * A_STRIDE + 8 * j + 2 * lt) =
                        make_float2(acc[g][j][2 * h], acc[g][j][2 * h + 1]);
            }
        __syncwarp();

        {
            const int dprev = __shfl_up_sync(0xffffffffu, dst, 1);
            const int dnext = __shfl_down_sync(0xffffffffu, dst, 1);
            const bool head = (l == 0) || (dprev != dst);
            const bool tail = (l == 31) || (dnext != dst);
            const unsigned hm = __ballot_sync(0xffffffffu, head);
            const int hs = 31 - __clz(hm & lm_le);
            const int dist = l - hs;
            float* p = agg + (long long)dst * 64;
#pragma unroll
            for (int u = 0; u < 16; u++) {
                float4 t  = *(const float4*)(myF + l * A_STRIDE + 4 * u);
                float4 bb = *(const float4*)(sB2 + 4 * u);
                float x0 = 0.f, x1 = 0.f, x2 = 0.f, x3 = 0.f;
                if (valid) {
                    x0 = fmaxf(t.x + bb.x, 0.f);
                    x1 = fmaxf(t.y + bb.y, 0.f);
                    x2 = fmaxf(t.z + bb.z, 0.f);
                    x3 = fmaxf(t.w + bb.w, 0.f);
                }
#pragma unroll
                for (int s = 1; s < 32; s <<= 1) {
                    float y0 = __shfl_up_sync(0xffffffffu, x0, s);
                    float y1 = __shfl_up_sync(0xffffffffu, x1, s);
                    float y2 = __shfl_up_sync(0xffffffffu, x2, s);
                    float y3 = __shfl_up_sync(0xffffffffu, x3, s);
                    if (dist >= s) { x0 += y0; x1 += y1; x2 += y2; x3 += y3; }
                }
                if (tail && valid)
                    asm volatile("red.global.add.v4.f32 [%0], {%1, %2, %3, %4};"
                                 :: "l"(p + 4 * u), "f"(x0), "f"(x1), "f"(x2), "f"(x3)
                                 : "memory");
            }
        }
        __syncwarp();
    }
}

// ---------------- prediction head ---------------------------------------------
__global__ __launch_bounds__(256)
void pred_kernel(const float* __restrict__ h, const float* __restrict__ pw,
                 const float* __restrict__ pb, float* __restrict__ out, int M)
{
    __shared__ float spw[64];
    __shared__ float swarp[8];
    if (threadIdx.x < 64) spw[threadIdx.x] = pw[threadIdx.x];
    __syncthreads();

    float sum = 0.0f;
    for (long long row = (long long)blockIdx.x * blockDim.x + threadIdx.x; row < M;
         row += (long long)gridDim.x * blockDim.x) {
        const float4* hr = (const float4*)(h + row * 64);
#pragma unroll
        for (int u = 0; u < 16; u++) {
            float4 v = hr[u];
            sum = fmaf(v.x, spw[4 * u + 0], sum);
            sum = fmaf(v.y, spw[4 * u + 1], sum);
            sum = fmaf(v.z, spw[4 * u + 2], sum);
            sum = fmaf(v.w, spw[4 * u + 3], sum);
        }
    }
#pragma unroll
    for (int o = 16; o > 0; o >>= 1) sum += __shfl_down_sync(0xffffffffu, sum, o);
    if ((threadIdx.x & 31) == 0) swarp[threadIdx.x >> 5] = sum;
    __syncthreads();
    if (threadIdx.x < 8) {
        float s = swarp[threadIdx.x];
#pragma unroll
        for (int o = 4; o > 0; o >>= 1) s += __shfl_down_sync(0xffu, s, o);
        if (threadIdx.x == 0) {
            if (blockIdx.x == 0) s = fmaf(pb[0], (float)M, s);
            atomicAdd(out, s);
        }
    }
}

// ---------------- launch ------------------------------------------------------
extern "C" void kernel_launch(void* const* d_in, const int* in_sizes, int n_in,
                              void* d_out, int out_size)
{
    const float* x       = (const float*)d_in[0];
    const void*  ei      = d_in[1];
    const float* eattr   = (const float*)d_in[2];
    const float* lin_w   = (const float*)d_in[3];
    const float* lin_b   = (const float*)d_in[4];
    const float* msg_w1  = (const float*)d_in[5];
    const float* msg_b1  = (const float*)d_in[6];
    const float* msg_w2  = (const float*)d_in[7];
    const float* msg_b2  = (const float*)d_in[8];
    const float* upd_w1  = (const float*)d_in[9];
    const float* upd_b1  = (const float*)d_in[10];
    const float* upd_w2  = (const float*)d_in[11];
    const float* upd_b2  = (const float*)d_in[12];
    const float* pred_w  = (const float*)d_in[13];
    const float* pred_b  = (const float*)d_in[14];

    const int M = in_sizes[0] / 128;   // 50000
    const int E = in_sizes[2] / 6;     // 800000

    float *h, *Pab, *agg;
    int* cnt;
    cudaGetSymbolAddress((void**)&h,   g_h);
    cudaGetSymbolAddress((void**)&Pab, g_Pab);
    cudaGetSymbolAddress((void**)&agg, g_agg);
    cudaGetSymbolAddress((void**)&cnt, g_cnt);

    const int gN = (M + 127) / 128;    // 391
    const int SM_EDGE = 96000, SM_UPD8 = 49408;
    cudaFuncSetAttribute(edge_kernel_mma, cudaFuncAttributeMaxDynamicSharedMemorySize, SM_EDGE);
    cudaFuncSetAttribute(update8, cudaFuncAttributeMaxDynamicSharedMemorySize, SM_UPD8);

    const int nChunks = (E + 31) / 32;
    int gEdge = 148 * 2;
    if (gEdge * 8 > nChunks) gEdge = (nChunks + 7) / 8;
    if (gEdge < 1) gEdge = 1;

    // ---- sort edges by dst (once; reused by all 4 layers) ----
    detect_idx_kernel<<<1, 32>>>((const unsigned int*)ei);
    cudaMemsetAsync(cnt, 0, NSCAN * sizeof(int));
    hist_kernel<<<1024, 256>>>(ei, E);
    scan1_kernel<<<NSCAN / 1024, 1024>>>();
    scan2_kernel<<<1, 32>>>(NSCAN / 1024);
    scan3_kernel<<<NSCAN / 1024, 1024>>>();
    scatter_kernel<<<1024, 256>>>(ei, eattr, E);

    // input projection
    proj8<<<gN, 128>>>(x, lin_w, lin_b, h, M);

    for (int l = 0; l < 4; l++) {
        const float* W1 = msg_w1 + (size_t)l * 134 * 64;
        dual8<<<gN, 256>>>(h, W1, msg_b1 + l * 64, Pab, M);
        edge_kernel_mma<<<gEdge, 256, SM_EDGE>>>(Pab,
                                                 W1 + 128 * 64,
                                                 msg_w2 + (size_t)l * 64 * 64,
                                                 msg_b2 + l * 64, agg, E);
        update8<<<gN, 128, SM_UPD8>>>(h, upd_w1 + (size_t)l * 128 * 64,
                                      upd_b1 + l * 64,
                                      upd_w2 + (size_t)l * 64 * 64,
                                      upd_b2 + l * 64, agg, h, M);
    }

    cudaMemsetAsync(d_out, 0, sizeof(float));
    pred_kernel<<<256, 256>>>(h, pred_w, pred_b, (float*)d_out, M);
}

// round 9
// speedup vs baseline: 1.0436x; 1.0436x over previous
#include <cuda_runtime.h>
#include <cstdint>

#define EMB 64
#define NN_MAX 50000
#define NSCAN 50176          // 49 * 1024
#define NE_MAX 800000
#define NE_PAD (NE_MAX + 64)

// ---------------- scratch (static device memory; no allocations) ----------------
__device__ __align__(128) float g_h  [NN_MAX * EMB];
__device__ __align__(128) float g_Pab[NN_MAX * 128];   // [Pa | Pb] per node
__device__ __align__(128) float g_agg[NN_MAX * EMB];   // zero at launch entry (invariant)
__device__ int g_is64;

// sort scratch
__device__ int   g_cnt [NSCAN];
__device__ int   g_inc [NSCAN];
__device__ int   g_cur [NSCAN];
__device__ int   g_bsum[64];
// packed sorted edge records: {ea0..ea5, src(bits), dst(bits)} per edge (32B)
__device__ __align__(128) float g_rec[NE_PAD * 8];

// ---------------- helpers ------------------------------------------------------
__device__ __forceinline__ uint32_t f32_to_tf32(float f) {
    uint32_t u;
    asm("cvt.rna.tf32.f32 %0, %1;" : "=r"(u) : "f"(f));
    return u;
}
__device__ __forceinline__ void mma_tf32(float* c, const uint32_t* a, const uint32_t* b) {
    asm volatile(
        "mma.sync.aligned.m16n8k8.row.col.f32.tf32.tf32.f32 "
        "{%0,%1,%2,%3}, {%4,%5,%6,%7}, {%8,%9}, {%0,%1,%2,%3};"
        : "+f"(c[0]), "+f"(c[1]), "+f"(c[2]), "+f"(c[3])
        : "r"(a[0]), "r"(a[1]), "r"(a[2]), "r"(a[3]), "r"(b[0]), "r"(b[1]));
}

// ---------------- detect whether edge_index is int64 or int32 ----------------
__global__ void detect_idx_kernel(const unsigned int* __restrict__ p)
{
    if (threadIdx.x == 0 && blockIdx.x == 0) {
        unsigned int v = 0;
#pragma unroll
        for (int k = 0; k < 64; k++) v |= p[2 * k + 1];
        g_is64 = (v == 0) ? 1 : 0;
    }
}

// ---------------- counting sort by dst ----------------------------------------
__global__ void hist_kernel(const void* __restrict__ ei, int E)
{
    const int is64 = g_is64;
    for (long long e = (long long)blockIdx.x * blockDim.x + threadIdx.x; e < E;
         e += (long long)gridDim.x * blockDim.x) {
        int dst = is64 ? (int)((const long long*)ei)[(long long)E + e]
                       : ((const int*)ei)[(long long)E + e];
        atomicAdd(&g_cnt[dst], 1);
    }
}

__global__ __launch_bounds__(1024) void scan1_kernel()
{
    const int t = threadIdx.x, b = blockIdx.x;
    const int i = b * 1024 + t;
    const int lane = t & 31, wid = t >> 5;
    int x = g_cnt[i];
#pragma unroll
    for (int s = 1; s < 32; s <<= 1) {
        int u = __shfl_up_sync(0xffffffffu, x, s);
        if (lane >= s) x += u;
    }
    __shared__ int ws[32];
    if (lane == 31) ws[wid] = x;
    __syncthreads();
    if (wid == 0) {
        int y = ws[lane];
#pragma unroll
        for (int s = 1; s < 32; s <<= 1) {
            int u = __shfl_up_sync(0xffffffffu, y, s);
            if (lane >= s) y += u;
        }
        ws[lane] = y;
    }
    __syncthreads();
    int inc = x + (wid ? ws[wid - 1] : 0);
    g_inc[i] = inc;
    if (t == 1023) g_bsum[b] = inc;
}

__global__ void scan2_kernel(int nb)
{
    if (threadIdx.x == 0 && blockIdx.x == 0) {
        int run = 0;
        for (int b = 0; b < nb; b++) { int t = g_bsum[b]; g_bsum[b] = run; run += t; }
    }
}

__global__ __launch_bounds__(1024) void scan3_kernel()
{
    const int i = blockIdx.x * 1024 + threadIdx.x;
    g_cur[i] = g_inc[i] - g_cnt[i] + g_bsum[blockIdx.x];
}

__global__ void scatter_kernel(const void* __restrict__ ei,
                               const float* __restrict__ eattr, int E)
{
    const int is64 = g_is64;
    for (long long e = (long long)blockIdx.x * blockDim.x + threadIdx.x; e < E;
         e += (long long)gridDim.x * blockDim.x) {
        int src, dst;
        if (is64) {
            src = (int)((const long long*)ei)[e];
            dst = (int)((const long long*)ei)[(long long)E + e];
        } else {
            src = ((const int*)ei)[e];
            dst = ((const int*)ei)[(long long)E + e];
        }
        float ea[6];
#pragma unroll
        for (int q = 0; q < 6; q++) ea[q] = eattr[e * 6 + q];
        int pos = atomicAdd(&g_cur[dst], 1);
        float* r = g_rec + (long long)pos * 8;
        *(float4*)(r)     = make_float4(ea[0], ea[1], ea[2], ea[3]);
        *(float4*)(r + 4) = make_float4(ea[4], ea[5],
                                        __int_as_float(src), __int_as_float(dst));
    }
}

// ---------------- generic node GEMM (input projection) -------------------------
template <bool RELU>
__global__ __launch_bounds__(256)
void node_gemm64(const float* __restrict__ A1, const float* __restrict__ W1k, int K1,
                 const float* __restrict__ bias, float* __restrict__ C, int M)
{
    __shared__ __align__(16) float sA[16 * 64];
    __shared__ __align__(16) float sW[16 * 64];

    const int tid  = threadIdx.x;
    const int brow = blockIdx.x * 64;
    const int cg = tid & 15, rg = tid >> 4;
    const int c0 = cg * 4,   r0 = rg * 4;

    float acc[4][4];
#pragma unroll
    for (int i = 0; i < 4; i++)
#pragma unroll
        for (int j = 0; j < 4; j++)
            acc[i][j] = bias[c0 + j];

    const int lrow = tid >> 2;
    const int lcol = (tid & 3) * 4;
    const int grow = brow + lrow;
    const int kr = tid >> 4;
    const int wc = (tid & 15) * 4;

    for (int k0 = 0; k0 < K1; k0 += 16) {
        float4 av = make_float4(0.f, 0.f, 0.f, 0.f);
        if (grow < M)
            av = *(const float4*)(A1 + (long long)grow * K1 + k0 + lcol);
        sA[(lcol + 0) * 64 + lrow] = av.x;
        sA[(lcol + 1) * 64 + lrow] = av.y;
        sA[(lcol + 2) * 64 + lrow] = av.z;
        sA[(lcol + 3) * 64 + lrow] = av.w;
        *(float4*)&sW[kr * 64 + wc] =
            *(const float4*)(W1k + (long long)(k0 + kr) * 64 + wc);
        __syncthreads();
#pragma unroll
        for (int kk = 0; kk < 16; kk++) {
            float4 a = *(const float4*)&sA[kk * 64 + r0];
            float4 w = *(const float4*)&sW[kk * 64 + c0];
            float ar[4] = {a.x, a.y, a.z, a.w};
            float wr[4] = {w.x, w.y, w.z, w.w};
#pragma unroll
            for (int i = 0; i < 4; i++)
#pragma unroll
                for (int j = 0; j < 4; j++)
                    acc[i][j] = fmaf(ar[i], wr[j], acc[i][j]);
        }
        __syncthreads();
    }

#pragma unroll
    for (int i = 0; i < 4; i++) {
        int row = brow + r0 + i;
        if (row < M) {
            float v0 = acc[i][0], v1 = acc[i][1], v2 = acc[i][2], v3 = acc[i][3];
            if (RELU) {
                v0 = fmaxf(v0, 0.f); v1 = fmaxf(v1, 0.f);
                v2 = fmaxf(v2, 0.f); v3 = fmaxf(v3, 0.f);
            }
            *(float4*)(C + (long long)row * 64 + c0) = make_float4(v0, v1, v2, v3);
        }
    }
}

// ---------------- dual node GEMM: Pab = [h@W1a + b1 | h@W1b] -------------------
__global__ __launch_bounds__(512)
void node_gemm_dual(const float* __restrict__ h, const float* __restrict__ W1,
                    const float* __restrict__ b1, float* __restrict__ Pab, int M)
{
    __shared__ __align__(16) float sA[16 * 64];
    __shared__ __align__(16) float sW[16 * 128];

    const int tid  = threadIdx.x;
    const int brow = blockIdx.x * 64;
    const int cg = tid & 31, rg = tid >> 5;
    const int c0 = cg * 4,   r0 = rg * 4;

    float acc[4][4];
#pragma unroll
    for (int i = 0; i < 4; i++)
#pragma unroll
        for (int j = 0; j < 4; j++)
            acc[i][j] = (c0 < 64) ? b1[c0 + j] : 0.0f;

    const int lrow = tid >> 2;
    const int lcol = (tid & 3) * 4;
    const int grow = brow + lrow;
    const int kr = tid >> 5;
    const int wc = (tid & 31) * 4;

    for (int k0 = 0; k0 < 64; k0 += 16) {
        if (tid < 256) {
            float4 av = make_float4(0.f, 0.f, 0.f, 0.f);
            if (grow < M)
                av = *(const float4*)(h + (long long)grow * 64 + k0 + lcol);
            sA[(lcol + 0) * 64 + lrow] = av.x;
            sA[(lcol + 1) * 64 + lrow] = av.y;
            sA[(lcol + 2) * 64 + lrow] = av.z;
            sA[(lcol + 3) * 64 + lrow] = av.w;
        }
        {
            const float* src = (wc < 64)
                ? (W1 + (long long)(k0 + kr) * 64 + wc)
                : (W1 + (long long)(64 + k0 + kr) * 64 + (wc - 64));
            *(float4*)&sW[kr * 128 + wc] = *(const float4*)src;
        }
        __syncthreads();
#pragma unroll
        for (int kk = 0; kk < 16; kk++) {
            float4 a = *(const float4*)&sA[kk * 64 + r0];
            float4 w = *(const float4*)&sW[kk * 128 + c0];
            float ar[4] = {a.x, a.y, a.z, a.w};
            float wr[4] = {w.x, w.y, w.z, w.w};
#pragma unroll
            for (int i = 0; i < 4; i++)
#pragma unroll
                for (int j = 0; j < 4; j++)
                    acc[i][j] = fmaf(ar[i], wr[j], acc[i][j]);
        }
        __syncthreads();
    }

#pragma unroll
    for (int i = 0; i < 4; i++) {
        int row = brow + r0 + i;
        if (row < M)
            *(float4*)(Pab + (long long)row * 128 + c0) =
                make_float4(acc[i][0], acc[i][1], acc[i][2], acc[i][3]);
    }
}

// ---------------- fused update: h += relu(relu([h|agg]@U1+b1)@U2+b2) ----------
// Also zeroes agg after reading it (restores the launch-entry invariant).
__global__ __launch_bounds__(256)
void fused_update(const float* __restrict__ h_in, const float* __restrict__ U1,
                  const float* __restrict__ b1, const float* __restrict__ U2,
                  const float* __restrict__ b2, float* agg,
                  float* __restrict__ h_out, int M)
{
    __shared__ __align__(16) float sA [16 * 64];
    __shared__ __align__(16) float sW [16 * 64];
    __shared__ __align__(16) float sU1[64 * 68];

    const int tid  = threadIdx.x;
    const int brow = blockIdx.x * 64;
    const int cg = tid & 15, rg = tid >> 4;
    const int c0 = cg * 4,   r0 = rg * 4;

    const int lrow = tid >> 2;
    const int lcol = (tid & 3) * 4;
    const int grow = brow + lrow;
    const int kr = tid >> 4;
    const int wc = (tid & 15) * 4;

    float acc[4][4];
#pragma unroll
    for (int i = 0; i < 4; i++)
#pragma unroll
        for (int j = 0; j < 4; j++)
            acc[i][j] = b1[c0 + j];

#pragma unroll
    for (int p = 0; p < 2; p++) {
        const float* A = p ? agg : h_in;
        const float* W = U1 + (long long)p * 64 * 64;
        for (int k0 = 0; k0 < 64; k0 += 16) {
            float4 av = make_float4(0.f, 0.f, 0.f, 0.f);
            if (grow < M) {
                av = *(const float4*)(A + (long long)grow * 64 + k0 + lcol);
                if (p == 1)
                    *(float4*)(agg + (long long)grow * 64 + k0 + lcol) =
                        make_float4(0.f, 0.f, 0.f, 0.f);
            }
            sA[(lcol + 0) * 64 + lrow] = av.x;
            sA[(lcol + 1) * 64 + lrow] = av.y;
            sA[(lcol + 2) * 64 + lrow] = av.z;
            sA[(lcol + 3) * 64 + lrow] = av.w;
            *(float4*)&sW[kr * 64 + wc] =
                *(const float4*)(W + (long long)(k0 + kr) * 64 + wc);
            __syncthreads();
#pragma unroll
            for (int kk = 0; kk < 16; kk++) {
                float4 a = *(const float4*)&sA[kk * 64 + r0];
                float4 w = *(const float4*)&sW[kk * 64 + c0];
                float ar[4] = {a.x, a.y, a.z, a.w};
                float wr[4] = {w.x, w.y, w.z, w.w};
#pragma unroll
                for (int i = 0; i < 4; i++)
#pragma unroll
                    for (int j = 0; j < 4; j++)
                        acc[i][j] = fmaf(ar[i], wr[j], acc[i][j]);
            }
            __syncthreads();
        }
    }

    // u1 = relu(acc) -> smem, k-major
#pragma unroll
    for (int i = 0; i < 4; i++)
#pragma unroll
        for (int j = 0; j < 4; j++)
            sU1[(c0 + j) * 68 + r0 + i] = fmaxf(acc[i][j], 0.0f);
    __syncthreads();

    // phase 2: acc2 = u1 @ U2 + b2
    float acc2[4][4];
#pragma unroll
    for (int i = 0; i < 4; i++)
#pragma unroll
        for (int j = 0; j < 4; j++)
            acc2[i][j] = b2[c0 + j];

    for (int k0 = 0; k0 < 64; k0 += 16) {
        *(float4*)&sW[kr * 64 + wc] =
            *(const float4*)(U2 + (long long)(k0 + kr) * 64 + wc);
        __syncthreads();
#pragma unroll
        for (int kk = 0; kk < 16; kk++) {
            float4 a = *(const float4*)&sU1[(k0 + kk) * 68 + r0];
            float4 w = *(const float4*)&sW[kk * 64 + c0];
            float ar[4] = {a.x, a.y, a.z, a.w};
            float wr[4] = {w.x, w.y, w.z, w.w};
#pragma unroll
            for (int i = 0; i < 4; i++)
#pragma unroll
                for (int j = 0; j < 4; j++)
                    acc2[i][j] = fmaf(ar[i], wr[j], acc2[i][j]);
        }
        __syncthreads();
    }

#pragma unroll
    for (int i = 0; i < 4; i++) {
        int row = brow + r0 + i;
        if (row < M) {
            float4 hh = *(const float4*)(h_out + (long long)row * 64 + c0);
            hh.x += fmaxf(acc2[i][0], 0.f);
            hh.y += fmaxf(acc2[i][1], 0.f);
            hh.z += fmaxf(acc2[i][2], 0.f);
            hh.w += fmaxf(acc2[i][3], 0.f);
            *(float4*)(h_out + (long long)row * 64 + c0) = hh;
        }
    }
}

// ---------------- edge kernel: packed sorted records, tf32 mma, seg-scan -------
#define A_STRIDE 68
#define W_STRIDE 72
__global__ __launch_bounds__(256, 2)
void edge_kernel_mma(const float* __restrict__ Pab,
                     const float* __restrict__ W1c,   // 6 x 64
                     const float* __restrict__ W2,    // 64 x 64 (k x n)
                     const float* __restrict__ b2,    // 64
                     float* __restrict__ agg, int E)
{
    extern __shared__ __align__(16) char smem[];
    uint32_t* sA   = (uint32_t*)smem;                       // 8 warps x 32 x 68
    uint32_t* sW2  = (uint32_t*)(smem + 69632);             // 64 x 72 (tf32)
    float*    sW1c = (float*)(smem + 88064);                // 6 x 64
    float*    sB2  = (float*)(smem + 89600);                // 64

    const int tid = threadIdx.x;
    const int w   = tid >> 5;
    const int l   = tid & 31;

    for (int i = tid; i < 64 * 64; i += 256) {
        int k = i >> 6, n = i & 63;
        sW2[k * W_STRIDE + n] = f32_to_tf32(W2[i]);
    }
    for (int i = tid; i < 384; i += 256) sW1c[i] = W1c[i];
    if (tid < 64) sB2[tid] = b2[tid];
    __syncthreads();

    uint32_t* myA = sA + w * 32 * A_STRIDE;
    float*    myF = (float*)myA;
    const int gw = blockIdx.x * 8 + w;
    const int nW = gridDim.x * 8;
    const int nChunks = (E + 31) >> 5;

    const int lg = l >> 2;
    const int lt = l & 3;
    const int er = l >> 3;
    const int c4 = (l & 7) * 4;

    unsigned lm_le;
    asm("mov.u32 %0, %%lanemask_le;" : "=r"(lm_le));

    for (int ch = gw; ch < nChunks; ch += nW) {
        const long long e0 = (long long)ch << 5;
        const long long eg = e0 + l;
        const bool valid = eg < E;

        // load packed record (2 coalesced LDG.128 per lane)
        int src = 0, dst = -1;
        float ea0 = 0.f, ea1 = 0.f, ea2 = 0.f, ea3 = 0.f, ea4 = 0.f, ea5 = 0.f;
        if (valid) {
            const float* r = g_rec + eg * 8;
            float4 p0 = *(const float4*)(r);
            float4 p1 = *(const float4*)(r + 4);
            ea0 = p0.x; ea1 = p0.y; ea2 = p0.z; ea3 = p0.w;
            ea4 = p1.x; ea5 = p1.y;
            src = __float_as_int(p1.z);
            dst = __float_as_int(p1.w);
        }

        // ---- phase A: m1, coalesced (4 consecutive edges x 8 lanes per pass) ----
#pragma unroll
        for (int it = 0; it < 8; it++) {
            const int e = 4 * it + er;
            const int de = __shfl_sync(0xffffffffu, dst, e);
            const int se = __shfl_sync(0xffffffffu, src, e);
            float eq[6];
            eq[0] = __shfl_sync(0xffffffffu, ea0, e);
            eq[1] = __shfl_sync(0xffffffffu, ea1, e);
            eq[2] = __shfl_sync(0xffffffffu, ea2, e);
            eq[3] = __shfl_sync(0xffffffffu, ea3, e);
            eq[4] = __shfl_sync(0xffffffffu, ea4, e);
            eq[5] = __shfl_sync(0xffffffffu, ea5, e);
            const bool ev = (e0 + e) < E;
            const float* par = Pab + (long long)de * 128;
            const float* pbr = Pab + (long long)se * 128 + 64;
#pragma unroll
            for (int h = 0; h < 2; h++) {
                const int c = c4 + 32 * h;
                float v0 = 0.f, v1 = 0.f, v2 = 0.f, v3 = 0.f;
                if (ev) {
                    float4 a = *(const float4*)(par + c);
                    float4 b = *(const float4*)(pbr + c);
                    v0 = a.x + b.x; v1 = a.y + b.y; v2 = a.z + b.z; v3 = a.w + b.w;
#pragma unroll
                    for (int q = 0; q < 6; q++) {
                        float4 wv = *(const float4*)(sW1c + q * 64 + c);
                        v0 = fmaf(eq[q], wv.x, v0);
                        v1 = fmaf(eq[q], wv.y, v1);
                        v2 = fmaf(eq[q], wv.z, v2);
                        v3 = fmaf(eq[q], wv.w, v3);
                    }
                }
                uint32_t r0 = f32_to_tf32(fmaxf(v0, 0.f));
                uint32_t r1 = f32_to_tf32(fmaxf(v1, 0.f));
                uint32_t r2 = f32_to_tf32(fmaxf(v2, 0.f));
                uint32_t r3 = f32_to_tf32(fmaxf(v3, 0.f));
                *(uint4*)(myA + e * A_STRIDE + c) = make_uint4(r0, r1, r2, r3);
            }
        }
        __syncwarp();

        // ---- mma: D(32x64) = m1 @ W2 ----
        float acc[2][8][4];
#pragma unroll
        for (int g = 0; g < 2; g++)
#pragma unroll
            for (int j = 0; j < 8; j++)
#pragma unroll
                for (int q = 0; q < 4; q++) acc[g][j][q] = 0.0f;

#pragma unroll
        for (int s = 0; s < 8; s++) {
            const int k0 = 8 * s;
            uint32_t bf[8][2];
#pragma unroll
            for (int j = 0; j < 8; j++) {
                bf[j][0] = sW2[(k0 + lt)     * W_STRIDE + 8 * j + lg];
                bf[j][1] = sW2[(k0 + lt + 4) * W_STRIDE + 8 * j + lg];
            }
            uint32_t af[2][4];
#pragma unroll
            for (int g = 0; g < 2; g++) {
                const uint32_t* base = myA + (16 * g + lg) * A_STRIDE + k0 + lt;
                af[g][0] = base[0];
                af[g][1] = base[8 * A_STRIDE];
                af[g][2] = base[4];
                af[g][3] = base[8 * A_STRIDE + 4];
            }
#pragma unroll
            for (int g = 0; g < 2; g++)
#pragma unroll
                for (int j = 0; j < 8; j++)
                    mma_tf32(acc[g][j], af[g], bf[j]);
        }
        __syncwarp();

        // ---- transpose to smem ----
#pragma unroll
        for (int g = 0; g < 2; g++)
#pragma unroll
            for (int h = 0; h < 2; h++) {
                const int row = 16 * g + 8 * h + lg;
#pragma unroll
                for (int j = 0; j < 8; j++)
                    *(float2*)(myF + row * A_STRIDE + 8 * j + 2 * lt) =
                        make_float2(acc[g][j][2 * h], acc[g][j][2 * h + 1]);
            }
        __syncwarp();

        // ---- segmented scan over sorted dst runs, RED only at tails ----
        {
            const int dprev = __shfl_up_sync(0xffffffffu, dst, 1);
            const int dnext = __shfl_down_sync(0xffffffffu, dst, 1);
            const bool head = (l == 0) || (dprev != dst);
            const bool tail = (l == 31) || (dnext != dst);
            const unsigned hm = __ballot_sync(0xffffffffu, head);
            const int hs = 31 - __clz(hm & lm_le);
            const int dist = l - hs;
            float* p = agg + (long long)dst * 64;
#pragma unroll
            for (int u = 0; u < 16; u++) {
                float4 t  = *(const float4*)(myF + l * A_STRIDE + 4 * u);
                float4 bb = *(const float4*)(sB2 + 4 * u);
                float x0 = 0.f, x1 = 0.f, x2 = 0.f, x3 = 0.f;
                if (valid) {
                    x0 = fmaxf(t.x + bb.x, 0.f);
                    x1 = fmaxf(t.y + bb.y, 0.f);
                    x2 = fmaxf(t.z + bb.z, 0.f);
                    x3 = fmaxf(t.w + bb.w, 0.f);
                }
#pragma unroll
                for (int s = 1; s < 32; s <<= 1) {
                    float y0 = __shfl_up_sync(0xffffffffu, x0, s);
                    float y1 = __shfl_up_sync(0xffffffffu, x1, s);
                    float y2 = __shfl_up_sync(0xffffffffu, x2, s);
                    float y3 = __shfl_up_sync(0xffffffffu, x3, s);
                    if (dist >= s) { x0 += y0; x1 += y1; x2 += y2; x3 += y3; }
                }
                if (tail && valid)
                    asm volatile("red.global.add.v4.f32 [%0], {%1, %2, %3, %4};"
                                 :: "l"(p + 4 * u), "f"(x0), "f"(x1), "f"(x2), "f"(x3)
                                 : "memory");
            }
        }
        __syncwarp();
    }
}

// ---------------- prediction head ---------------------------------------------
__global__ __launch_bounds__(256)
void pred_kernel(const float* __restrict__ h, const float* __restrict__ pw,
                 const float* __restrict__ pb, float* __restrict__ out, int M)
{
    __shared__ float spw[64];
    __shared__ float swarp[8];
    if (threadIdx.x < 64) spw[threadIdx.x] = pw[threadIdx.x];
    __syncthreads();

    float sum = 0.0f;
    for (long long row = (long long)blockIdx.x * blockDim.x + threadIdx.x; row < M;
         row += (long long)gridDim.x * blockDim.x) {
        const float4* hr = (const float4*)(h + row * 64);
#pragma unroll
        for (int u = 0; u < 16; u++) {
            float4 v = hr[u];
            sum = fmaf(v.x, spw[4 * u + 0], sum);
            sum = fmaf(v.y, spw[4 * u + 1], sum);
            sum = fmaf(v.z, spw[4 * u + 2], sum);
            sum = fmaf(v.w, spw[4 * u + 3], sum);
        }
    }
#pragma unroll
    for (int o = 16; o > 0; o >>= 1) sum += __shfl_down_sync(0xffffffffu, sum, o);
    if ((threadIdx.x & 31) == 0) swarp[threadIdx.x >> 5] = sum;
    __syncthreads();
    if (threadIdx.x < 8) {
        float s = swarp[threadIdx.x];
#pragma unroll
        for (int o = 4; o > 0; o >>= 1) s += __shfl_down_sync(0xffu, s, o);
        if (threadIdx.x == 0) {
            if (blockIdx.x == 0) s = fmaf(pb[0], (float)M, s);
            atomicAdd(out, s);
        }
    }
}

// ---------------- launch ------------------------------------------------------
extern "C" void kernel_launch(void* const* d_in, const int* in_sizes, int n_in,
                              void* d_out, int out_size)
{
    const float* x       = (const float*)d_in[0];
    const void*  ei      = d_in[1];
    const float* eattr   = (const float*)d_in[2];
    const float* lin_w   = (const float*)d_in[3];
    const float* lin_b   = (const float*)d_in[4];
    const float* msg_w1  = (const float*)d_in[5];
    const float* msg_b1  = (const float*)d_in[6];
    const float* msg_w2  = (const float*)d_in[7];
    const float* msg_b2  = (const float*)d_in[8];
    const float* upd_w1  = (const float*)d_in[9];
    const float* upd_b1  = (const float*)d_in[10];
    const float* upd_w2  = (const float*)d_in[11];
    const float* upd_b2  = (const float*)d_in[12];
    const float* pred_w  = (const float*)d_in[13];
    const float* pred_b  = (const float*)d_in[14];

    const int M = in_sizes[0] / 128;   // 50000
    const int E = in_sizes[2] / 6;     // 800000

    float *h, *Pab, *agg;
    int* cnt;
    cudaGetSymbolAddress((void**)&h,   g_h);
    cudaGetSymbolAddress((void**)&Pab, g_Pab);
    cudaGetSymbolAddress((void**)&agg, g_agg);
    cudaGetSymbolAddress((void**)&cnt, g_cnt);

    const int gN = (M + 63) / 64;      // 782
    const int SM_EDGE = 89856;
    cudaFuncSetAttribute(edge_kernel_mma,
                         cudaFuncAttributeMaxDynamicSharedMemorySize, SM_EDGE);
    const int nChunks = (E + 31) / 32;
    int gEdge = 148 * 2;
    if (gEdge * 8 > nChunks) gEdge = (nChunks + 7) / 8;
    if (gEdge < 1) gEdge = 1;

    // ---- sort edges by dst (once; reused by all 4 layers) ----
    detect_idx_kernel<<<1, 32>>>((const unsigned int*)ei);
    cudaMemsetAsync(cnt, 0, NSCAN * sizeof(int));
    hist_kernel<<<1024, 256>>>(ei, E);
    scan1_kernel<<<NSCAN / 1024, 1024>>>();
    scan2_kernel<<<1, 32>>>(NSCAN / 1024);
    scan3_kernel<<<NSCAN / 1024, 1024>>>();
    scatter_kernel<<<1024, 256>>>(ei, eattr, E);

    // input projection
    node_gemm64<false><<<gN, 256>>>(x, lin_w, 128, lin_b, h, M);

    for (int l = 0; l < 4; l++) {
        const float* W1 = msg_w1 + (size_t)l * 134 * 64;
        node_gemm_dual<<<gN, 512>>>(h, W1, msg_b1 + l * 64, Pab, M);
        edge_kernel_mma<<<gEdge, 256, SM_EDGE>>>(Pab,
                                                 W1 + 128 * 64,
                                                 msg_w2 + (size_t)l * 64 * 64,
                                                 msg_b2 + l * 64, agg, E);
        fused_update<<<gN, 256>>>(h, upd_w1 + (size_t)l * 128 * 64,
                                  upd_b1 + l * 64,
                                  upd_w2 + (size_t)l * 64 * 64,
                                  upd_b2 + l * 64, agg, h, M);
    }

    cudaMemsetAsync(d_out, 0, sizeof(float));
    pred_kernel<<<256, 256>>>(h, pred_w, pred_b, (float*)d_out, M);
}

// round 10
// speedup vs baseline: 1.0569x; 1.0128x over previous
#include <cuda_runtime.h>
#include <cstdint>

#define EMB 64
#define NN_MAX 50000
#define NSCAN 50176          // 49 * 1024
#define NE_MAX 800000
#define NE_PAD (NE_MAX + 64)

// ---------------- scratch (static device memory; no allocations) ----------------
__device__ __align__(128) float g_h  [NN_MAX * EMB];
__device__ __align__(128) float g_Pab[NN_MAX * 128];   // [Pa | Pb] per node
__device__ __align__(128) float g_agg[NN_MAX * EMB];   // zero at launch entry (invariant)
__device__ int g_is64;

// sort scratch
__device__ int   g_cnt [NSCAN];
__device__ int   g_inc [NSCAN];
__device__ int   g_cur [NSCAN];
__device__ int   g_bsum[64];
// packed sorted edge records: {ea0..ea5, src(bits), dst(bits)} per edge (32B)
__device__ __align__(128) float g_rec[NE_PAD * 8];

// ---------------- helpers ------------------------------------------------------
__device__ __forceinline__ uint32_t f32_to_tf32(float f) {
    uint32_t u;
    asm("cvt.rna.tf32.f32 %0, %1;" : "=r"(u) : "f"(f));
    return u;
}
__device__ __forceinline__ void mma_tf32(float* c, const uint32_t* a, const uint32_t* b) {
    asm volatile(
        "mma.sync.aligned.m16n8k8.row.col.f32.tf32.tf32.f32 "
        "{%0,%1,%2,%3}, {%4,%5,%6,%7}, {%8,%9}, {%0,%1,%2,%3};"
        : "+f"(c[0]), "+f"(c[1]), "+f"(c[2]), "+f"(c[3])
        : "r"(a[0]), "r"(a[1]), "r"(a[2]), "r"(a[3]), "r"(b[0]), "r"(b[1]));
}

// ---------------- detect whether edge_index is int64 or int32 ----------------
__global__ void detect_idx_kernel(const unsigned int* __restrict__ p)
{
    if (threadIdx.x == 0 && blockIdx.x == 0) {
        unsigned int v = 0;
#pragma unroll
        for (int k = 0; k < 64; k++) v |= p[2 * k + 1];
        g_is64 = (v == 0) ? 1 : 0;
    }
}

// ---------------- counting sort by dst ----------------------------------------
__global__ void hist_kernel(const void* __restrict__ ei, int E)
{
    const int is64 = g_is64;
    for (long long e = (long long)blockIdx.x * blockDim.x + threadIdx.x; e < E;
         e += (long long)gridDim.x * blockDim.x) {
        int dst = is64 ? (int)((const long long*)ei)[(long long)E + e]
                       : ((const int*)ei)[(long long)E + e];
        atomicAdd(&g_cnt[dst], 1);
    }
}

__global__ __launch_bounds__(1024) void scan1_kernel()
{
    const int t = threadIdx.x, b = blockIdx.x;
    const int i = b * 1024 + t;
    const int lane = t & 31, wid = t >> 5;
    int x = g_cnt[i];
#pragma unroll
    for (int s = 1; s < 32; s <<= 1) {
        int u = __shfl_up_sync(0xffffffffu, x, s);
        if (lane >= s) x += u;
    }
    __shared__ int ws[32];
    if (lane == 31) ws[wid] = x;
    __syncthreads();
    if (wid == 0) {
        int y = ws[lane];
#pragma unroll
        for (int s = 1; s < 32; s <<= 1) {
            int u = __shfl_up_sync(0xffffffffu, y, s);
            if (lane >= s) y += u;
        }
        ws[lane] = y;
    }
    __syncthreads();
    int inc = x + (wid ? ws[wid - 1] : 0);
    g_inc[i] = inc;
    if (t == 1023) g_bsum[b] = inc;
}

__global__ void scan2_kernel(int nb)
{
    if (threadIdx.x == 0 && blockIdx.x == 0) {
        int run = 0;
        for (int b = 0; b < nb; b++) { int t = g_bsum[b]; g_bsum[b] = run; run += t; }
    }
}

__global__ __launch_bounds__(1024) void scan3_kernel()
{
    const int i = blockIdx.x * 1024 + threadIdx.x;
    g_cur[i] = g_inc[i] - g_cnt[i] + g_bsum[blockIdx.x];
}

__global__ void scatter_kernel(const void* __restrict__ ei,
                               const float* __restrict__ eattr, int E)
{
    const int is64 = g_is64;
    for (long long e = (long long)blockIdx.x * blockDim.x + threadIdx.x; e < E;
         e += (long long)gridDim.x * blockDim.x) {
        int src, dst;
        if (is64) {
            src = (int)((const long long*)ei)[e];
            dst = (int)((const long long*)ei)[(long long)E + e];
        } else {
            src = ((const int*)ei)[e];
            dst = ((const int*)ei)[(long long)E + e];
        }
        float ea[6];
#pragma unroll
        for (int q = 0; q < 6; q++) ea[q] = eattr[e * 6 + q];
        int pos = atomicAdd(&g_cur[dst], 1);
        float* r = g_rec + (long long)pos * 8;
        *(float4*)(r)     = make_float4(ea[0], ea[1], ea[2], ea[3]);
        *(float4*)(r + 4) = make_float4(ea[4], ea[5],
                                        __int_as_float(src), __int_as_float(dst));
    }
}

// ---------------- generic node GEMM (input projection) -------------------------
template <bool RELU>
__global__ __launch_bounds__(256)
void node_gemm64(const float* __restrict__ A1, const float* __restrict__ W1k, int K1,
                 const float* __restrict__ bias, float* __restrict__ C, int M)
{
    __shared__ __align__(16) float sA[16 * 64];
    __shared__ __align__(16) float sW[16 * 64];

    const int tid  = threadIdx.x;
    const int brow = blockIdx.x * 64;
    const int cg = tid & 15, rg = tid >> 4;
    const int c0 = cg * 4,   r0 = rg * 4;

    float acc[4][4];
#pragma unroll
    for (int i = 0; i < 4; i++)
#pragma unroll
        for (int j = 0; j < 4; j++)
            acc[i][j] = bias[c0 + j];

    const int lrow = tid >> 2;
    const int lcol = (tid & 3) * 4;
    const int grow = brow + lrow;
    const int kr = tid >> 4;
    const int wc = (tid & 15) * 4;

    for (int k0 = 0; k0 < K1; k0 += 16) {
        float4 av = make_float4(0.f, 0.f, 0.f, 0.f);
        if (grow < M)
            av = *(const float4*)(A1 + (long long)grow * K1 + k0 + lcol);
        sA[(lcol + 0) * 64 + lrow] = av.x;
        sA[(lcol + 1) * 64 + lrow] = av.y;
        sA[(lcol + 2) * 64 + lrow] = av.z;
        sA[(lcol + 3) * 64 + lrow] = av.w;
        *(float4*)&sW[kr * 64 + wc] =
            *(const float4*)(W1k + (long long)(k0 + kr) * 64 + wc);
        __syncthreads();
#pragma unroll
        for (int kk = 0; kk < 16; kk++) {
            float4 a = *(const float4*)&sA[kk * 64 + r0];
            float4 w = *(const float4*)&sW[kk * 64 + c0];
            float ar[4] = {a.x, a.y, a.z, a.w};
            float wr[4] = {w.x, w.y, w.z, w.w};
#pragma unroll
            for (int i = 0; i < 4; i++)
#pragma unroll
                for (int j = 0; j < 4; j++)
                    acc[i][j] = fmaf(ar[i], wr[j], acc[i][j]);
        }
        __syncthreads();
    }

#pragma unroll
    for (int i = 0; i < 4; i++) {
        int row = brow + r0 + i;
        if (row < M) {
            float v0 = acc[i][0], v1 = acc[i][1], v2 = acc[i][2], v3 = acc[i][3];
            if (RELU) {
                v0 = fmaxf(v0, 0.f); v1 = fmaxf(v1, 0.f);
                v2 = fmaxf(v2, 0.f); v3 = fmaxf(v3, 0.f);
            }
            *(float4*)(C + (long long)row * 64 + c0) = make_float4(v0, v1, v2, v3);
        }
    }
}

// ---------------- dual node GEMM: Pab = [h@W1a + b1 | h@W1b] -------------------
__global__ __launch_bounds__(512)
void node_gemm_dual(const float* __restrict__ h, const float* __restrict__ W1,
                    const float* __restrict__ b1, float* __restrict__ Pab, int M)
{
    __shared__ __align__(16) float sA[16 * 64];
    __shared__ __align__(16) float sW[16 * 128];

    const int tid  = threadIdx.x;
    const int brow = blockIdx.x * 64;
    const int cg = tid & 31, rg = tid >> 5;
    const int c0 = cg * 4,   r0 = rg * 4;

    float acc[4][4];
#pragma unroll
    for (int i = 0; i < 4; i++)
#pragma unroll
        for (int j = 0; j < 4; j++)
            acc[i][j] = (c0 < 64) ? b1[c0 + j] : 0.0f;

    const int lrow = tid >> 2;
    const int lcol = (tid & 3) * 4;
    const int grow = brow + lrow;
    const int kr = tid >> 5;
    const int wc = (tid & 31) * 4;

    for (int k0 = 0; k0 < 64; k0 += 16) {
        if (tid < 256) {
            float4 av = make_float4(0.f, 0.f, 0.f, 0.f);
            if (grow < M)
                av = *(const float4*)(h + (long long)grow * 64 + k0 + lcol);
            sA[(lcol + 0) * 64 + lrow] = av.x;
            sA[(lcol + 1) * 64 + lrow] = av.y;
            sA[(lcol + 2) * 64 + lrow] = av.z;
            sA[(lcol + 3) * 64 + lrow] = av.w;
        }
        {
            const float* src = (wc < 64)
                ? (W1 + (long long)(k0 + kr) * 64 + wc)
                : (W1 + (long long)(64 + k0 + kr) * 64 + (wc - 64));
            *(float4*)&sW[kr * 128 + wc] = *(const float4*)src;
        }
        __syncthreads();
#pragma unroll
        for (int kk = 0; kk < 16; kk++) {
            float4 a = *(const float4*)&sA[kk * 64 + r0];
            float4 w = *(const float4*)&sW[kk * 128 + c0];
            float ar[4] = {a.x, a.y, a.z, a.w};
            float wr[4] = {w.x, w.y, w.z, w.w};
#pragma unroll
            for (int i = 0; i < 4; i++)
#pragma unroll
                for (int j = 0; j < 4; j++)
                    acc[i][j] = fmaf(ar[i], wr[j], acc[i][j]);
        }
        __syncthreads();
    }

#pragma unroll
    for (int i = 0; i < 4; i++) {
        int row = brow + r0 + i;
        if (row < M)
            *(float4*)(Pab + (long long)row * 128 + c0) =
                make_float4(acc[i][0], acc[i][1], acc[i][2], acc[i][3]);
    }
}

// ---------------- fused update: h += relu(relu([h|agg]@U1+b1)@U2+b2) ----------
// Also zeroes agg after reading it (restores the launch-entry invariant).
__global__ __launch_bounds__(256)
void fused_update(const float* __restrict__ h_in, const float* __restrict__ U1,
                  const float* __restrict__ b1, const float* __restrict__ U2,
                  const float* __restrict__ b2, float* agg,
                  float* __restrict__ h_out, int M)
{
    __shared__ __align__(16) float sA [16 * 64];
    __shared__ __align__(16) float sW [16 * 64];
    __shared__ __align__(16) float sU1[64 * 68];

    const int tid  = threadIdx.x;
    const int brow = blockIdx.x * 64;
    const int cg = tid & 15, rg = tid >> 4;
    const int c0 = cg * 4,   r0 = rg * 4;

    const int lrow = tid >> 2;
    const int lcol = (tid & 3) * 4;
    const int grow = brow + lrow;
    const int kr = tid >> 4;
    const int wc = (tid & 15) * 4;

    float acc[4][4];
#pragma unroll
    for (int i = 0; i < 4; i++)
#pragma unroll
        for (int j = 0; j < 4; j++)
            acc[i][j] = b1[c0 + j];

#pragma unroll
    for (int p = 0; p < 2; p++) {
        const float* A = p ? agg : h_in;
        const float* W = U1 + (long long)p * 64 * 64;
        for (int k0 = 0; k0 < 64; k0 += 16) {
            float4 av = make_float4(0.f, 0.f, 0.f, 0.f);
            if (grow < M) {
                av = *(const float4*)(A + (long long)grow * 64 + k0 + lcol);
                if (p == 1)
                    *(float4*)(agg + (long long)grow * 64 + k0 + lcol) =
                        make_float4(0.f, 0.f, 0.f, 0.f);
            }
            sA[(lcol + 0) * 64 + lrow] = av.x;
            sA[(lcol + 1) * 64 + lrow] = av.y;
            sA[(lcol + 2) * 64 + lrow] = av.z;
            sA[(lcol + 3) * 64 + lrow] = av.w;
            *(float4*)&sW[kr * 64 + wc] =
                *(const float4*)(W + (long long)(k0 + kr) * 64 + wc);
            __syncthreads();
#pragma unroll
            for (int kk = 0; kk < 16; kk++) {
                float4 a = *(const float4*)&sA[kk * 64 + r0];
                float4 w = *(const float4*)&sW[kk * 64 + c0];
                float ar[4] = {a.x, a.y, a.z, a.w};
                float wr[4] = {w.x, w.y, w.z, w.w};
#pragma unroll
                for (int i = 0; i < 4; i++)
#pragma unroll
                    for (int j = 0; j < 4; j++)
                        acc[i][j] = fmaf(ar[i], wr[j], acc[i][j]);
            }
            __syncthreads();
        }
    }

    // u1 = relu(acc) -> smem, k-major
#pragma unroll
    for (int i = 0; i < 4; i++)
#pragma unroll
        for (int j = 0; j < 4; j++)
            sU1[(c0 + j) * 68 + r0 + i] = fmaxf(acc[i][j], 0.0f);
    __syncthreads();

    // phase 2: acc2 = u1 @ U2 + b2
    float acc2[4][4];
#pragma unroll
    for (int i = 0; i < 4; i++)
#pragma unroll
        for (int j = 0; j < 4; j++)
            acc2[i][j] = b2[c0 + j];

    for (int k0 = 0; k0 < 64; k0 += 16) {
        *(float4*)&sW[kr * 64 + wc] =
            *(const float4*)(U2 + (long long)(k0 + kr) * 64 + wc);
        __syncthreads();
#pragma unroll
        for (int kk = 0; kk < 16; kk++) {
            float4 a = *(const float4*)&sU1[(k0 + kk) * 68 + r0];
            float4 w = *(const float4*)&sW[kk * 64 + c0];
            float ar[4] = {a.x, a.y, a.z, a.w};
            float wr[4] = {w.x, w.y, w.z, w.w};
#pragma unroll
            for (int i = 0; i < 4; i++)
#pragma unroll
                for (int j = 0; j < 4; j++)
                    acc2[i][j] = fmaf(ar[i], wr[j], acc2[i][j]);
        }
        __syncthreads();
    }

#pragma unroll
    for (int i = 0; i < 4; i++) {
        int row = brow + r0 + i;
        if (row < M) {
            float4 hh = *(const float4*)(h_out + (long long)row * 64 + c0);
            hh.x += fmaxf(acc2[i][0], 0.f);
            hh.y += fmaxf(acc2[i][1], 0.f);
            hh.z += fmaxf(acc2[i][2], 0.f);
            hh.w += fmaxf(acc2[i][3], 0.f);
            *(float4*)(h_out + (long long)row * 64 + c0) = hh;
        }
    }
}

// ---------------- edge kernel: 16-edge warp tiles for 3 CTAs/SM ----------------
#define A_STRIDE 68
#define W_STRIDE 72
__global__ __launch_bounds__(256, 3)
void edge_kernel_mma(const float* __restrict__ Pab,
                     const float* __restrict__ W1c,   // 6 x 64
                     const float* __restrict__ W2,    // 64 x 64 (k x n)
                     const float* __restrict__ b2,    // 64
                     float* __restrict__ agg, int E)
{
    extern __shared__ __align__(16) char smem[];
    uint32_t* sA   = (uint32_t*)smem;                       // 8 warps x 16 x 68
    uint32_t* sW2  = (uint32_t*)(smem + 34816);             // 64 x 72 (tf32)
    float*    sW1c = (float*)(smem + 53248);                // 6 x 64
    float*    sB2  = (float*)(smem + 54784);                // 64

    const int tid = threadIdx.x;
    const int w   = tid >> 5;
    const int l   = tid & 31;

    for (int i = tid; i < 64 * 64; i += 256) {
        int k = i >> 6, n = i & 63;
        sW2[k * W_STRIDE + n] = f32_to_tf32(W2[i]);
    }
    for (int i = tid; i < 384; i += 256) sW1c[i] = W1c[i];
    if (tid < 64) sB2[tid] = b2[tid];
    __syncthreads();

    uint32_t* myA = sA + w * 16 * A_STRIDE;
    float*    myF = (float*)myA;
    const int gw = blockIdx.x * 8 + w;
    const int nW = gridDim.x * 8;
    const int nChunks = (E + 15) >> 4;

    const int lg  = l >> 2;       // 0..7 (mma row group)
    const int lt  = l & 3;        // 0..3
    const int er  = l >> 3;       // 0..3 (phase A: edge-in-quad)
    const int c4  = (l & 7) * 4;  // phase A col base
    const int eL  = l & 15;       // scan: edge within chunk
    const int chf = l >> 4;       // scan: column half

    unsigned lm_le;
    asm("mov.u32 %0, %%lanemask_le;" : "=r"(lm_le));

    // prefetch first record (each lane: its eL edge)
    float4 p0 = make_float4(0.f, 0.f, 0.f, 0.f);
    float4 p1 = make_float4(0.f, 0.f, 0.f, __int_as_float(-1));
    if (gw < nChunks) {
        long long eg = ((long long)gw << 4) + eL;
        if (eg < E) {
            const float* r = g_rec + eg * 8;
            p0 = *(const float4*)(r);
            p1 = *(const float4*)(r + 4);
        }
    }

    for (int ch = gw; ch < nChunks; ch += nW) {
        const long long e0 = (long long)ch << 4;
        const bool valid = (e0 + eL) < E;

        // consume prefetched record
        const float ea0 = p0.x, ea1 = p0.y, ea2 = p0.z, ea3 = p0.w;
        const float ea4 = p1.x, ea5 = p1.y;
        const int src = __float_as_int(p1.z);
        const int dst = __float_as_int(p1.w);

        // prefetch next chunk's record
        {
            const int chn = ch + nW;
            p0 = make_float4(0.f, 0.f, 0.f, 0.f);
            p1 = make_float4(0.f, 0.f, 0.f, __int_as_float(-1));
            if (chn < nChunks) {
                long long eg = ((long long)chn << 4) + eL;
                if (eg < E) {
                    const float* r = g_rec + eg * 8;
                    p0 = *(const float4*)(r);
                    p1 = *(const float4*)(r + 4);
                }
            }
        }

        // ---- phase A: m1, coalesced (4 consecutive edges x 8 lanes per pass) ----
#pragma unroll
        for (int it = 0; it < 4; it++) {
            const int e = 4 * it + er;   // 0..15; source lane e holds edge e
            const int de = __shfl_sync(0xffffffffu, dst, e);
            const int se = __shfl_sync(0xffffffffu, src, e);
            float eq[6];
            eq[0] = __shfl_sync(0xffffffffu, ea0, e);
            eq[1] = __shfl_sync(0xffffffffu, ea1, e);
            eq[2] = __shfl_sync(0xffffffffu, ea2, e);
            eq[3] = __shfl_sync(0xffffffffu, ea3, e);
            eq[4] = __shfl_sync(0xffffffffu, ea4, e);
            eq[5] = __shfl_sync(0xffffffffu, ea5, e);
            const bool ev = (e0 + e) < E;
            const float* par = Pab + (long long)de * 128;
            const float* pbr = Pab + (long long)se * 128 + 64;
#pragma unroll
            for (int h = 0; h < 2; h++) {
                const int c = c4 + 32 * h;
                float v0 = 0.f, v1 = 0.f, v2 = 0.f, v3 = 0.f;
                if (ev) {
                    float4 a = *(const float4*)(par + c);
                    float4 b = *(const float4*)(pbr + c);
                    v0 = a.x + b.x; v1 = a.y + b.y; v2 = a.z + b.z; v3 = a.w + b.w;
#pragma unroll
                    for (int q = 0; q < 6; q++) {
                        float4 wv = *(const float4*)(sW1c + q * 64 + c);
                        v0 = fmaf(eq[q], wv.x, v0);
                        v1 = fmaf(eq[q], wv.y, v1);
                        v2 = fmaf(eq[q], wv.z, v2);
                        v3 = fmaf(eq[q], wv.w, v3);
                    }
                }
                uint32_t r0 = f32_to_tf32(fmaxf(v0, 0.f));
                uint32_t r1 = f32_to_tf32(fmaxf(v1, 0.f));
                uint32_t r2 = f32_to_tf32(fmaxf(v2, 0.f));
                uint32_t r3 = f32_to_tf32(fmaxf(v3, 0.f));
                *(uint4*)(myA + e * A_STRIDE + c) = make_uint4(r0, r1, r2, r3);
            }
        }
        __syncwarp();

        // ---- mma: D(16x64) = m1 @ W2 ----
        float acc[8][4];
#pragma unroll
        for (int j = 0; j < 8; j++)
#pragma unroll
            for (int q = 0; q < 4; q++) acc[j][q] = 0.0f;

#pragma unroll
        for (int s = 0; s < 8; s++) {
            const int k0 = 8 * s;
            uint32_t af[4];
            const uint32_t* base = myA + lg * A_STRIDE + k0 + lt;
            af[0] = base[0];
            af[1] = base[8 * A_STRIDE];
            af[2] = base[4];
            af[3] = base[8 * A_STRIDE + 4];
#pragma unroll
            for (int j = 0; j < 8; j++) {
                uint32_t bf[2];
                bf[0] = sW2[(k0 + lt)     * W_STRIDE + 8 * j + lg];
                bf[1] = sW2[(k0 + lt + 4) * W_STRIDE + 8 * j + lg];
                mma_tf32(acc[j], af, bf);
            }
        }
        __syncwarp();

        // ---- transpose to smem (16 rows x 64 cols) ----
#pragma unroll
        for (int h = 0; h < 2; h++) {
            const int row = 8 * h + lg;
#pragma unroll
            for (int j = 0; j < 8; j++)
                *(float2*)(myF + row * A_STRIDE + 8 * j + 2 * lt) =
                    make_float2(acc[j][2 * h], acc[j][2 * h + 1]);
        }
        __syncwarp();

        // ---- segmented scan over sorted dst runs (16 edges, both col halves) ----
        {
            const int dprev = __shfl_up_sync(0xffffffffu, dst, 1);
            const int dnext = __shfl_down_sync(0xffffffffu, dst, 1);
            const bool head = (eL == 0) || (dprev != dst);
            const bool tail = (eL == 15) || (dnext != dst);
            const unsigned hm = __ballot_sync(0xffffffffu, head);
            const int hs = 31 - __clz(hm & lm_le);
            const int dist = l - hs;
            const int cb = 32 * chf;
            float* p = agg + (long long)dst * 64 + cb;
#pragma unroll
            for (int u = 0; u < 8; u++) {
                float4 t  = *(const float4*)(myF + eL * A_STRIDE + cb + 4 * u);
                float4 bb = *(const float4*)(sB2 + cb + 4 * u);
                float x0 = 0.f, x1 = 0.f, x2 = 0.f, x3 = 0.f;
                if (valid) {
                    x0 = fmaxf(t.x + bb.x, 0.f);
                    x1 = fmaxf(t.y + bb.y, 0.f);
                    x2 = fmaxf(t.z + bb.z, 0.f);
                    x3 = fmaxf(t.w + bb.w, 0.f);
                }
#pragma unroll
                for (int s = 1; s < 16; s <<= 1) {
                    float y0 = __shfl_up_sync(0xffffffffu, x0, s);
                    float y1 = __shfl_up_sync(0xffffffffu, x1, s);
                    float y2 = __shfl_up_sync(0xffffffffu, x2, s);
                    float y3 = __shfl_up_sync(0xffffffffu, x3, s);
                    if (dist >= s) { x0 += y0; x1 += y1; x2 += y2; x3 += y3; }
                }
                if (tail && valid)
                    asm volatile("red.global.add.v4.f32 [%0], {%1, %2, %3, %4};"
                                 :: "l"(p + 4 * u), "f"(x0), "f"(x1), "f"(x2), "f"(x3)
                                 : "memory");
            }
        }
        __syncwarp();
    }
}

// ---------------- prediction head ---------------------------------------------
__global__ __launch_bounds__(256)
void pred_kernel(const float* __restrict__ h, const float* __restrict__ pw,
                 const float* __restrict__ pb, float* __restrict__ out, int M)
{
    __shared__ float spw[64];
    __shared__ float swarp[8];
    if (threadIdx.x < 64) spw[threadIdx.x] = pw[threadIdx.x];
    __syncthreads();

    float sum = 0.0f;
    for (long long row = (long long)blockIdx.x * blockDim.x + threadIdx.x; row < M;
         row += (long long)gridDim.x * blockDim.x) {
        const float4* hr = (const float4*)(h + row * 64);
#pragma unroll
        for (int u = 0; u < 16; u++) {
            float4 v = hr[u];
            sum = fmaf(v.x, spw[4 * u + 0], sum);
            sum = fmaf(v.y, spw[4 * u + 1], sum);
            sum = fmaf(v.z, spw[4 * u + 2], sum);
            sum = fmaf(v.w, spw[4 * u + 3], sum);
        }
    }
#pragma unroll
    for (int o = 16; o > 0; o >>= 1) sum += __shfl_down_sync(0xffffffffu, sum, o);
    if ((threadIdx.x & 31) == 0) swarp[threadIdx.x >> 5] = sum;
    __syncthreads();
    if (threadIdx.x < 8) {
        float s = swarp[threadIdx.x];
#pragma unroll
        for (int o = 4; o > 0; o >>= 1) s += __shfl_down_sync(0xffu, s, o);
        if (threadIdx.x == 0) {
            if (blockIdx.x == 0) s = fmaf(pb[0], (float)M, s);
            atomicAdd(out, s);
        }
    }
}

// ---------------- launch ------------------------------------------------------
extern "C" void kernel_launch(void* const* d_in, const int* in_sizes, int n_in,
                              void* d_out, int out_size)
{
    const float* x       = (const float*)d_in[0];
    const void*  ei      = d_in[1];
    const float* eattr   = (const float*)d_in[2];
    const float* lin_w   = (const float*)d_in[3];
    const float* lin_b   = (const float*)d_in[4];
    const float* msg_w1  = (const float*)d_in[5];
    const float* msg_b1  = (const float*)d_in[6];
    const float* msg_w2  = (const float*)d_in[7];
    const float* msg_b2  = (const float*)d_in[8];
    const float* upd_w1  = (const float*)d_in[9];
    const float* upd_b1  = (const float*)d_in[10];
    const float* upd_w2  = (const float*)d_in[11];
    const float* upd_b2  = (const float*)d_in[12];
    const float* pred_w  = (const float*)d_in[13];
    const float* pred_b  = (const float*)d_in[14];

    const int M = in_sizes[0] / 128;   // 50000
    const int E = in_sizes[2] / 6;     // 800000

    float *h, *Pab, *agg;
    int* cnt;
    cudaGetSymbolAddress((void**)&h,   g_h);
    cudaGetSymbolAddress((void**)&Pab, g_Pab);
    cudaGetSymbolAddress((void**)&agg, g_agg);
    cudaGetSymbolAddress((void**)&cnt, g_cnt);

    const int gN = (M + 63) / 64;      // 782
    const int SM_EDGE = 55040;
    cudaFuncSetAttribute(edge_kernel_mma,
                         cudaFuncAttributeMaxDynamicSharedMemorySize, SM_EDGE);
    const int nChunks = (E + 15) / 16;
    int gEdge = 148 * 3;
    if (gEdge * 8 > nChunks) gEdge = (nChunks + 7) / 8;
    if (gEdge < 1) gEdge = 1;

    // ---- sort edges by dst (once; reused by all 4 layers) ----
    detect_idx_kernel<<<1, 32>>>((const unsigned int*)ei);
    cudaMemsetAsync(cnt, 0, NSCAN * sizeof(int));
    hist_kernel<<<1024, 256>>>(ei, E);
    scan1_kernel<<<NSCAN / 1024, 1024>>>();
    scan2_kernel<<<1, 32>>>(NSCAN / 1024);
    scan3_kernel<<<NSCAN / 1024, 1024>>>();
    scatter_kernel<<<1024, 256>>>(ei, eattr, E);

    // input projection
    node_gemm64<false><<<gN, 256>>>(x, lin_w, 128, lin_b, h, M);

    for (int l = 0; l < 4; l++) {
        const float* W1 = msg_w1 + (size_t)l * 134 * 64;
        node_gemm_dual<<<gN, 512>>>(h, W1, msg_b1 + l * 64, Pab, M);
        edge_kernel_mma<<<gEdge, 256, SM_EDGE>>>(Pab,
                                                 W1 + 128 * 64,
                                                 msg_w2 + (size_t)l * 64 * 64,
                                                 msg_b2 + l * 64, agg, E);
        fused_update<<<gN, 256>>>(h, upd_w1 + (size_t)l * 128 * 64,
                                  upd_b1 + l * 64,
                                  upd_w2 + (size_t)l * 64 * 64,
                                  upd_b2 + l * 64, agg, h, M);
    }

    cudaMemsetAsync(d_out, 0, sizeof(float));
    pred_kernel<<<256, 256>>>(h, pred_w, pred_b, (float*)d_out, M);
}

// round 11
// speedup vs baseline: 1.0758x; 1.0179x over previous
#include <cuda_runtime.h>
#include <cstdint>

#define EMB 64
#define NN_MAX 50000
#define NSCAN 50176          // 49 * 1024
#define NE_MAX 800000
#define NE_PAD (NE_MAX + 64)

// ---------------- scratch (static device memory; no allocations) ----------------
__device__ __align__(128) float g_h  [NN_MAX * EMB];
__device__ __align__(128) float g_Pab[NN_MAX * 128];   // [Pa | Pb] per node
__device__ __align__(128) float g_agg[NN_MAX * EMB];   // zero at launch entry (invariant)
__device__ int g_is64;

// sort scratch
__device__ int   g_cnt [NSCAN];
__device__ int   g_inc [NSCAN];
__device__ int   g_cur [NSCAN];
__device__ int   g_bsum[64];
// packed sorted edge records: {ea0..ea5, src(bits), dst(bits)} per edge (32B)
__device__ __align__(128) float g_rec[NE_PAD * 8];

// ---------------- helpers ------------------------------------------------------
__device__ __forceinline__ uint32_t f32_to_tf32(float f) {
    uint32_t u;
    asm("cvt.rna.tf32.f32 %0, %1;" : "=r"(u) : "f"(f));
    return u;
}
__device__ __forceinline__ void mma_tf32(float* c, const uint32_t* a, const uint32_t* b) {
    asm volatile(
        "mma.sync.aligned.m16n8k8.row.col.f32.tf32.tf32.f32 "
        "{%0,%1,%2,%3}, {%4,%5,%6,%7}, {%8,%9}, {%0,%1,%2,%3};"
        : "+f"(c[0]), "+f"(c[1]), "+f"(c[2]), "+f"(c[3])
        : "r"(a[0]), "r"(a[1]), "r"(a[2]), "r"(a[3]), "r"(b[0]), "r"(b[1]));
}

// ---------------- detect whether edge_index is int64 or int32 ----------------
__global__ void detect_idx_kernel(const unsigned int* __restrict__ p)
{
    if (threadIdx.x == 0 && blockIdx.x == 0) {
        unsigned int v = 0;
#pragma unroll
        for (int k = 0; k < 64; k++) v |= p[2 * k + 1];
        g_is64 = (v == 0) ? 1 : 0;
    }
}

// ---------------- counting sort by dst ----------------------------------------
__global__ void hist_kernel(const void* __restrict__ ei, int E)
{
    const int is64 = g_is64;
    for (long long e = (long long)blockIdx.x * blockDim.x + threadIdx.x; e < E;
         e += (long long)gridDim.x * blockDim.x) {
        int dst = is64 ? (int)((const long long*)ei)[(long long)E + e]
                       : ((const int*)ei)[(long long)E + e];
        atomicAdd(&g_cnt[dst], 1);
    }
}

__global__ __launch_bounds__(1024) void scan1_kernel()
{
    const int t = threadIdx.x, b = blockIdx.x;
    const int i = b * 1024 + t;
    const int lane = t & 31, wid = t >> 5;
    int x = g_cnt[i];
#pragma unroll
    for (int s = 1; s < 32; s <<= 1) {
        int u = __shfl_up_sync(0xffffffffu, x, s);
        if (lane >= s) x += u;
    }
    __shared__ int ws[32];
    if (lane == 31) ws[wid] = x;
    __syncthreads();
    if (wid == 0) {
        int y = ws[lane];
#pragma unroll
        for (int s = 1; s < 32; s <<= 1) {
            int u = __shfl_up_sync(0xffffffffu, y, s);
            if (lane >= s) y += u;
        }
        ws[lane] = y;
    }
    __syncthreads();
    int inc = x + (wid ? ws[wid - 1] : 0);
    g_inc[i] = inc;
    if (t == 1023) g_bsum[b] = inc;
}

// parallel exclusive scan of block sums (nb <= 64)
__global__ __launch_bounds__(64) void scan2_kernel(int nb)
{
    __shared__ int s[64];
    const int t = threadIdx.x;
    const int v = (t < nb) ? g_bsum[t] : 0;
    s[t] = v;
    __syncthreads();
#pragma unroll
    for (int o = 1; o < 64; o <<= 1) {
        int x = (t >= o) ? s[t - o] : 0;
        __syncthreads();
        s[t] += x;
        __syncthreads();
    }
    if (t < nb) g_bsum[t] = s[t] - v;
}

__global__ __launch_bounds__(1024) void scan3_kernel()
{
    const int i = blockIdx.x * 1024 + threadIdx.x;
    g_cur[i] = g_inc[i] - g_cnt[i] + g_bsum[blockIdx.x];
}

__global__ void scatter_kernel(const void* __restrict__ ei,
                               const float* __restrict__ eattr, int E)
{
    const int is64 = g_is64;
    for (long long e = (long long)blockIdx.x * blockDim.x + threadIdx.x; e < E;
         e += (long long)gridDim.x * blockDim.x) {
        int src, dst;
        if (is64) {
            src = (int)((const long long*)ei)[e];
            dst = (int)((const long long*)ei)[(long long)E + e];
        } else {
            src = ((const int*)ei)[e];
            dst = ((const int*)ei)[(long long)E + e];
        }
        float ea[6];
#pragma unroll
        for (int q = 0; q < 6; q++) ea[q] = eattr[e * 6 + q];
        int pos = atomicAdd(&g_cur[dst], 1);
        float* r = g_rec + (long long)pos * 8;
        *(float4*)(r)     = make_float4(ea[0], ea[1], ea[2], ea[3]);
        *(float4*)(r + 4) = make_float4(ea[4], ea[5],
                                        __int_as_float(src), __int_as_float(dst));
    }
}

// ---------------- generic node GEMM (input projection), 32-k chunks ------------
template <bool RELU>
__global__ __launch_bounds__(256)
void node_gemm64(const float* __restrict__ A1, const float* __restrict__ W1k, int K1,
                 const float* __restrict__ bias, float* __restrict__ C, int M)
{
    __shared__ __align__(16) float sA[32 * 64];
    __shared__ __align__(16) float sW[32 * 64];

    const int tid  = threadIdx.x;
    const int brow = blockIdx.x * 64;
    const int cg = tid & 15, rg = tid >> 4;
    const int c0 = cg * 4,   r0 = rg * 4;

    float acc[4][4];
#pragma unroll
    for (int i = 0; i < 4; i++)
#pragma unroll
        for (int j = 0; j < 4; j++)
            acc[i][j] = bias[c0 + j];

    const int lrow = tid >> 2;          // 0..63
    const int lcol = (tid & 3) * 4;     // 0,4,8,12
    const int grow = brow + lrow;
    const int kr = tid >> 4;            // 0..15
    const int wc = (tid & 15) * 4;

    for (int kc = 0; kc < K1; kc += 32) {
#pragma unroll
        for (int q = 0; q < 2; q++) {
            const int col = lcol + 16 * q;
            float4 av = make_float4(0.f, 0.f, 0.f, 0.f);
            if (grow < M)
                av = *(const float4*)(A1 + (long long)grow * K1 + kc + col);
            sA[(col + 0) * 64 + lrow] = av.x;
            sA[(col + 1) * 64 + lrow] = av.y;
            sA[(col + 2) * 64 + lrow] = av.z;
            sA[(col + 3) * 64 + lrow] = av.w;
            *(float4*)&sW[(kr + 16 * q) * 64 + wc] =
                *(const float4*)(W1k + (long long)(kc + kr + 16 * q) * 64 + wc);
        }
        __syncthreads();
#pragma unroll
        for (int kk = 0; kk < 32; kk++) {
            float4 a = *(const float4*)&sA[kk * 64 + r0];
            float4 w = *(const float4*)&sW[kk * 64 + c0];
            float ar[4] = {a.x, a.y, a.z, a.w};
            float wr[4] = {w.x, w.y, w.z, w.w};
#pragma unroll
            for (int i = 0; i < 4; i++)
#pragma unroll
                for (int j = 0; j < 4; j++)
                    acc[i][j] = fmaf(ar[i], wr[j], acc[i][j]);
        }
        __syncthreads();
    }

#pragma unroll
    for (int i = 0; i < 4; i++) {
        int row = brow + r0 + i;
        if (row < M) {
            float v0 = acc[i][0], v1 = acc[i][1], v2 = acc[i][2], v3 = acc[i][3];
            if (RELU) {
                v0 = fmaxf(v0, 0.f); v1 = fmaxf(v1, 0.f);
                v2 = fmaxf(v2, 0.f); v3 = fmaxf(v3, 0.f);
            }
            *(float4*)(C + (long long)row * 64 + c0) = make_float4(v0, v1, v2, v3);
        }
    }
}

// ---------------- dual node GEMM: Pab = [h@W1a + b1 | h@W1b], 32-k chunks ------
__global__ __launch_bounds__(512)
void node_gemm_dual(const float* __restrict__ h, const float* __restrict__ W1,
                    const float* __restrict__ b1, float* __restrict__ Pab, int M)
{
    __shared__ __align__(16) float sA[32 * 64];
    __shared__ __align__(16) float sW[32 * 128];

    const int tid  = threadIdx.x;
    const int brow = blockIdx.x * 64;
    const int cg = tid & 31, rg = tid >> 5;
    const int c0 = cg * 4,   r0 = rg * 4;

    float acc[4][4];
#pragma unroll
    for (int i = 0; i < 4; i++)
#pragma unroll
        for (int j = 0; j < 4; j++)
            acc[i][j] = (c0 < 64) ? b1[c0 + j] : 0.0f;

    const int arow = tid >> 3;          // 0..63
    const int acol = (tid & 7) * 4;     // 0..28
    const int garow = brow + arow;
    const int kr = tid >> 5;            // 0..15
    const int wc = (tid & 31) * 4;      // 0..124

    for (int kc = 0; kc < 64; kc += 32) {
        {
            float4 av = make_float4(0.f, 0.f, 0.f, 0.f);
            if (garow < M)
                av = *(const float4*)(h + (long long)garow * 64 + kc + acol);
            sA[(acol + 0) * 64 + arow] = av.x;
            sA[(acol + 1) * 64 + arow] = av.y;
            sA[(acol + 2) * 64 + arow] = av.z;
            sA[(acol + 3) * 64 + arow] = av.w;
        }
#pragma unroll
        for (int q = 0; q < 2; q++) {
            const int row = kr + 16 * q;
            const float* src = (wc < 64)
                ? (W1 + (long long)(kc + row) * 64 + wc)
                : (W1 + (long long)(64 + kc + row) * 64 + (wc - 64));
            *(float4*)&sW[row * 128 + wc] = *(const float4*)src;
        }
        __syncthreads();
#pragma unroll
        for (int kk = 0; kk < 32; kk++) {
            float4 a = *(const float4*)&sA[kk * 64 + r0];
            float4 w = *(const float4*)&sW[kk * 128 + c0];
            float ar[4] = {a.x, a.y, a.z, a.w};
            float wr[4] = {w.x, w.y, w.z, w.w};
#pragma unroll
            for (int i = 0; i < 4; i++)
#pragma unroll
                for (int j = 0; j < 4; j++)
                    acc[i][j] = fmaf(ar[i], wr[j], acc[i][j]);
        }
        __syncthreads();
    }

#pragma unroll
    for (int i = 0; i < 4; i++) {
        int row = brow + r0 + i;
        if (row < M)
            *(float4*)(Pab + (long long)row * 128 + c0) =
                make_float4(acc[i][0], acc[i][1], acc[i][2], acc[i][3]);
    }
}

// ---------------- fused update: h += relu(relu([h|agg]@U1+b1)@U2+b2) ----------
// 32-k chunks; zeroes agg after reading it (restores launch-entry invariant).
__global__ __launch_bounds__(256)
void fused_update(const float* __restrict__ h_in, const float* __restrict__ U1,
                  const float* __restrict__ b1, const float* __restrict__ U2,
                  const float* __restrict__ b2, float* agg,
                  float* __restrict__ h_out, int M)
{
    __shared__ __align__(16) float sA [32 * 64];
    __shared__ __align__(16) float sW [32 * 64];
    __shared__ __align__(16) float sU1[64 * 68];

    const int tid  = threadIdx.x;
    const int brow = blockIdx.x * 64;
    const int cg = tid & 15, rg = tid >> 4;
    const int c0 = cg * 4,   r0 = rg * 4;

    const int lrow = tid >> 2;
    const int lcol = (tid & 3) * 4;
    const int grow = brow + lrow;
    const int kr = tid >> 4;
    const int wc = (tid & 15) * 4;

    float acc[4][4];
#pragma unroll
    for (int i = 0; i < 4; i++)
#pragma unroll
        for (int j = 0; j < 4; j++)
            acc[i][j] = b1[c0 + j];

#pragma unroll
    for (int p = 0; p < 2; p++) {
        const float* A = p ? agg : h_in;
        const float* W = U1 + (long long)p * 64 * 64;
        for (int kc = 0; kc < 64; kc += 32) {
#pragma unroll
            for (int q = 0; q < 2; q++) {
                const int col = lcol + 16 * q;
                float4 av = make_float4(0.f, 0.f, 0.f, 0.f);
                if (grow < M) {
                    av = *(const float4*)(A + (long long)grow * 64 + kc + col);
                    if (p == 1)
                        *(float4*)(agg + (long long)grow * 64 + kc + col) =
                            make_float4(0.f, 0.f, 0.f, 0.f);
                }
                sA[(col + 0) * 64 + lrow] = av.x;
                sA[(col + 1) * 64 + lrow] = av.y;
                sA[(col + 2) * 64 + lrow] = av.z;
                sA[(col + 3) * 64 + lrow] = av.w;
                *(float4*)&sW[(kr + 16 * q) * 64 + wc] =
                    *(const float4*)(W + (long long)(kc + kr + 16 * q) * 64 + wc);
            }
            __syncthreads();
#pragma unroll
            for (int kk = 0; kk < 32; kk++) {
                float4 a = *(const float4*)&sA[kk * 64 + r0];
                float4 w = *(const float4*)&sW[kk * 64 + c0];
                float ar[4] = {a.x, a.y, a.z, a.w};
                float wr[4] = {w.x, w.y, w.z, w.w};
#pragma unroll
                for (int i = 0; i < 4; i++)
#pragma unroll
                    for (int j = 0; j < 4; j++)
                        acc[i][j] = fmaf(ar[i], wr[j], acc[i][j]);
            }
            __syncthreads();
        }
    }

    // u1 = relu(acc) -> smem, k-major
#pragma unroll
    for (int i = 0; i < 4; i++)
#pragma unroll
        for (int j = 0; j < 4; j++)
            sU1[(c0 + j) * 68 + r0 + i] = fmaxf(acc[i][j], 0.0f);
    __syncthreads();

    // phase 2: acc2 = u1 @ U2 + b2
    float acc2[4][4];
#pragma unroll
    for (int i = 0; i < 4; i++)
#pragma unroll
        for (int j = 0; j < 4; j++)
            acc2[i][j] = b2[c0 + j];

    for (int kc = 0; kc < 64; kc += 32) {
#pragma unroll
        for (int q = 0; q < 2; q++)
            *(float4*)&sW[(kr + 16 * q) * 64 + wc] =
                *(const float4*)(U2 + (long long)(kc + kr + 16 * q) * 64 + wc);
        __syncthreads();
#pragma unroll
        for (int kk = 0; kk < 32; kk++) {
            float4 a = *(const float4*)&sU1[(kc + kk) * 68 + r0];
            float4 w = *(const float4*)&sW[kk * 64 + c0];
            float ar[4] = {a.x, a.y, a.z, a.w};
            float wr[4] = {w.x, w.y, w.z, w.w};
#pragma unroll
            for (int i = 0; i < 4; i++)
#pragma unroll
                for (int j = 0; j < 4; j++)
                    acc2[i][j] = fmaf(ar[i], wr[j], acc2[i][j]);
        }
        __syncthreads();
    }

#pragma unroll
    for (int i = 0; i < 4; i++) {
        int row = brow + r0 + i;
        if (row < M) {
            float4 hh = *(const float4*)(h_out + (long long)row * 64 + c0);
            hh.x += fmaxf(acc2[i][0], 0.f);
            hh.y += fmaxf(acc2[i][1], 0.f);
            hh.z += fmaxf(acc2[i][2], 0.f);
            hh.w += fmaxf(acc2[i][3], 0.f);
            *(float4*)(h_out + (long long)row * 64 + c0) = hh;
        }
    }
}

// ---------------- edge kernel: 16-edge warp tiles for 3 CTAs/SM ----------------
#define A_STRIDE 68
#define W_STRIDE 72
__global__ __launch_bounds__(256, 3)
void edge_kernel_mma(const float* __restrict__ Pab,
                     const float* __restrict__ W1c,   // 6 x 64
                     const float* __restrict__ W2,    // 64 x 64 (k x n)
                     const float* __restrict__ b2,    // 64
                     float* __restrict__ agg, int E)
{
    extern __shared__ __align__(16) char smem[];
    uint32_t* sA   = (uint32_t*)smem;                       // 8 warps x 16 x 68
    uint32_t* sW2  = (uint32_t*)(smem + 34816);             // 64 x 72 (tf32)
    float*    sW1c = (float*)(smem + 53248);                // 6 x 64
    float*    sB2  = (float*)(smem + 54784);                // 64

    const int tid = threadIdx.x;
    const int w   = tid >> 5;
    const int l   = tid & 31;

    for (int i = tid; i < 64 * 64; i += 256) {
        int k = i >> 6, n = i & 63;
        sW2[k * W_STRIDE + n] = f32_to_tf32(W2[i]);
    }
    for (int i = tid; i < 384; i += 256) sW1c[i] = W1c[i];
    if (tid < 64) sB2[tid] = b2[tid];
    __syncthreads();

    uint32_t* myA = sA + w * 16 * A_STRIDE;
    float*    myF = (float*)myA;
    const int gw = blockIdx.x * 8 + w;
    const int nW = gridDim.x * 8;
    const int nChunks = (E + 15) >> 4;

    const int lg  = l >> 2;
    const int lt  = l & 3;
    const int er  = l >> 3;
    const int c4  = (l & 7) * 4;
    const int eL  = l & 15;
    const int chf = l >> 4;

    unsigned lm_le;
    asm("mov.u32 %0, %%lanemask_le;" : "=r"(lm_le));

    // prefetch first record (each lane: its eL edge)
    float4 p0 = make_float4(0.f, 0.f, 0.f, 0.f);
    float4 p1 = make_float4(0.f, 0.f, 0.f, __int_as_float(-1));
    if (gw < nChunks) {
        long long eg = ((long long)gw << 4) + eL;
        if (eg < E) {
            const float* r = g_rec + eg * 8;
            p0 = *(const float4*)(r);
            p1 = *(const float4*)(r + 4);
        }
    }

    for (int ch = gw; ch < nChunks; ch += nW) {
        const long long e0 = (long long)ch << 4;
        const bool valid = (e0 + eL) < E;

        const float ea0 = p0.x, ea1 = p0.y, ea2 = p0.z, ea3 = p0.w;
        const float ea4 = p1.x, ea5 = p1.y;
        const int src = __float_as_int(p1.z);
        const int dst = __float_as_int(p1.w);

        // prefetch next chunk's record
        {
            const int chn = ch + nW;
            p0 = make_float4(0.f, 0.f, 0.f, 0.f);
            p1 = make_float4(0.f, 0.f, 0.f, __int_as_float(-1));
            if (chn < nChunks) {
                long long eg = ((long long)chn << 4) + eL;
                if (eg < E) {
                    const float* r = g_rec + eg * 8;
                    p0 = *(const float4*)(r);
                    p1 = *(const float4*)(r + 4);
                }
            }
        }

        // ---- phase A: m1, coalesced (4 consecutive edges x 8 lanes per pass) ----
#pragma unroll
        for (int it = 0; it < 4; it++) {
            const int e = 4 * it + er;
            const int de = __shfl_sync(0xffffffffu, dst, e);
            const int se = __shfl_sync(0xffffffffu, src, e);
            float eq[6];
            eq[0] = __shfl_sync(0xffffffffu, ea0, e);
            eq[1] = __shfl_sync(0xffffffffu, ea1, e);
            eq[2] = __shfl_sync(0xffffffffu, ea2, e);
            eq[3] = __shfl_sync(0xffffffffu, ea3, e);
            eq[4] = __shfl_sync(0xffffffffu, ea4, e);
            eq[5] = __shfl_sync(0xffffffffu, ea5, e);
            const bool ev = (e0 + e) < E;
            const float* par = Pab + (long long)de * 128;
            const float* pbr = Pab + (long long)se * 128 + 64;
#pragma unroll
            for (int h = 0; h < 2; h++) {
                const int c = c4 + 32 * h;
                float v0 = 0.f, v1 = 0.f, v2 = 0.f, v3 = 0.f;
                if (ev) {
                    float4 a = *(const float4*)(par + c);
                    float4 b = *(const float4*)(pbr + c);
                    v0 = a.x + b.x; v1 = a.y + b.y; v2 = a.z + b.z; v3 = a.w + b.w;
#pragma unroll
                    for (int q = 0; q < 6; q++) {
                        float4 wv = *(const float4*)(sW1c + q * 64 + c);
                        v0 = fmaf(eq[q], wv.x, v0);
                        v1 = fmaf(eq[q], wv.y, v1);
                        v2 = fmaf(eq[q], wv.z, v2);
                        v3 = fmaf(eq[q], wv.w, v3);
                    }
                }
                uint32_t r0 = f32_to_tf32(fmaxf(v0, 0.f));
                uint32_t r1 = f32_to_tf32(fmaxf(v1, 0.f));
                uint32_t r2 = f32_to_tf32(fmaxf(v2, 0.f));
                uint32_t r3 = f32_to_tf32(fmaxf(v3, 0.f));
                *(uint4*)(myA + e * A_STRIDE + c) = make_uint4(r0, r1, r2, r3);
            }
        }
        __syncwarp();

        // ---- mma: D(16x64) = m1 @ W2 ----
        float acc[8][4];
#pragma unroll
        for (int j = 0; j < 8; j++)
#pragma unroll
            for (int q = 0; q < 4; q++) acc[j][q] = 0.0f;

#pragma unroll
        for (int s = 0; s < 8; s++) {
            const int k0 = 8 * s;
            uint32_t af[4];
            const uint32_t* base = myA + lg * A_STRIDE + k0 + lt;
            af[0] = base[0];
            af[1] = base[8 * A_STRIDE];
            af[2] = base[4];
            af[3] = base[8 * A_STRIDE + 4];
#pragma unroll
            for (int j = 0; j < 8; j++) {
                uint32_t bf[2];
                bf[0] = sW2[(k0 + lt)     * W_STRIDE + 8 * j + lg];
                bf[1] = sW2[(k0 + lt + 4) * W_STRIDE + 8 * j + lg];
                mma_tf32(acc[j], af, bf);
            }
        }
        __syncwarp();

        // ---- transpose to smem (16 rows x 64 cols) ----
#pragma unroll
        for (int h = 0; h < 2; h++) {
            const int row = 8 * h + lg;
#pragma unroll
            for (int j = 0; j < 8; j++)
                *(float2*)(myF + row * A_STRIDE + 8 * j + 2 * lt) =
                    make_float2(acc[j][2 * h], acc[j][2 * h + 1]);
        }
        __syncwarp();

        // ---- segmented scan over sorted dst runs (16 edges, both col halves) ----
        {
            const int dprev = __shfl_up_sync(0xffffffffu, dst, 1);
            const int dnext = __shfl_down_sync(0xffffffffu, dst, 1);
            const bool head = (eL == 0) || (dprev != dst);
            const bool tail = (eL == 15) || (dnext != dst);
            const unsigned hm = __ballot_sync(0xffffffffu, head);
            const int hs = 31 - __clz(hm & lm_le);
            const int dist = l - hs;
            const int cb = 32 * chf;
            float* p = agg + (long long)dst * 64 + cb;
#pragma unroll
            for (int u = 0; u < 8; u++) {
                float4 t  = *(const float4*)(myF + eL * A_STRIDE + cb + 4 * u);
                float4 bb = *(const float4*)(sB2 + cb + 4 * u);
                float x0 = 0.f, x1 = 0.f, x2 = 0.f, x3 = 0.f;
                if (valid) {
                    x0 = fmaxf(t.x + bb.x, 0.f);
                    x1 = fmaxf(t.y + bb.y, 0.f);
                    x2 = fmaxf(t.z + bb.z, 0.f);
                    x3 = fmaxf(t.w + bb.w, 0.f);
                }
#pragma unroll
                for (int s = 1; s < 16; s <<= 1) {
                    float y0 = __shfl_up_sync(0xffffffffu, x0, s);
                    float y1 = __shfl_up_sync(0xffffffffu, x1, s);
                    float y2 = __shfl_up_sync(0xffffffffu, x2, s);
                    float y3 = __shfl_up_sync(0xffffffffu, x3, s);
                    if (dist >= s) { x0 += y0; x1 += y1; x2 += y2; x3 += y3; }
                }
                if (tail && valid)
                    asm volatile("red.global.add.v4.f32 [%0], {%1, %2, %3, %4};"
                                 :: "l"(p + 4 * u), "f"(x0), "f"(x1), "f"(x2), "f"(x3)
                                 : "memory");
            }
        }
        __syncwarp();
    }
}

// ---------------- prediction head ---------------------------------------------
__global__ __launch_bounds__(256)
void pred_kernel(const float* __restrict__ h, const float* __restrict__ pw,
                 const float* __restrict__ pb, float* __restrict__ out, int M)
{
    __shared__ float spw[64];
    __shared__ float swarp[8];
    if (threadIdx.x < 64) spw[threadIdx.x] = pw[threadIdx.x];
    __syncthreads();

    float sum = 0.0f;
    for (long long row = (long long)blockIdx.x * blockDim.x + threadIdx.x; row < M;
         row += (long long)gridDim.x * blockDim.x) {
        const float4* hr = (const float4*)(h + row * 64);
#pragma unroll
        for (int u = 0; u < 16; u++) {
            float4 v = hr[u];
            sum = fmaf(v.x, spw[4 * u + 0], sum);
            sum = fmaf(v.y, spw[4 * u + 1], sum);
            sum = fmaf(v.z, spw[4 * u + 2], sum);
            sum = fmaf(v.w, spw[4 * u + 3], sum);
        }
    }
#pragma unroll
    for (int o = 16; o > 0; o >>= 1) sum += __shfl_down_sync(0xffffffffu, sum, o);
    if ((threadIdx.x & 31) == 0) swarp[threadIdx.x >> 5] = sum;
    __syncthreads();
    if (threadIdx.x < 8) {
        float s = swarp[threadIdx.x];
#pragma unroll
        for (int o = 4; o > 0; o >>= 1) s += __shfl_down_sync(0xffu, s, o);
        if (threadIdx.x == 0) {
            if (blockIdx.x == 0) s = fmaf(pb[0], (float)M, s);
            atomicAdd(out, s);
        }
    }
}

// ---------------- launch ------------------------------------------------------
extern "C" void kernel_launch(void* const* d_in, const int* in_sizes, int n_in,
                              void* d_out, int out_size)
{
    const float* x       = (const float*)d_in[0];
    const void*  ei      = d_in[1];
    const float* eattr   = (const float*)d_in[2];
    const float* lin_w   = (const float*)d_in[3];
    const float* lin_b   = (const float*)d_in[4];
    const float* msg_w1  = (const float*)d_in[5];
    const float* msg_b1  = (const float*)d_in[6];
    const float* msg_w2  = (const float*)d_in[7];
    const float* msg_b2  = (const float*)d_in[8];
    const float* upd_w1  = (const float*)d_in[9];
    const float* upd_b1  = (const float*)d_in[10];
    const float* upd_w2  = (const float*)d_in[11];
    const float* upd_b2  = (const float*)d_in[12];
    const float* pred_w  = (const float*)d_in[13];
    const float* pred_b  = (const float*)d_in[14];

    const int M = in_sizes[0] / 128;   // 50000
    const int E = in_sizes[2] / 6;     // 800000

    float *h, *Pab, *agg;
    int* cnt;
    cudaGetSymbolAddress((void**)&h,   g_h);
    cudaGetSymbolAddress((void**)&Pab, g_Pab);
    cudaGetSymbolAddress((void**)&agg, g_agg);
    cudaGetSymbolAddress((void**)&cnt, g_cnt);

    const int gN = (M + 63) / 64;      // 782
    const int SM_EDGE = 55040;
    cudaFuncSetAttribute(edge_kernel_mma,
                         cudaFuncAttributeMaxDynamicSharedMemorySize, SM_EDGE);
    const int nChunks = (E + 15) / 16;
    int gEdge = 148 * 3;
    if (gEdge * 8 > nChunks) gEdge = (nChunks + 7) / 8;
    if (gEdge < 1) gEdge = 1;

    // ---- sort edges by dst (once; reused by all 4 layers) ----
    detect_idx_kernel<<<1, 32>>>((const unsigned int*)ei);
    cudaMemsetAsync(cnt, 0, NSCAN * sizeof(int));
    hist_kernel<<<1024, 256>>>(ei, E);
    scan1_kernel<<<NSCAN / 1024, 1024>>>();
    scan2_kernel<<<1, 64>>>(NSCAN / 1024);
    scan3_kernel<<<NSCAN / 1024, 1024>>>();
    scatter_kernel<<<1024, 256>>>(ei, eattr, E);

    // input projection
    node_gemm64<false><<<gN, 256>>>(x, lin_w, 128, lin_b, h, M);

    for (int l = 0; l < 4; l++) {
        const float* W1 = msg_w1 + (size_t)l * 134 * 64;
        node_gemm_dual<<<gN, 512>>>(h, W1, msg_b1 + l * 64, Pab, M);
        edge_kernel_mma<<<gEdge, 256, SM_EDGE>>>(Pab,
                                                 W1 + 128 * 64,
                                                 msg_w2 + (size_t)l * 64 * 64,
                                                 msg_b2 + l * 64, agg, E);
        fused_update<<<gN, 256>>>(h, upd_w1 + (size_t)l * 128 * 64,
                                  upd_b1 + l * 64,
                                  upd_w2 + (size_t)l * 64 * 64,
                                  upd_b2 + l * 64, agg, h, M);
    }

    cudaMemsetAsync(d_out, 0, sizeof(float));
    pred_kernel<<<256, 256>>>(h, pred_w, pred_b, (float*)d_out, M);
}

// round 12
// speedup vs baseline: 1.0914x; 1.0144x over previous
#include <cuda_runtime.h>
#include <cstdint>

#define EMB 64
#define NN_MAX 50000
#define NSCAN 50176          // 49 * 1024
#define NE_MAX 800000
#define NE_PAD (NE_MAX + 64)

// ---------------- scratch (static device memory; no allocations) ----------------
__device__ __align__(128) float g_h  [NN_MAX * EMB];
__device__ __align__(128) float g_Pab[NN_MAX * 128];   // [Pa | Pb] per node
__device__ __align__(128) float g_agg[NN_MAX * EMB];   // zero at launch entry (invariant)
__device__ int g_is64;

// sort scratch
__device__ int   g_cnt [NSCAN];
__device__ int   g_inc [NSCAN];
__device__ int   g_cur [NSCAN];
__device__ int   g_bsum[64];
// packed sorted edge records: {ea0..ea5, src(bits), dst(bits)} per edge (32B)
__device__ __align__(128) float g_rec[NE_PAD * 8];

// ---------------- helpers ------------------------------------------------------
__device__ __forceinline__ uint32_t f32_to_tf32(float f) {
    uint32_t u;
    asm("cvt.rna.tf32.f32 %0, %1;" : "=r"(u) : "f"(f));
    return u;
}
__device__ __forceinline__ void mma_tf32(float* c, const uint32_t* a, const uint32_t* b) {
    asm volatile(
        "mma.sync.aligned.m16n8k8.row.col.f32.tf32.tf32.f32 "
        "{%0,%1,%2,%3}, {%4,%5,%6,%7}, {%8,%9}, {%0,%1,%2,%3};"
        : "+f"(c[0]), "+f"(c[1]), "+f"(c[2]), "+f"(c[3])
        : "r"(a[0]), "r"(a[1]), "r"(a[2]), "r"(a[3]), "r"(b[0]), "r"(b[1]));
}

// ---------------- detect whether edge_index is int64 or int32 ----------------
__global__ void detect_idx_kernel(const unsigned int* __restrict__ p)
{
    if (threadIdx.x == 0 && blockIdx.x == 0) {
        unsigned int v = 0;
#pragma unroll
        for (int k = 0; k < 64; k++) v |= p[2 * k + 1];
        g_is64 = (v == 0) ? 1 : 0;
    }
}

// ---------------- counting sort by dst ----------------------------------------
__global__ void hist_kernel(const void* __restrict__ ei, int E)
{
    const int is64 = g_is64;
    for (long long e = (long long)blockIdx.x * blockDim.x + threadIdx.x; e < E;
         e += (long long)gridDim.x * blockDim.x) {
        int dst = is64 ? (int)((const long long*)ei)[(long long)E + e]
                       : ((const int*)ei)[(long long)E + e];
        atomicAdd(&g_cnt[dst], 1);
    }
}

__global__ __launch_bounds__(1024) void scan1_kernel()
{
    const int t = threadIdx.x, b = blockIdx.x;
    const int i = b * 1024 + t;
    const int lane = t & 31, wid = t >> 5;
    int x = g_cnt[i];
#pragma unroll
    for (int s = 1; s < 32; s <<= 1) {
        int u = __shfl_up_sync(0xffffffffu, x, s);
        if (lane >= s) x += u;
    }
    __shared__ int ws[32];
    if (lane == 31) ws[wid] = x;
    __syncthreads();
    if (wid == 0) {
        int y = ws[lane];
#pragma unroll
        for (int s = 1; s < 32; s <<= 1) {
            int u = __shfl_up_sync(0xffffffffu, y, s);
            if (lane >= s) y += u;
        }
        ws[lane] = y;
    }
    __syncthreads();
    int inc = x + (wid ? ws[wid - 1] : 0);
    g_inc[i] = inc;
    if (t == 1023) g_bsum[b] = inc;
}

// parallel exclusive scan of block sums (nb <= 64)
__global__ __launch_bounds__(64) void scan2_kernel(int nb)
{
    __shared__ int s[64];
    const int t = threadIdx.x;
    const int v = (t < nb) ? g_bsum[t] : 0;
    s[t] = v;
    __syncthreads();
#pragma unroll
    for (int o = 1; o < 64; o <<= 1) {
        int x = (t >= o) ? s[t - o] : 0;
        __syncthreads();
        s[t] += x;
        __syncthreads();
    }
    if (t < nb) g_bsum[t] = s[t] - v;
}

__global__ __launch_bounds__(1024) void scan3_kernel()
{
    const int i = blockIdx.x * 1024 + threadIdx.x;
    g_cur[i] = g_inc[i] - g_cnt[i] + g_bsum[blockIdx.x];
}

__global__ void scatter_kernel(const void* __restrict__ ei,
                               const float* __restrict__ eattr, int E)
{
    const int is64 = g_is64;
    for (long long e = (long long)blockIdx.x * blockDim.x + threadIdx.x; e < E;
         e += (long long)gridDim.x * blockDim.x) {
        int src, dst;
        if (is64) {
            src = (int)((const long long*)ei)[e];
            dst = (int)((const long long*)ei)[(long long)E + e];
        } else {
            src = ((const int*)ei)[e];
            dst = ((const int*)ei)[(long long)E + e];
        }
        float ea[6];
#pragma unroll
        for (int q = 0; q < 6; q++) ea[q] = eattr[e * 6 + q];
        int pos = atomicAdd(&g_cur[dst], 1);
        float* r = g_rec + (long long)pos * 8;
        *(float4*)(r)     = make_float4(ea[0], ea[1], ea[2], ea[3]);
        *(float4*)(r + 4) = make_float4(ea[4], ea[5],
                                        __int_as_float(src), __int_as_float(dst));
    }
}

// ---------------- dual phase helper: Pab = [hT@W1a + b1 | hT@W1b] --------------
// sH: 64 k x 64 rows (k-major, stride 68). sW: scratch >= 32*136 floats.
__device__ __forceinline__ void dual_phase(const float* __restrict__ sH,
                                           float* __restrict__ sW,
                                           const float* __restrict__ W1n,
                                           const float* __restrict__ b1n,
                                           float* __restrict__ Pab,
                                           int brow, int M, int tid)
{
    const int cg = tid & 15, rg = tid >> 4;
    const int c0 = cg * 4,   r0 = rg * 4;

    float a3[4][4], b3[4][4];
#pragma unroll
    for (int i = 0; i < 4; i++)
#pragma unroll
        for (int j = 0; j < 4; j++) {
            a3[i][j] = b1n[c0 + j];
            b3[i][j] = 0.0f;
        }

#pragma unroll
    for (int kc = 0; kc < 64; kc += 32) {
        // stage W1n chunk: 32 k-rows x 128 cols at stride 136
#pragma unroll
        for (int s = 0; s < 4; s++) {
            const int f = tid * 4 + s;
            const int kk = f >> 5;
            const int w4 = (f & 31) * 4;
            const float* src = (w4 < 64)
                ? (W1n + (long long)(kc + kk) * 64 + w4)
                : (W1n + (long long)(64 + kc + kk) * 64 + (w4 - 64));
            *(float4*)&sW[kk * 136 + w4] = *(const float4*)src;
        }
        __syncthreads();
#pragma unroll
        for (int kk = 0; kk < 32; kk++) {
            float4 a  = *(const float4*)&sH[(kc + kk) * 68 + r0];
            float4 w0 = *(const float4*)&sW[kk * 136 + c0];
            float4 w1 = *(const float4*)&sW[kk * 136 + c0 + 64];
            float ar[4] = {a.x, a.y, a.z, a.w};
            float wa[4] = {w0.x, w0.y, w0.z, w0.w};
            float wb[4] = {w1.x, w1.y, w1.z, w1.w};
#pragma unroll
            for (int i = 0; i < 4; i++)
#pragma unroll
                for (int j = 0; j < 4; j++) {
                    a3[i][j] = fmaf(ar[i], wa[j], a3[i][j]);
                    b3[i][j] = fmaf(ar[i], wb[j], b3[i][j]);
                }
        }
        __syncthreads();
    }

#pragma unroll
    for (int i = 0; i < 4; i++) {
        const int row = brow + r0 + i;
        if (row < M) {
            *(float4*)(Pab + (long long)row * 128 + c0) =
                make_float4(a3[i][0], a3[i][1], a3[i][2], a3[i][3]);
            *(float4*)(Pab + (long long)row * 128 + c0 + 64) =
                make_float4(b3[i][0], b3[i][1], b3[i][2], b3[i][3]);
        }
    }
}

// ---------------- proj_dual: h = x@Win + bin; Pab = [h@W1a+b1 | h@W1b] ---------
__global__ __launch_bounds__(256)
void proj_dual(const float* __restrict__ x, const float* __restrict__ Win,
               const float* __restrict__ bin,
               const float* __restrict__ W1n, const float* __restrict__ b1n,
               float* __restrict__ h, float* __restrict__ Pab, int M)
{
    __shared__ __align__(16) float sA[32 * 64];
    __shared__ __align__(16) float sW[32 * 136];
    __shared__ __align__(16) float sH[64 * 68];

    const int tid  = threadIdx.x;
    const int brow = blockIdx.x * 64;
    const int cg = tid & 15, rg = tid >> 4;
    const int c0 = cg * 4,   r0 = rg * 4;

    const int lrow = tid >> 2;
    const int lcol = (tid & 3) * 4;
    const int grow = brow + lrow;
    const int kr = tid >> 4;
    const int wc = (tid & 15) * 4;

    float acc[4][4];
#pragma unroll
    for (int i = 0; i < 4; i++)
#pragma unroll
        for (int j = 0; j < 4; j++)
            acc[i][j] = bin[c0 + j];

    for (int kc = 0; kc < 128; kc += 32) {
#pragma unroll
        for (int q = 0; q < 2; q++) {
            const int col = lcol + 16 * q;
            float4 av = make_float4(0.f, 0.f, 0.f, 0.f);
            if (grow < M)
                av = *(const float4*)(x + (long long)grow * 128 + kc + col);
            sA[(col + 0) * 64 + lrow] = av.x;
            sA[(col + 1) * 64 + lrow] = av.y;
            sA[(col + 2) * 64 + lrow] = av.z;
            sA[(col + 3) * 64 + lrow] = av.w;
            *(float4*)&sW[(kr + 16 * q) * 64 + wc] =
                *(const float4*)(Win + (long long)(kc + kr + 16 * q) * 64 + wc);
        }
        __syncthreads();
#pragma unroll
        for (int kk = 0; kk < 32; kk++) {
            float4 a = *(const float4*)&sA[kk * 64 + r0];
            float4 w = *(const float4*)&sW[kk * 64 + c0];
            float ar[4] = {a.x, a.y, a.z, a.w};
            float wr[4] = {w.x, w.y, w.z, w.w};
#pragma unroll
            for (int i = 0; i < 4; i++)
#pragma unroll
                for (int j = 0; j < 4; j++)
                    acc[i][j] = fmaf(ar[i], wr[j], acc[i][j]);
        }
        __syncthreads();
    }

    // write h (gmem) and stage into sH (k-major)
#pragma unroll
    for (int i = 0; i < 4; i++) {
        const int row = brow + r0 + i;
        const bool v = row < M;
        if (v)
            *(float4*)(h + (long long)row * 64 + c0) =
                make_float4(acc[i][0], acc[i][1], acc[i][2], acc[i][3]);
#pragma unroll
        for (int j = 0; j < 4; j++)
            sH[(c0 + j) * 68 + r0 + i] = v ? acc[i][j] : 0.0f;
    }
    __syncthreads();

    dual_phase(sH, sW, W1n, b1n, Pab, brow, M, tid);
}

// ---------------- update_dual: h += relu(relu([h|agg]U1+b1)U2+b2); Pab = dual --
// Zeroes agg after reading (restores launch-entry invariant).
template <bool DO_DUAL>
__global__ __launch_bounds__(256)
void update_dual(const float* __restrict__ h_in, const float* __restrict__ U1,
                 const float* __restrict__ b1, const float* __restrict__ U2,
                 const float* __restrict__ b2, float* agg,
                 float* __restrict__ h_out,
                 const float* __restrict__ W1n, const float* __restrict__ b1n,
                 float* __restrict__ Pab, int M)
{
    __shared__ __align__(16) float sA [32 * 64];
    __shared__ __align__(16) float sW [32 * 136];
    __shared__ __align__(16) float sU1[64 * 68];   // phase2 input; reused as sH

    const int tid  = threadIdx.x;
    const int brow = blockIdx.x * 64;
    const int cg = tid & 15, rg = tid >> 4;
    const int c0 = cg * 4,   r0 = rg * 4;

    const int lrow = tid >> 2;
    const int lcol = (tid & 3) * 4;
    const int grow = brow + lrow;
    const int kr = tid >> 4;
    const int wc = (tid & 15) * 4;

    float acc[4][4];
#pragma unroll
    for (int i = 0; i < 4; i++)
#pragma unroll
        for (int j = 0; j < 4; j++)
            acc[i][j] = b1[c0 + j];

#pragma unroll
    for (int p = 0; p < 2; p++) {
        const float* A = p ? agg : h_in;
        const float* W = U1 + (long long)p * 64 * 64;
        for (int kc = 0; kc < 64; kc += 32) {
#pragma unroll
            for (int q = 0; q < 2; q++) {
                const int col = lcol + 16 * q;
                float4 av = make_float4(0.f, 0.f, 0.f, 0.f);
                if (grow < M) {
                    av = *(const float4*)(A + (long long)grow * 64 + kc + col);
                    if (p == 1)
                        *(float4*)(agg + (long long)grow * 64 + kc + col) =
                            make_float4(0.f, 0.f, 0.f, 0.f);
                }
                sA[(col + 0) * 64 + lrow] = av.x;
                sA[(col + 1) * 64 + lrow] = av.y;
                sA[(col + 2) * 64 + lrow] = av.z;
                sA[(col + 3) * 64 + lrow] = av.w;
                *(float4*)&sW[(kr + 16 * q) * 64 + wc] =
                    *(const float4*)(W + (long long)(kc + kr + 16 * q) * 64 + wc);
            }
            __syncthreads();
#pragma unroll
            for (int kk = 0; kk < 32; kk++) {
                float4 a = *(const float4*)&sA[kk * 64 + r0];
                float4 w = *(const float4*)&sW[kk * 64 + c0];
                float ar[4] = {a.x, a.y, a.z, a.w};
                float wr[4] = {w.x, w.y, w.z, w.w};
#pragma unroll
                for (int i = 0; i < 4; i++)
#pragma unroll
                    for (int j = 0; j < 4; j++)
                        acc[i][j] = fmaf(ar[i], wr[j], acc[i][j]);
            }
            __syncthreads();
        }
    }

    // u1 = relu(acc) -> smem, k-major
#pragma unroll
    for (int i = 0; i < 4; i++)
#pragma unroll
        for (int j = 0; j < 4; j++)
            sU1[(c0 + j) * 68 + r0 + i] = fmaxf(acc[i][j], 0.0f);
    __syncthreads();

    // phase 2: acc2 = u1 @ U2 + b2
    float acc2[4][4];
#pragma unroll
    for (int i = 0; i < 4; i++)
#pragma unroll
        for (int j = 0; j < 4; j++)
            acc2[i][j] = b2[c0 + j];

    for (int kc = 0; kc < 64; kc += 32) {
#pragma unroll
        for (int q = 0; q < 2; q++)
            *(float4*)&sW[(kr + 16 * q) * 64 + wc] =
                *(const float4*)(U2 + (long long)(kc + kr + 16 * q) * 64 + wc);
        __syncthreads();
#pragma unroll
        for (int kk = 0; kk < 32; kk++) {
            float4 a = *(const float4*)&sU1[(kc + kk) * 68 + r0];
            float4 w = *(const float4*)&sW[kk * 64 + c0];
            float ar[4] = {a.x, a.y, a.z, a.w};
            float wr[4] = {w.x, w.y, w.z, w.w};
#pragma unroll
            for (int i = 0; i < 4; i++)
#pragma unroll
                for (int j = 0; j < 4; j++)
                    acc2[i][j] = fmaf(ar[i], wr[j], acc2[i][j]);
        }
        __syncthreads();
    }

    // epilogue: h_new = h_old + relu(acc2); write h_out (+ stage into sU1 as sH)
#pragma unroll
    for (int i = 0; i < 4; i++) {
        const int row = brow + r0 + i;
        const bool v = row < M;
        float hn[4] = {0.f, 0.f, 0.f, 0.f};
        if (v) {
            float4 hh = *(const float4*)(h_out + (long long)row * 64 + c0);
            hn[0] = hh.x + fmaxf(acc2[i][0], 0.f);
            hn[1] = hh.y + fmaxf(acc2[i][1], 0.f);
            hn[2] = hh.z + fmaxf(acc2[i][2], 0.f);
            hn[3] = hh.w + fmaxf(acc2[i][3], 0.f);
            *(float4*)(h_out + (long long)row * 64 + c0) =
                make_float4(hn[0], hn[1], hn[2], hn[3]);
        }
        if (DO_DUAL) {
#pragma unroll
            for (int j = 0; j < 4; j++)
                sU1[(c0 + j) * 68 + r0 + i] = hn[j];
        }
    }

    if (DO_DUAL) {
        __syncthreads();
        dual_phase(sU1, sW, W1n, b1n, Pab, brow, M, tid);
    }
}

// ---------------- edge kernel: 16-edge warp tiles for 3 CTAs/SM ----------------
#define A_STRIDE 68
#define W_STRIDE 72
__global__ __launch_bounds__(256, 3)
void edge_kernel_mma(const float* __restrict__ Pab,
                     const float* __restrict__ W1c,   // 6 x 64
                     const float* __restrict__ W2,    // 64 x 64 (k x n)
                     const float* __restrict__ b2,    // 64
                     float* __restrict__ agg, int E)
{
    extern __shared__ __align__(16) char smem[];
    uint32_t* sA   = (uint32_t*)smem;                       // 8 warps x 16 x 68
    uint32_t* sW2  = (uint32_t*)(smem + 34816);             // 64 x 72 (tf32)
    float*    sW1c = (float*)(smem + 53248);                // 6 x 64
    float*    sB2  = (float*)(smem + 54784);                // 64

    const int tid = threadIdx.x;
    const int w   = tid >> 5;
    const int l   = tid & 31;

    for (int i = tid; i < 64 * 64; i += 256) {
        int k = i >> 6, n = i & 63;
        sW2[k * W_STRIDE + n] = f32_to_tf32(W2[i]);
    }
    for (int i = tid; i < 384; i += 256) sW1c[i] = W1c[i];
    if (tid < 64) sB2[tid] = b2[tid];
    __syncthreads();

    uint32_t* myA = sA + w * 16 * A_STRIDE;
    float*    myF = (float*)myA;
    const int gw = blockIdx.x * 8 + w;
    const int nW = gridDim.x * 8;
    const int nChunks = (E + 15) >> 4;

    const int lg  = l >> 2;
    const int lt  = l & 3;
    const int er  = l >> 3;
    const int c4  = (l & 7) * 4;
    const int eL  = l & 15;
    const int chf = l >> 4;

    unsigned lm_le;
    asm("mov.u32 %0, %%lanemask_le;" : "=r"(lm_le));

    // prefetch first record (each lane: its eL edge)
    float4 p0 = make_float4(0.f, 0.f, 0.f, 0.f);
    float4 p1 = make_float4(0.f, 0.f, 0.f, __int_as_float(-1));
    if (gw < nChunks) {
        long long eg = ((long long)gw << 4) + eL;
        if (eg < E) {
            const float* r = g_rec + eg * 8;
            p0 = *(const float4*)(r);
            p1 = *(const float4*)(r + 4);
        }
    }

    for (int ch = gw; ch < nChunks; ch += nW) {
        const long long e0 = (long long)ch << 4;
        const bool valid = (e0 + eL) < E;

        const float ea0 = p0.x, ea1 = p0.y, ea2 = p0.z, ea3 = p0.w;
        const float ea4 = p1.x, ea5 = p1.y;
        const int src = __float_as_int(p1.z);
        const int dst = __float_as_int(p1.w);

        // prefetch next chunk's record
        {
            const int chn = ch + nW;
            p0 = make_float4(0.f, 0.f, 0.f, 0.f);
            p1 = make_float4(0.f, 0.f, 0.f, __int_as_float(-1));
            if (chn < nChunks) {
                long long eg = ((long long)chn << 4) + eL;
                if (eg < E) {
                    const float* r = g_rec + eg * 8;
                    p0 = *(const float4*)(r);
                    p1 = *(const float4*)(r + 4);
                }
            }
        }

        // ---- phase A: m1, coalesced (4 consecutive edges x 8 lanes per pass) ----
#pragma unroll
        for (int it = 0; it < 4; it++) {
            const int e = 4 * it + er;
            const int de = __shfl_sync(0xffffffffu, dst, e);
            const int se = __shfl_sync(0xffffffffu, src, e);
            float eq[6];
            eq[0] = __shfl_sync(0xffffffffu, ea0, e);
            eq[1] = __shfl_sync(0xffffffffu, ea1, e);
            eq[2] = __shfl_sync(0xffffffffu, ea2, e);
            eq[3] = __shfl_sync(0xffffffffu, ea3, e);
            eq[4] = __shfl_sync(0xffffffffu, ea4, e);
            eq[5] = __shfl_sync(0xffffffffu, ea5, e);
            const bool ev = (e0 + e) < E;
            const float* par = Pab + (long long)de * 128;
            const float* pbr = Pab + (long long)se * 128 + 64;
#pragma unroll
            for (int h = 0; h < 2; h++) {
                const int c = c4 + 32 * h;
                float v0 = 0.f, v1 = 0.f, v2 = 0.f, v3 = 0.f;
                if (ev) {
                    float4 a = *(const float4*)(par + c);
                    float4 b = *(const float4*)(pbr + c);
                    v0 = a.x + b.x; v1 = a.y + b.y; v2 = a.z + b.z; v3 = a.w + b.w;
#pragma unroll
                    for (int q = 0; q < 6; q++) {
                        float4 wv = *(const float4*)(sW1c + q * 64 + c);
                        v0 = fmaf(eq[q], wv.x, v0);
                        v1 = fmaf(eq[q], wv.y, v1);
                        v2 = fmaf(eq[q], wv.z, v2);
                        v3 = fmaf(eq[q], wv.w, v3);
                    }
                }
                uint32_t r0 = f32_to_tf32(fmaxf(v0, 0.f));
                uint32_t r1 = f32_to_tf32(fmaxf(v1, 0.f));
                uint32_t r2 = f32_to_tf32(fmaxf(v2, 0.f));
                uint32_t r3 = f32_to_tf32(fmaxf(v3, 0.f));
                *(uint4*)(myA + e * A_STRIDE + c) = make_uint4(r0, r1, r2, r3);
            }
        }
        __syncwarp();

        // ---- mma: D(16x64) = m1 @ W2 ----
        float acc[8][4];
#pragma unroll
        for (int j = 0; j < 8; j++)
#pragma unroll
            for (int q = 0; q < 4; q++) acc[j][q] = 0.0f;

#pragma unroll
        for (int s = 0; s < 8; s++) {
            const int k0 = 8 * s;
            uint32_t af[4];
            const uint32_t* base = myA + lg * A_STRIDE + k0 + lt;
            af[0] = base[0];
            af[1] = base[8 * A_STRIDE];
            af[2] = base[4];
            af[3] = base[8 * A_STRIDE + 4];
#pragma unroll
            for (int j = 0; j < 8; j++) {
                uint32_t bf[2];
                bf[0] = sW2[(k0 + lt)     * W_STRIDE + 8 * j + lg];
                bf[1] = sW2[(k0 + lt + 4) * W_STRIDE + 8 * j + lg];
                mma_tf32(acc[j], af, bf);
            }
        }
        __syncwarp();

        // ---- transpose to smem (16 rows x 64 cols) ----
#pragma unroll
        for (int h = 0; h < 2; h++) {
            const int row = 8 * h + lg;
#pragma unroll
            for (int j = 0; j < 8; j++)
                *(float2*)(myF + row * A_STRIDE + 8 * j + 2 * lt) =
                    make_float2(acc[j][2 * h], acc[j][2 * h + 1]);
        }
        __syncwarp();

        // ---- segmented scan over sorted dst runs (16 edges, both col halves) ----
        {
            const int dprev = __shfl_up_sync(0xffffffffu, dst, 1);
            const int dnext = __shfl_down_sync(0xffffffffu, dst, 1);
            const bool head = (eL == 0) || (dprev != dst);
            const bool tail = (eL == 15) || (dnext != dst);
            const unsigned hm = __ballot_sync(0xffffffffu, head);
            const int hs = 31 - __clz(hm & lm_le);
            const int dist = l - hs;
            const int cb = 32 * chf;
            float* p = agg + (long long)dst * 64 + cb;
#pragma unroll
            for (int u = 0; u < 8; u++) {
                float4 t  = *(const float4*)(myF + eL * A_STRIDE + cb + 4 * u);
                float4 bb = *(const float4*)(sB2 + cb + 4 * u);
                float x0 = 0.f, x1 = 0.f, x2 = 0.f, x3 = 0.f;
                if (valid) {
                    x0 = fmaxf(t.x + bb.x, 0.f);
                    x1 = fmaxf(t.y + bb.y, 0.f);
                    x2 = fmaxf(t.z + bb.z, 0.f);
                    x3 = fmaxf(t.w + bb.w, 0.f);
                }
#pragma unroll
                for (int s = 1; s < 16; s <<= 1) {
                    float y0 = __shfl_up_sync(0xffffffffu, x0, s);
                    float y1 = __shfl_up_sync(0xffffffffu, x1, s);
                    float y2 = __shfl_up_sync(0xffffffffu, x2, s);
                    float y3 = __shfl_up_sync(0xffffffffu, x3, s);
                    if (dist >= s) { x0 += y0; x1 += y1; x2 += y2; x3 += y3; }
                }
                if (tail && valid)
                    asm volatile("red.global.add.v4.f32 [%0], {%1, %2, %3, %4};"
                                 :: "l"(p + 4 * u), "f"(x0), "f"(x1), "f"(x2), "f"(x3)
                                 : "memory");
            }
        }
        __syncwarp();
    }
}

// ---------------- prediction head ---------------------------------------------
__global__ __launch_bounds__(256)
void pred_kernel(const float* __restrict__ h, const float* __restrict__ pw,
                 const float* __restrict__ pb, float* __restrict__ out, int M)
{
    __shared__ float spw[64];
    __shared__ float swarp[8];
    if (threadIdx.x < 64) spw[threadIdx.x] = pw[threadIdx.x];
    __syncthreads();

    float sum = 0.0f;
    for (long long row = (long long)blockIdx.x * blockDim.x + threadIdx.x; row < M;
         row += (long long)gridDim.x * blockDim.x) {
        const float4* hr = (const float4*)(h + row * 64);
#pragma unroll
        for (int u = 0; u < 16; u++) {
            float4 v = hr[u];
            sum = fmaf(v.x, spw[4 * u + 0], sum);
            sum = fmaf(v.y, spw[4 * u + 1], sum);
            sum = fmaf(v.z, spw[4 * u + 2], sum);
            sum = fmaf(v.w, spw[4 * u + 3], sum);
        }
    }
#pragma unroll
    for (int o = 16; o > 0; o >>= 1) sum += __shfl_down_sync(0xffffffffu, sum, o);
    if ((threadIdx.x & 31) == 0) swarp[threadIdx.x >> 5] = sum;
    __syncthreads();
    if (threadIdx.x < 8) {
        float s = swarp[threadIdx.x];
#pragma unroll
        for (int o = 4; o > 0; o >>= 1) s += __shfl_down_sync(0xffu, s, o);
        if (threadIdx.x == 0) {
            if (blockIdx.x == 0) s = fmaf(pb[0], (float)M, s);
            atomicAdd(out, s);
        }
    }
}

// ---------------- launch ------------------------------------------------------
extern "C" void kernel_launch(void* const* d_in, const int* in_sizes, int n_in,
                              void* d_out, int out_size)
{
    const float* x       = (const float*)d_in[0];
    const void*  ei      = d_in[1];
    const float* eattr   = (const float*)d_in[2];
    const float* lin_w   = (const float*)d_in[3];
    const float* lin_b   = (const float*)d_in[4];
    const float* msg_w1  = (const float*)d_in[5];
    const float* msg_b1  = (const float*)d_in[6];
    const float* msg_w2  = (const float*)d_in[7];
    const float* msg_b2  = (const float*)d_in[8];
    const float* upd_w1  = (const float*)d_in[9];
    const float* upd_b1  = (const float*)d_in[10];
    const float* upd_w2  = (const float*)d_in[11];
    const float* upd_b2  = (const float*)d_in[12];
    const float* pred_w  = (const float*)d_in[13];
    const float* pred_b  = (const float*)d_in[14];

    const int M = in_sizes[0] / 128;   // 50000
    const int E = in_sizes[2] / 6;     // 800000

    float *h, *Pab, *agg;
    int* cnt;
    cudaGetSymbolAddress((void**)&h,   g_h);
    cudaGetSymbolAddress((void**)&Pab, g_Pab);
    cudaGetSymbolAddress((void**)&agg, g_agg);
    cudaGetSymbolAddress((void**)&cnt, g_cnt);

    const int gN = (M + 63) / 64;      // 782
    const int SM_EDGE = 55040;
    cudaFuncSetAttribute(edge_kernel_mma,
                         cudaFuncAttributeMaxDynamicSharedMemorySize, SM_EDGE);
    const int nChunks = (E + 15) / 16;
    int gEdge = 148 * 3;
    if (gEdge * 8 > nChunks) gEdge = (nChunks + 7) / 8;
    if (gEdge < 1) gEdge = 1;

    // ---- sort edges by dst (once; reused by all 4 layers) ----
    detect_idx_kernel<<<1, 32>>>((const unsigned int*)ei);
    cudaMemsetAsync(cnt, 0, NSCAN * sizeof(int));
    hist_kernel<<<1024, 256>>>(ei, E);
    scan1_kernel<<<NSCAN / 1024, 1024>>>();
    scan2_kernel<<<1, 64>>>(NSCAN / 1024);
    scan3_kernel<<<NSCAN / 1024, 1024>>>();
    scatter_kernel<<<1024, 256>>>(ei, eattr, E);

    // input projection fused with layer-0 dual
    proj_dual<<<gN, 256>>>(x, lin_w, lin_b,
                           msg_w1, msg_b1, h, Pab, M);

    for (int l = 0; l < 4; l++) {
        const float* W1 = msg_w1 + (size_t)l * 134 * 64;
        edge_kernel_mma<<<gEdge, 256, SM_EDGE>>>(Pab,
                                                 W1 + 128 * 64,
                                                 msg_w2 + (size_t)l * 64 * 64,
                                                 msg_b2 + l * 64, agg, E);
        if (l < 3) {
            const float* W1n = msg_w1 + (size_t)(l + 1) * 134 * 64;
            update_dual<true><<<gN, 256>>>(h, upd_w1 + (size_t)l * 128 * 64,
                                           upd_b1 + l * 64,
                                           upd_w2 + (size_t)l * 64 * 64,
                                           upd_b2 + l * 64, agg, h,
                                           W1n, msg_b1 + (l + 1) * 64, Pab, M);
        } else {
            update_dual<false><<<gN, 256>>>(h, upd_w1 + (size_t)l * 128 * 64,
                                            upd_b1 + l * 64,
                                            upd_w2 + (size_t)l * 64 * 64,
                                            upd_b2 + l * 64, agg, h,
                                            nullptr, nullptr, nullptr, M);
        }
    }

    cudaMemsetAsync(d_out, 0, sizeof(float));
    pred_kernel<<<256, 256>>>(h, pred_w, pred_b, (float*)d_out, M);
}

// round 13
// speedup vs baseline: 1.1882x; 1.0887x over previous
#include <cuda_runtime.h>
#include <cstdint>

#define EMB 64
#define NN_MAX 50000
#define NSCAN 50176          // 49 * 1024
#define NE_MAX 800000
#define NE_PAD (NE_MAX + 64)

// ---------------- scratch (static device memory; no allocations) ----------------
__device__ __align__(128) float g_h  [NN_MAX * EMB];
__device__ __align__(128) float g_Pab[NN_MAX * 128];   // [Pa | Pb] per node
__device__ __align__(128) float g_agg[NN_MAX * EMB];   // zero at launch entry (invariant)
__device__ int g_is64;

// sort scratch
__device__ int   g_cnt [NSCAN];
__device__ int   g_inc [NSCAN];
__device__ int   g_cur [NSCAN];
__device__ int   g_bsum[64];
// packed sorted edge records: {ea0..ea5, src(bits), dst(bits)} per edge (32B)
__device__ __align__(128) float g_rec[NE_PAD * 8];

// ---------------- helpers ------------------------------------------------------
__device__ __forceinline__ uint32_t f32_to_tf32(float f) {
    uint32_t u;
    asm("cvt.rna.tf32.f32 %0, %1;" : "=r"(u) : "f"(f));
    return u;
}
__device__ __forceinline__ void mma_tf32(float* c, const uint32_t* a, const uint32_t* b) {
    asm volatile(
        "mma.sync.aligned.m16n8k8.row.col.f32.tf32.tf32.f32 "
        "{%0,%1,%2,%3}, {%4,%5,%6,%7}, {%8,%9}, {%0,%1,%2,%3};"
        : "+f"(c[0]), "+f"(c[1]), "+f"(c[2]), "+f"(c[3])
        : "r"(a[0]), "r"(a[1]), "r"(a[2]), "r"(a[3]), "r"(b[0]), "r"(b[1]));
}

// ---------------- detect whether edge_index is int64 or int32 ----------------
__global__ void detect_idx_kernel(const unsigned int* __restrict__ p)
{
    if (threadIdx.x == 0 && blockIdx.x == 0) {
        unsigned int v = 0;
#pragma unroll
        for (int k = 0; k < 64; k++) v |= p[2 * k + 1];
        g_is64 = (v == 0) ? 1 : 0;
    }
}

// ---------------- counting sort by dst ----------------------------------------
__global__ void hist_kernel(const void* __restrict__ ei, int E)
{
    const int is64 = g_is64;
    for (long long e = (long long)blockIdx.x * blockDim.x + threadIdx.x; e < E;
         e += (long long)gridDim.x * blockDim.x) {
        int dst = is64 ? (int)((const long long*)ei)[(long long)E + e]
                       : ((const int*)ei)[(long long)E + e];
        atomicAdd(&g_cnt[dst], 1);
    }
}

__global__ __launch_bounds__(1024) void scan1_kernel()
{
    const int t = threadIdx.x, b = blockIdx.x;
    const int i = b * 1024 + t;
    const int lane = t & 31, wid = t >> 5;
    int x = g_cnt[i];
#pragma unroll
    for (int s = 1; s < 32; s <<= 1) {
        int u = __shfl_up_sync(0xffffffffu, x, s);
        if (lane >= s) x += u;
    }
    __shared__ int ws[32];
    if (lane == 31) ws[wid] = x;
    __syncthreads();
    if (wid == 0) {
        int y = ws[lane];
#pragma unroll
        for (int s = 1; s < 32; s <<= 1) {
            int u = __shfl_up_sync(0xffffffffu, y, s);
            if (lane >= s) y += u;
        }
        ws[lane] = y;
    }
    __syncthreads();
    int inc = x + (wid ? ws[wid - 1] : 0);
    g_inc[i] = inc;
    if (t == 1023) g_bsum[b] = inc;
}

// parallel exclusive scan of block sums (nb <= 64)
__global__ __launch_bounds__(64) void scan2_kernel(int nb)
{
    __shared__ int s[64];
    const int t = threadIdx.x;
    const int v = (t < nb) ? g_bsum[t] : 0;
    s[t] = v;
    __syncthreads();
#pragma unroll
    for (int o = 1; o < 64; o <<= 1) {
        int x = (t >= o) ? s[t - o] : 0;
        __syncthreads();
        s[t] += x;
        __syncthreads();
    }
    if (t < nb) g_bsum[t] = s[t] - v;
}

__global__ __launch_bounds__(1024) void scan3_kernel()
{
    const int i = blockIdx.x * 1024 + threadIdx.x;
    g_cur[i] = g_inc[i] - g_cnt[i] + g_bsum[blockIdx.x];
}

__global__ void scatter_kernel(const void* __restrict__ ei,
                               const float* __restrict__ eattr, int E)
{
    const int is64 = g_is64;
    for (long long e = (long long)blockIdx.x * blockDim.x + threadIdx.x; e < E;
         e += (long long)gridDim.x * blockDim.x) {
        int src, dst;
        if (is64) {
            src = (int)((const long long*)ei)[e];
            dst = (int)((const long long*)ei)[(long long)E + e];
        } else {
            src = ((const int*)ei)[e];
            dst = ((const int*)ei)[(long long)E + e];
        }
        float ea[6];
#pragma unroll
        for (int q = 0; q < 6; q++) ea[q] = eattr[e * 6 + q];
        int pos = atomicAdd(&g_cur[dst], 1);
        float* r = g_rec + (long long)pos * 8;
        *(float4*)(r)     = make_float4(ea[0], ea[1], ea[2], ea[3]);
        *(float4*)(r + 4) = make_float4(ea[4], ea[5],
                                        __int_as_float(src), __int_as_float(dst));
    }
}

// ---------------- dual phase helper: Pab = [hT@W1a + b1 | hT@W1b] --------------
// sH: 64 k x 64 rows (k-major, stride 68). sW: scratch >= 32*136 floats.
__device__ __forceinline__ void dual_phase(const float* __restrict__ sH,
                                           float* __restrict__ sW,
                                           const float* __restrict__ W1n,
                                           const float* __restrict__ b1n,
                                           float* __restrict__ Pab,
                                           int brow, int M, int tid)
{
    const int cg = tid & 15, rg = tid >> 4;
    const int c0 = cg * 4,   r0 = rg * 4;

    float a3[4][4], b3[4][4];
#pragma unroll
    for (int i = 0; i < 4; i++)
#pragma unroll
        for (int j = 0; j < 4; j++) {
            a3[i][j] = b1n[c0 + j];
            b3[i][j] = 0.0f;
        }

#pragma unroll
    for (int kc = 0; kc < 64; kc += 32) {
        // stage W1n chunk: 32 k-rows x 128 cols at stride 136
#pragma unroll
        for (int s = 0; s < 4; s++) {
            const int f = tid * 4 + s;
            const int kk = f >> 5;
            const int w4 = (f & 31) * 4;
            const float* src = (w4 < 64)
                ? (W1n + (long long)(kc + kk) * 64 + w4)
                : (W1n + (long long)(64 + kc + kk) * 64 + (w4 - 64));
            *(float4*)&sW[kk * 136 + w4] = *(const float4*)src;
        }
        __syncthreads();
#pragma unroll
        for (int kk = 0; kk < 32; kk++) {
            float4 a  = *(const float4*)&sH[(kc + kk) * 68 + r0];
            float4 w0 = *(const float4*)&sW[kk * 136 + c0];
            float4 w1 = *(const float4*)&sW[kk * 136 + c0 + 64];
            float ar[4] = {a.x, a.y, a.z, a.w};
            float wa[4] = {w0.x, w0.y, w0.z, w0.w};
            float wb[4] = {w1.x, w1.y, w1.z, w1.w};
#pragma unroll
            for (int i = 0; i < 4; i++)
#pragma unroll
                for (int j = 0; j < 4; j++) {
                    a3[i][j] = fmaf(ar[i], wa[j], a3[i][j]);
                    b3[i][j] = fmaf(ar[i], wb[j], b3[i][j]);
                }
        }
        __syncthreads();
    }

#pragma unroll
    for (int i = 0; i < 4; i++) {
        const int row = brow + r0 + i;
        if (row < M) {
            *(float4*)(Pab + (long long)row * 128 + c0) =
                make_float4(a3[i][0], a3[i][1], a3[i][2], a3[i][3]);
            *(float4*)(Pab + (long long)row * 128 + c0 + 64) =
                make_float4(b3[i][0], b3[i][1], b3[i][2], b3[i][3]);
        }
    }
}

// ---------------- proj_dual: h = x@Win + bin; Pab = [h@W1a+b1 | h@W1b] ---------
__global__ __launch_bounds__(256)
void proj_dual(const float* __restrict__ x, const float* __restrict__ Win,
               const float* __restrict__ bin,
               const float* __restrict__ W1n, const float* __restrict__ b1n,
               float* __restrict__ h, float* __restrict__ Pab, int M)
{
    __shared__ __align__(16) float sA[32 * 64];
    __shared__ __align__(16) float sW[32 * 136];
    __shared__ __align__(16) float sH[64 * 68];

    const int tid  = threadIdx.x;
    const int brow = blockIdx.x * 64;
    const int cg = tid & 15, rg = tid >> 4;
    const int c0 = cg * 4,   r0 = rg * 4;

    const int lrow = tid >> 2;
    const int lcol = (tid & 3) * 4;
    const int grow = brow + lrow;
    const int kr = tid >> 4;
    const int wc = (tid & 15) * 4;

    float acc[4][4];
#pragma unroll
    for (int i = 0; i < 4; i++)
#pragma unroll
        for (int j = 0; j < 4; j++)
            acc[i][j] = bin[c0 + j];

    for (int kc = 0; kc < 128; kc += 32) {
#pragma unroll
        for (int q = 0; q < 2; q++) {
            const int col = lcol + 16 * q;
            float4 av = make_float4(0.f, 0.f, 0.f, 0.f);
            if (grow < M)
                av = *(const float4*)(x + (long long)grow * 128 + kc + col);
            sA[(col + 0) * 64 + lrow] = av.x;
            sA[(col + 1) * 64 + lrow] = av.y;
            sA[(col + 2) * 64 + lrow] = av.z;
            sA[(col + 3) * 64 + lrow] = av.w;
            *(float4*)&sW[(kr + 16 * q) * 64 + wc] =
                *(const float4*)(Win + (long long)(kc + kr + 16 * q) * 64 + wc);
        }
        __syncthreads();
#pragma unroll
        for (int kk = 0; kk < 32; kk++) {
            float4 a = *(const float4*)&sA[kk * 64 + r0];
            float4 w = *(const float4*)&sW[kk * 64 + c0];
            float ar[4] = {a.x, a.y, a.z, a.w};
            float wr[4] = {w.x, w.y, w.z, w.w};
#pragma unroll
            for (int i = 0; i < 4; i++)
#pragma unroll
                for (int j = 0; j < 4; j++)
                    acc[i][j] = fmaf(ar[i], wr[j], acc[i][j]);
        }
        __syncthreads();
    }

    // write h (gmem) and stage into sH (k-major)
#pragma unroll
    for (int i = 0; i < 4; i++) {
        const int row = brow + r0 + i;
        const bool v = row < M;
        if (v)
            *(float4*)(h + (long long)row * 64 + c0) =
                make_float4(acc[i][0], acc[i][1], acc[i][2], acc[i][3]);
#pragma unroll
        for (int j = 0; j < 4; j++)
            sH[(c0 + j) * 68 + r0 + i] = v ? acc[i][j] : 0.0f;
    }
    __syncthreads();

    dual_phase(sH, sW, W1n, b1n, Pab, brow, M, tid);
}

// ---------------- update_dual: h += relu(relu([h|agg]U1+b1)U2+b2); Pab = dual --
// Zeroes agg after reading (restores launch-entry invariant).
template <bool DO_DUAL>
__global__ __launch_bounds__(256)
void update_dual(const float* __restrict__ h_in, const float* __restrict__ U1,
                 const float* __restrict__ b1, const float* __restrict__ U2,
                 const float* __restrict__ b2, float* agg,
                 float* __restrict__ h_out,
                 const float* __restrict__ W1n, const float* __restrict__ b1n,
                 float* __restrict__ Pab, int M)
{
    __shared__ __align__(16) float sA [32 * 64];
    __shared__ __align__(16) float sW [32 * 136];
    __shared__ __align__(16) float sU1[64 * 68];   // phase2 input; reused as sH

    const int tid  = threadIdx.x;
    const int brow = blockIdx.x * 64;
    const int cg = tid & 15, rg = tid >> 4;
    const int c0 = cg * 4,   r0 = rg * 4;

    const int lrow = tid >> 2;
    const int lcol = (tid & 3) * 4;
    const int grow = brow + lrow;
    const int kr = tid >> 4;
    const int wc = (tid & 15) * 4;

    float acc[4][4];
#pragma unroll
    for (int i = 0; i < 4; i++)
#pragma unroll
        for (int j = 0; j < 4; j++)
            acc[i][j] = b1[c0 + j];

#pragma unroll
    for (int p = 0; p < 2; p++) {
        const float* A = p ? agg : h_in;
        const float* W = U1 + (long long)p * 64 * 64;
        for (int kc = 0; kc < 64; kc += 32) {
#pragma unroll
            for (int q = 0; q < 2; q++) {
                const int col = lcol + 16 * q;
                float4 av = make_float4(0.f, 0.f, 0.f, 0.f);
                if (grow < M) {
                    av = *(const float4*)(A + (long long)grow * 64 + kc + col);
                    if (p == 1)
                        *(float4*)(agg + (long long)grow * 64 + kc + col) =
                            make_float4(0.f, 0.f, 0.f, 0.f);
                }
                sA[(col + 0) * 64 + lrow] = av.x;
                sA[(col + 1) * 64 + lrow] = av.y;
                sA[(col + 2) * 64 + lrow] = av.z;
                sA[(col + 3) * 64 + lrow] = av.w;
                *(float4*)&sW[(kr + 16 * q) * 64 + wc] =
                    *(const float4*)(W + (long long)(kc + kr + 16 * q) * 64 + wc);
            }
            __syncthreads();
#pragma unroll
            for (int kk = 0; kk < 32; kk++) {
                float4 a = *(const float4*)&sA[kk * 64 + r0];
                float4 w = *(const float4*)&sW[kk * 64 + c0];
                float ar[4] = {a.x, a.y, a.z, a.w};
                float wr[4] = {w.x, w.y, w.z, w.w};
#pragma unroll
                for (int i = 0; i < 4; i++)
#pragma unroll
                    for (int j = 0; j < 4; j++)
                        acc[i][j] = fmaf(ar[i], wr[j], acc[i][j]);
            }
            __syncthreads();
        }
    }

    // u1 = relu(acc) -> smem, k-major
#pragma unroll
    for (int i = 0; i < 4; i++)
#pragma unroll
        for (int j = 0; j < 4; j++)
            sU1[(c0 + j) * 68 + r0 + i] = fmaxf(acc[i][j], 0.0f);
    __syncthreads();

    // phase 2: acc2 = u1 @ U2 + b2
    float acc2[4][4];
#pragma unroll
    for (int i = 0; i < 4; i++)
#pragma unroll
        for (int j = 0; j < 4; j++)
            acc2[i][j] = b2[c0 + j];

    for (int kc = 0; kc < 64; kc += 32) {
#pragma unroll
        for (int q = 0; q < 2; q++)
            *(float4*)&sW[(kr + 16 * q) * 64 + wc] =
                *(const float4*)(U2 + (long long)(kc + kr + 16 * q) * 64 + wc);
        __syncthreads();
#pragma unroll
        for (int kk = 0; kk < 32; kk++) {
            float4 a = *(const float4*)&sU1[(kc + kk) * 68 + r0];
            float4 w = *(const float4*)&sW[kk * 64 + c0];
            float ar[4] = {a.x, a.y, a.z, a.w};
            float wr[4] = {w.x, w.y, w.z, w.w};
#pragma unroll
            for (int i = 0; i < 4; i++)
#pragma unroll
                for (int j = 0; j < 4; j++)
                    acc2[i][j] = fmaf(ar[i], wr[j], acc2[i][j]);
        }
        __syncthreads();
    }

    // epilogue: h_new = h_old + relu(acc2); write h_out (+ stage into sU1 as sH)
#pragma unroll
    for (int i = 0; i < 4; i++) {
        const int row = brow + r0 + i;
        const bool v = row < M;
        float hn[4] = {0.f, 0.f, 0.f, 0.f};
        if (v) {
            float4 hh = *(const float4*)(h_out + (long long)row * 64 + c0);
            hn[0] = hh.x + fmaxf(acc2[i][0], 0.f);
            hn[1] = hh.y + fmaxf(acc2[i][1], 0.f);
            hn[2] = hh.z + fmaxf(acc2[i][2], 0.f);
            hn[3] = hh.w + fmaxf(acc2[i][3], 0.f);
            *(float4*)(h_out + (long long)row * 64 + c0) =
                make_float4(hn[0], hn[1], hn[2], hn[3]);
        }
        if (DO_DUAL) {
#pragma unroll
            for (int j = 0; j < 4; j++)
                sU1[(c0 + j) * 68 + r0 + i] = hn[j];
        }
    }

    if (DO_DUAL) {
        __syncthreads();
        dual_phase(sU1, sW, W1n, b1n, Pab, brow, M, tid);
    }
}

// ---------------- edge kernel: fragment-layout segmented scan ------------------
#define A_STRIDE 68
#define W_STRIDE 72
__global__ __launch_bounds__(256, 3)
void edge_kernel_mma(const float* __restrict__ Pab,
                     const float* __restrict__ W1c,   // 6 x 64
                     const float* __restrict__ W2,    // 64 x 64 (k x n)
                     const float* __restrict__ b2,    // 64
                     float* __restrict__ agg, int E)
{
    extern __shared__ __align__(16) char smem[];
    uint32_t* sA   = (uint32_t*)smem;                       // 8 warps x 16 x 68
    uint32_t* sW2  = (uint32_t*)(smem + 34816);             // 64 x 72 (tf32)
    float*    sW1c = (float*)(smem + 53248);                // 6 x 64
    float*    sB2  = (float*)(smem + 54784);                // 64

    const int tid = threadIdx.x;
    const int w   = tid >> 5;
    const int l   = tid & 31;

    for (int i = tid; i < 64 * 64; i += 256) {
        int k = i >> 6, n = i & 63;
        sW2[k * W_STRIDE + n] = f32_to_tf32(W2[i]);
    }
    for (int i = tid; i < 384; i += 256) sW1c[i] = W1c[i];
    if (tid < 64) sB2[tid] = b2[tid];
    __syncthreads();

    uint32_t* myA = sA + w * 16 * A_STRIDE;
    const int gw = blockIdx.x * 8 + w;
    const int nW = gridDim.x * 8;
    const int nChunks = (E + 15) >> 4;

    const int lg  = l >> 2;       // 0..7 (mma row group)
    const int lt  = l & 3;        // 0..3
    const int er  = l >> 3;       // 0..3 (phase A: edge-in-quad)
    const int c4  = (l & 7) * 4;  // phase A col base
    const int eL  = l & 15;       // edge within chunk

    // prefetch first record (each lane: its eL edge)
    float4 p0 = make_float4(0.f, 0.f, 0.f, 0.f);
    float4 p1 = make_float4(0.f, 0.f, 0.f, __int_as_float(-1));
    if (gw < nChunks) {
        long long eg = ((long long)gw << 4) + eL;
        if (eg < E) {
            const float* r = g_rec + eg * 8;
            p0 = *(const float4*)(r);
            p1 = *(const float4*)(r + 4);
        }
    }

    for (int ch = gw; ch < nChunks; ch += nW) {
        const long long e0 = (long long)ch << 4;

        const float ea0 = p0.x, ea1 = p0.y, ea2 = p0.z, ea3 = p0.w;
        const float ea4 = p1.x, ea5 = p1.y;
        const int src = __float_as_int(p1.z);
        const int dst = __float_as_int(p1.w);

        // prefetch next chunk's record
        {
            const int chn = ch + nW;
            p0 = make_float4(0.f, 0.f, 0.f, 0.f);
            p1 = make_float4(0.f, 0.f, 0.f, __int_as_float(-1));
            if (chn < nChunks) {
                long long eg = ((long long)chn << 4) + eL;
                if (eg < E) {
                    const float* r = g_rec + eg * 8;
                    p0 = *(const float4*)(r);
                    p1 = *(const float4*)(r + 4);
                }
            }
        }

        // ---- phase A: m1, coalesced (4 consecutive edges x 8 lanes per pass) ----
#pragma unroll
        for (int it = 0; it < 4; it++) {
            const int e = 4 * it + er;
            const int de = __shfl_sync(0xffffffffu, dst, e);
            const int se = __shfl_sync(0xffffffffu, src, e);
            float eq[6];
            eq[0] = __shfl_sync(0xffffffffu, ea0, e);
            eq[1] = __shfl_sync(0xffffffffu, ea1, e);
            eq[2] = __shfl_sync(0xffffffffu, ea2, e);
            eq[3] = __shfl_sync(0xffffffffu, ea3, e);
            eq[4] = __shfl_sync(0xffffffffu, ea4, e);
            eq[5] = __shfl_sync(0xffffffffu, ea5, e);
            const bool ev = (e0 + e) < E;
            const float* par = Pab + (long long)de * 128;
            const float* pbr = Pab + (long long)se * 128 + 64;
#pragma unroll
            for (int h = 0; h < 2; h++) {
                const int c = c4 + 32 * h;
                float v0 = 0.f, v1 = 0.f, v2 = 0.f, v3 = 0.f;
                if (ev) {
                    float4 a = *(const float4*)(par + c);
                    float4 b = *(const float4*)(pbr + c);
                    v0 = a.x + b.x; v1 = a.y + b.y; v2 = a.z + b.z; v3 = a.w + b.w;
#pragma unroll
                    for (int q = 0; q < 6; q++) {
                        float4 wv = *(const float4*)(sW1c + q * 64 + c);
                        v0 = fmaf(eq[q], wv.x, v0);
                        v1 = fmaf(eq[q], wv.y, v1);
                        v2 = fmaf(eq[q], wv.z, v2);
                        v3 = fmaf(eq[q], wv.w, v3);
                    }
                }
                uint32_t r0 = f32_to_tf32(fmaxf(v0, 0.f));
                uint32_t r1 = f32_to_tf32(fmaxf(v1, 0.f));
                uint32_t r2 = f32_to_tf32(fmaxf(v2, 0.f));
                uint32_t r3 = f32_to_tf32(fmaxf(v3, 0.f));
                *(uint4*)(myA + e * A_STRIDE + c) = make_uint4(r0, r1, r2, r3);
            }
        }
        __syncwarp();

        // ---- mma: D(16x64) = m1 @ W2 ----
        float acc[8][4];
#pragma unroll
        for (int j = 0; j < 8; j++)
#pragma unroll
            for (int q = 0; q < 4; q++) acc[j][q] = 0.0f;

#pragma unroll
        for (int s = 0; s < 8; s++) {
            const int k0 = 8 * s;
            uint32_t af[4];
            const uint32_t* base = myA + lg * A_STRIDE + k0 + lt;
            af[0] = base[0];
            af[1] = base[8 * A_STRIDE];
            af[2] = base[4];
            af[3] = base[8 * A_STRIDE + 4];
#pragma unroll
            for (int j = 0; j < 8; j++) {
                uint32_t bf[2];
                bf[0] = sW2[(k0 + lt)     * W_STRIDE + 8 * j + lg];
                bf[1] = sW2[(k0 + lt + 4) * W_STRIDE + 8 * j + lg];
                mma_tf32(acc[j], af, bf);
            }
        }
        __syncwarp();   // all lanes done reading myA before next phase A

        // ---- segmented reduction in fragment layout ----
        // lane(lg,lt) holds rows lg and lg+8, cols 8j+2lt{,+1}
        {
            const bool v0r = (e0 + lg) < E;
            const bool v1r = (e0 + lg + 8) < E;
            const int d0 = __shfl_sync(0xffffffffu, dst, lg);
            const int d1 = __shfl_sync(0xffffffffu, dst, lg + 8);

            const int dprev = __shfl_up_sync(0xffffffffu, dst, 1);
            const bool head = (eL == 0) || (dprev != dst);
            const unsigned hm = __ballot_sync(0xffffffffu, head) & 0xFFFFu;

            const int hs0 = 31 - __clz(hm & ((2u << lg) - 1u));
            const int hs1 = 31 - __clz(hm & ((2u << (lg + 8)) - 1u));
            const int dist0 = lg - hs0;
            const int dist1 = (lg + 8) - hs1;
            const int dd1 = dist1 < lg ? dist1 : lg;
            const bool cross = dist1 >= lg + 1;
            const bool tail0 = ((hm >> (lg + 1)) & 1u) != 0;
            const bool tail1 = (lg == 7) || (((hm >> (lg + 9)) & 1u) != 0);

            // bias + relu (+zero invalid rows); bias via broadcast LDS
#pragma unroll
            for (int j = 0; j < 8; j++) {
                float2 bb = *(const float2*)(sB2 + 8 * j + 2 * lt);
                acc[j][0] = v0r ? fmaxf(acc[j][0] + bb.x, 0.f) : 0.f;
                acc[j][1] = v0r ? fmaxf(acc[j][1] + bb.y, 0.f) : 0.f;
                acc[j][2] = v1r ? fmaxf(acc[j][2] + bb.x, 0.f) : 0.f;
                acc[j][3] = v1r ? fmaxf(acc[j][3] + bb.y, 0.f) : 0.f;
            }

            // 3-step segmented inclusive scan within each 8-row half (stride-4 lanes)
#pragma unroll
            for (int s = 1; s < 8; s <<= 1) {
#pragma unroll
                for (int j = 0; j < 8; j++) {
                    float y0 = __shfl_up_sync(0xffffffffu, acc[j][0], 4 * s);
                    float y1 = __shfl_up_sync(0xffffffffu, acc[j][1], 4 * s);
                    float y2 = __shfl_up_sync(0xffffffffu, acc[j][2], 4 * s);
                    float y3 = __shfl_up_sync(0xffffffffu, acc[j][3], 4 * s);
                    if (dist0 >= s) { acc[j][0] += y0; acc[j][1] += y1; }
                    if (dd1   >= s) { acc[j][2] += y2; acc[j][3] += y3; }
                }
            }
            // cross-half: rows 8..15 whose segment extends past row 8 add row 7's sums
#pragma unroll
            for (int j = 0; j < 8; j++) {
                float y0 = __shfl_sync(0xffffffffu, acc[j][0], 28 + lt);
                float y1 = __shfl_sync(0xffffffffu, acc[j][1], 28 + lt);
                if (cross) { acc[j][2] += y0; acc[j][3] += y1; }
            }

            // emit tails
            if (tail0 && v0r) {
                float* p = agg + (long long)d0 * 64 + 2 * lt;
#pragma unroll
                for (int j = 0; j < 8; j++)
                    asm volatile("red.global.add.v2.f32 [%0], {%1, %2};"
                                 :: "l"(p + 8 * j), "f"(acc[j][0]), "f"(acc[j][1])
                                 : "memory");
            }
            if (tail1 && v1r) {
                float* p = agg + (long long)d1 * 64 + 2 * lt;
#pragma unroll
                for (int j = 0; j < 8; j++)
                    asm volatile("red.global.add.v2.f32 [%0], {%1, %2};"
                                 :: "l"(p + 8 * j), "f"(acc[j][2]), "f"(acc[j][3])
                                 : "memory");
            }
        }
    }
}

// ---------------- prediction head ---------------------------------------------
__global__ __launch_bounds__(256)
void pred_kernel(const float* __restrict__ h, const float* __restrict__ pw,
                 const float* __restrict__ pb, float* __restrict__ out, int M)
{
    __shared__ float spw[64];
    __shared__ float swarp[8];
    if (threadIdx.x < 64) spw[threadIdx.x] = pw[threadIdx.x];
    __syncthreads();

    float sum = 0.0f;
    for (long long row = (long long)blockIdx.x * blockDim.x + threadIdx.x; row < M;
         row += (long long)gridDim.x * blockDim.x) {
        const float4* hr = (const float4*)(h + row * 64);
#pragma unroll
        for (int u = 0; u < 16; u++) {
            float4 v = hr[u];
            sum = fmaf(v.x, spw[4 * u + 0], sum);
            sum = fmaf(v.y, spw[4 * u + 1], sum);
            sum = fmaf(v.z, spw[4 * u + 2], sum);
            sum = fmaf(v.w, spw[4 * u + 3], sum);
        }
    }
#pragma unroll
    for (int o = 16; o > 0; o >>= 1) sum += __shfl_down_sync(0xffffffffu, sum, o);
    if ((threadIdx.x & 31) == 0) swarp[threadIdx.x >> 5] = sum;
    __syncthreads();
    if (threadIdx.x < 8) {
        float s = swarp[threadIdx.x];
#pragma unroll
        for (int o = 4; o > 0; o >>= 1) s += __shfl_down_sync(0xffu, s, o);
        if (threadIdx.x == 0) {
            if (blockIdx.x == 0) s = fmaf(pb[0], (float)M, s);
            atomicAdd(out, s);
        }
    }
}

// ---------------- launch ------------------------------------------------------
extern "C" void kernel_launch(void* const* d_in, const int* in_sizes, int n_in,
                              void* d_out, int out_size)
{
    const float* x       = (const float*)d_in[0];
    const void*  ei      = d_in[1];
    const float* eattr   = (const float*)d_in[2];
    const float* lin_w   = (const float*)d_in[3];
    const float* lin_b   = (const float*)d_in[4];
    const float* msg_w1  = (const float*)d_in[5];
    const float* msg_b1  = (const float*)d_in[6];
    const float* msg_w2  = (const float*)d_in[7];
    const float* msg_b2  = (const float*)d_in[8];
    const float* upd_w1  = (const float*)d_in[9];
    const float* upd_b1  = (const float*)d_in[10];
    const float* upd_w2  = (const float*)d_in[11];
    const float* upd_b2  = (const float*)d_in[12];
    const float* pred_w  = (const float*)d_in[13];
    const float* pred_b  = (const float*)d_in[14];

    const int M = in_sizes[0] / 128;   // 50000
    const int E = in_sizes[2] / 6;     // 800000

    float *h, *Pab, *agg;
    int* cnt;
    cudaGetSymbolAddress((void**)&h,   g_h);
    cudaGetSymbolAddress((void**)&Pab, g_Pab);
    cudaGetSymbolAddress((void**)&agg, g_agg);
    cudaGetSymbolAddress((void**)&cnt, g_cnt);

    const int gN = (M + 63) / 64;      // 782
    const int SM_EDGE = 55040;
    cudaFuncSetAttribute(edge_kernel_mma,
                         cudaFuncAttributeMaxDynamicSharedMemorySize, SM_EDGE);
    const int nChunks = (E + 15) / 16;
    int gEdge = 148 * 3;
    if (gEdge * 8 > nChunks) gEdge = (nChunks + 7) / 8;
    if (gEdge < 1) gEdge = 1;

    // ---- sort edges by dst (once; reused by all 4 layers) ----
    detect_idx_kernel<<<1, 32>>>((const unsigned int*)ei);
    cudaMemsetAsync(cnt, 0, NSCAN * sizeof(int));
    hist_kernel<<<1024, 256>>>(ei, E);
    scan1_kernel<<<NSCAN / 1024, 1024>>>();
    scan2_kernel<<<1, 64>>>(NSCAN / 1024);
    scan3_kernel<<<NSCAN / 1024, 1024>>>();
    scatter_kernel<<<1024, 256>>>(ei, eattr, E);

    // input projection fused with layer-0 dual
    proj_dual<<<gN, 256>>>(x, lin_w, lin_b,
                           msg_w1, msg_b1, h, Pab, M);

    for (int l = 0; l < 4; l++) {
        const float* W1 = msg_w1 + (size_t)l * 134 * 64;
        edge_kernel_mma<<<gEdge, 256, SM_EDGE>>>(Pab,
                                                 W1 + 128 * 64,
                                                 msg_w2 + (size_t)l * 64 * 64,
                                                 msg_b2 + l * 64, agg, E);
        if (l < 3) {
            const float* W1n = msg_w1 + (size_t)(l + 1) * 134 * 64;
            update_dual<true><<<gN, 256>>>(h, upd_w1 + (size_t)l * 128 * 64,
                                           upd_b1 + l * 64,
                                           upd_w2 + (size_t)l * 64 * 64,
                                           upd_b2 + l * 64, agg, h,
                                           W1n, msg_b1 + (l + 1) * 64, Pab, M);
        } else {
            update_dual<false><<<gN, 256>>>(h, upd_w1 + (size_t)l * 128 * 64,
                                            upd_b1 + l * 64,
                                            upd_w2 + (size_t)l * 64 * 64,
                                            upd_b2 + l * 64, agg, h,
                                            nullptr, nullptr, nullptr, M);
        }
    }

    cudaMemsetAsync(d_out, 0, sizeof(float));
    pred_kernel<<<256, 256>>>(h, pred_w, pred_b, (float*)d_out, M);
}

// round 14
// speedup vs baseline: 1.2606x; 1.0610x over previous
#include <cuda_runtime.h>
#include <cstdint>

#define EMB 64
#define NN_MAX 50000
#define NSCAN 50176          // 49 * 1024
#define NE_MAX 800000
#define NE_PAD (NE_MAX + 64)

// ---------------- scratch (static device memory; no allocations) ----------------
__device__ __align__(128) float g_h  [NN_MAX * EMB];
__device__ __align__(128) float g_Pab[NN_MAX * 128];   // [Pa | Pb] per node
__device__ __align__(128) float g_agg[NN_MAX * EMB];   // zero at launch entry (invariant)
__device__ int g_is64;

// sort scratch
__device__ int   g_cnt [NSCAN];
__device__ int   g_inc [NSCAN];
__device__ int   g_cur [NSCAN];
__device__ int   g_bsum[64];
// packed sorted edge records: {ea0..ea5, src(bits), dst(bits)} per edge (32B)
__device__ __align__(128) float g_rec[NE_PAD * 8];

// ---------------- helpers ------------------------------------------------------
__device__ __forceinline__ uint32_t f32_to_tf32(float f) {
    uint32_t u;
    asm("cvt.rna.tf32.f32 %0, %1;" : "=r"(u) : "f"(f));
    return u;
}
__device__ __forceinline__ void mma_tf32(float* c, const uint32_t* a, const uint32_t* b) {
    asm volatile(
        "mma.sync.aligned.m16n8k8.row.col.f32.tf32.tf32.f32 "
        "{%0,%1,%2,%3}, {%4,%5,%6,%7}, {%8,%9}, {%0,%1,%2,%3};"
        : "+f"(c[0]), "+f"(c[1]), "+f"(c[2]), "+f"(c[3])
        : "r"(a[0]), "r"(a[1]), "r"(a[2]), "r"(a[3]), "r"(b[0]), "r"(b[1]));
}

// ---------------- detect whether edge_index is int64 or int32 ----------------
__global__ void detect_idx_kernel(const unsigned int* __restrict__ p)
{
    if (threadIdx.x == 0 && blockIdx.x == 0) {
        unsigned int v = 0;
#pragma unroll
        for (int k = 0; k < 64; k++) v |= p[2 * k + 1];
        g_is64 = (v == 0) ? 1 : 0;
    }
}

// ---------------- counting sort by dst ----------------------------------------
__global__ void hist_kernel(const void* __restrict__ ei, int E)
{
    const int is64 = g_is64;
    for (long long e = (long long)blockIdx.x * blockDim.x + threadIdx.x; e < E;
         e += (long long)gridDim.x * blockDim.x) {
        int dst = is64 ? (int)((const long long*)ei)[(long long)E + e]
                       : ((const int*)ei)[(long long)E + e];
        atomicAdd(&g_cnt[dst], 1);
    }
}

__global__ __launch_bounds__(1024) void scan1_kernel()
{
    const int t = threadIdx.x, b = blockIdx.x;
    const int i = b * 1024 + t;
    const int lane = t & 31, wid = t >> 5;
    int x = g_cnt[i];
#pragma unroll
    for (int s = 1; s < 32; s <<= 1) {
        int u = __shfl_up_sync(0xffffffffu, x, s);
        if (lane >= s) x += u;
    }
    __shared__ int ws[32];
    if (lane == 31) ws[wid] = x;
    __syncthreads();
    if (wid == 0) {
        int y = ws[lane];
#pragma unroll
        for (int s = 1; s < 32; s <<= 1) {
            int u = __shfl_up_sync(0xffffffffu, y, s);
            if (lane >= s) y += u;
        }
        ws[lane] = y;
    }
    __syncthreads();
    int inc = x + (wid ? ws[wid - 1] : 0);
    g_inc[i] = inc;
    if (t == 1023) g_bsum[b] = inc;
}

// parallel exclusive scan of block sums (nb <= 64)
__global__ __launch_bounds__(64) void scan2_kernel(int nb)
{
    __shared__ int s[64];
    const int t = threadIdx.x;
    const int v = (t < nb) ? g_bsum[t] : 0;
    s[t] = v;
    __syncthreads();
#pragma unroll
    for (int o = 1; o < 64; o <<= 1) {
        int x = (t >= o) ? s[t - o] : 0;
        __syncthreads();
        s[t] += x;
        __syncthreads();
    }
    if (t < nb) g_bsum[t] = s[t] - v;
}

__global__ __launch_bounds__(1024) void scan3_kernel()
{
    const int i = blockIdx.x * 1024 + threadIdx.x;
    g_cur[i] = g_inc[i] - g_cnt[i] + g_bsum[blockIdx.x];
}

__global__ void scatter_kernel(const void* __restrict__ ei,
                               const float* __restrict__ eattr, int E)
{
    const int is64 = g_is64;
    for (long long e = (long long)blockIdx.x * blockDim.x + threadIdx.x; e < E;
         e += (long long)gridDim.x * blockDim.x) {
        int src, dst;
        if (is64) {
            src = (int)((const long long*)ei)[e];
            dst = (int)((const long long*)ei)[(long long)E + e];
        } else {
            src = ((const int*)ei)[e];
            dst = ((const int*)ei)[(long long)E + e];
        }
        float ea[6];
#pragma unroll
        for (int q = 0; q < 6; q++) ea[q] = eattr[e * 6 + q];
        int pos = atomicAdd(&g_cur[dst], 1);
        float* r = g_rec + (long long)pos * 8;
        *(float4*)(r)     = make_float4(ea[0], ea[1], ea[2], ea[3]);
        *(float4*)(r + 4) = make_float4(ea[4], ea[5],
                                        __int_as_float(src), __int_as_float(dst));
    }
}

// ---------------- dual phase (tf32 mma): Pab = [hT@W1a + b1 | hT@W1b] ----------
// sHT: 64 rows x stride 68 (tf32 bits, row-major). sWn: uint32 scratch 32x136.
// 8 warps: (rowg = w&3) x (half = w>>2). Output 64 rows x 128 cols.
__device__ __forceinline__ void dual_phase_mma(const uint32_t* __restrict__ sHT,
                                               uint32_t* __restrict__ sWn,
                                               const float* __restrict__ W1n,
                                               const float* __restrict__ b1n,
                                               float* __restrict__ sB1,
                                               float* __restrict__ Pab,
                                               int brow, int M, int tid)
{
    const int w = tid >> 5, l = tid & 31;
    const int lg = l >> 2, lt = l & 3;
    const int rowg = w & 3, half = w >> 2;

    if (tid < 64) sB1[tid] = b1n[tid];

    float acc[8][4];
#pragma unroll
    for (int j = 0; j < 8; j++)
#pragma unroll
        for (int q = 0; q < 4; q++) acc[j][q] = 0.0f;

#pragma unroll
    for (int stage = 0; stage < 2; stage++) {
        const int kc = stage * 32;
        __syncthreads();   // sHT ready (first) / prev-stage reads done
        // stage 32 k-rows x 128 cols of W1n (tf32) at stride 136
#pragma unroll
        for (int s4 = 0; s4 < 4; s4++) {
            const int f = tid * 4 + s4;
            const int kk = f >> 5;
            const int c4 = (f & 31) * 4;
            const float* src = (c4 < 64)
                ? (W1n + (long long)(kc + kk) * 64 + c4)
                : (W1n + (long long)(64 + kc + kk) * 64 + (c4 - 64));
            float4 v = *(const float4*)src;
            uint4 t;
            t.x = f32_to_tf32(v.x); t.y = f32_to_tf32(v.y);
            t.z = f32_to_tf32(v.z); t.w = f32_to_tf32(v.w);
            *(uint4*)&sWn[kk * 136 + c4] = t;
        }
        __syncthreads();
#pragma unroll
        for (int s = 0; s < 4; s++) {
            const int k0 = 8 * s;
            uint32_t af[4];
            const uint32_t* base = sHT + (16 * rowg + lg) * 68 + kc + k0 + lt;
            af[0] = base[0];
            af[1] = base[8 * 68];
            af[2] = base[4];
            af[3] = base[8 * 68 + 4];
#pragma unroll
            for (int j = 0; j < 8; j++) {
                uint32_t bf[2];
                bf[0] = sWn[(k0 + lt)     * 136 + 8 * j + lg + 64 * half];
                bf[1] = sWn[(k0 + lt + 4) * 136 + 8 * j + lg + 64 * half];
                mma_tf32(acc[j], af, bf);
            }
        }
    }

    // bias (half 0 only) + write fragments to Pab
    const bool dob = (half == 0);
#pragma unroll
    for (int j = 0; j < 8; j++) {
        const int col = 64 * half + 8 * j + 2 * lt;
        float b0 = 0.f, b1v = 0.f;
        if (dob) {
            float2 bb = *(const float2*)(sB1 + 8 * j + 2 * lt);
            b0 = bb.x; b1v = bb.y;
        }
        const int r0 = brow + 16 * rowg + lg;
        const int r1 = r0 + 8;
        if (r0 < M)
            *(float2*)(Pab + (long long)r0 * 128 + col) =
                make_float2(acc[j][0] + b0, acc[j][1] + b1v);
        if (r1 < M)
            *(float2*)(Pab + (long long)r1 * 128 + col) =
                make_float2(acc[j][2] + b0, acc[j][3] + b1v);
    }
}

// ---------------- proj_dual: h = x@Win + bin; Pab = dual(h) --------------------
__global__ __launch_bounds__(256)
void proj_dual(const float* __restrict__ x, const float* __restrict__ Win,
               const float* __restrict__ bin,
               const float* __restrict__ W1n, const float* __restrict__ b1n,
               float* __restrict__ h, float* __restrict__ Pab, int M)
{
    __shared__ __align__(16) float    sA[32 * 64];
    __shared__ __align__(16) float    sW[32 * 136];
    __shared__ __align__(16) uint32_t sHT[64 * 68];
    __shared__ float sB1[64];

    const int tid  = threadIdx.x;
    const int brow = blockIdx.x * 64;
    const int cg = tid & 15, rg = tid >> 4;
    const int c0 = cg * 4,   r0 = rg * 4;

    const int lrow = tid >> 2;
    const int lcol = (tid & 3) * 4;
    const int grow = brow + lrow;
    const int kr = tid >> 4;
    const int wc = (tid & 15) * 4;

    float acc[4][4];
#pragma unroll
    for (int i = 0; i < 4; i++)
#pragma unroll
        for (int j = 0; j < 4; j++)
            acc[i][j] = bin[c0 + j];

    for (int kc = 0; kc < 128; kc += 32) {
#pragma unroll
        for (int q = 0; q < 2; q++) {
            const int col = lcol + 16 * q;
            float4 av = make_float4(0.f, 0.f, 0.f, 0.f);
            if (grow < M)
                av = *(const float4*)(x + (long long)grow * 128 + kc + col);
            sA[(col + 0) * 64 + lrow] = av.x;
            sA[(col + 1) * 64 + lrow] = av.y;
            sA[(col + 2) * 64 + lrow] = av.z;
            sA[(col + 3) * 64 + lrow] = av.w;
            *(float4*)&sW[(kr + 16 * q) * 64 + wc] =
                *(const float4*)(Win + (long long)(kc + kr + 16 * q) * 64 + wc);
        }
        __syncthreads();
#pragma unroll
        for (int kk = 0; kk < 32; kk++) {
            float4 a = *(const float4*)&sA[kk * 64 + r0];
            float4 w = *(const float4*)&sW[kk * 64 + c0];
            float ar[4] = {a.x, a.y, a.z, a.w};
            float wr[4] = {w.x, w.y, w.z, w.w};
#pragma unroll
            for (int i = 0; i < 4; i++)
#pragma unroll
                for (int j = 0; j < 4; j++)
                    acc[i][j] = fmaf(ar[i], wr[j], acc[i][j]);
        }
        __syncthreads();
    }

    // write h (gmem fp32) + stage tf32 row-major into sHT
#pragma unroll
    for (int i = 0; i < 4; i++) {
        const int row = brow + r0 + i;
        const bool v = row < M;
        if (v)
            *(float4*)(h + (long long)row * 64 + c0) =
                make_float4(acc[i][0], acc[i][1], acc[i][2], acc[i][3]);
        uint4 t;
        t.x = f32_to_tf32(v ? acc[i][0] : 0.f);
        t.y = f32_to_tf32(v ? acc[i][1] : 0.f);
        t.z = f32_to_tf32(v ? acc[i][2] : 0.f);
        t.w = f32_to_tf32(v ? acc[i][3] : 0.f);
        *(uint4*)&sHT[(r0 + i) * 68 + c0] = t;
    }

    dual_phase_mma(sHT, (uint32_t*)sW, W1n, b1n, sB1, Pab, brow, M, tid);
}

// ---------------- update_dual: h += relu(relu([h|agg]U1+b1)U2+b2); dual --------
// Zeroes agg after reading (restores launch-entry invariant).
template <bool DO_DUAL>
__global__ __launch_bounds__(256)
void update_dual(const float* __restrict__ h_in, const float* __restrict__ U1,
                 const float* __restrict__ b1, const float* __restrict__ U2,
                 const float* __restrict__ b2, float* agg,
                 float* __restrict__ h_out,
                 const float* __restrict__ W1n, const float* __restrict__ b1n,
                 float* __restrict__ Pab, int M)
{
    __shared__ __align__(16) float sA [32 * 64];
    __shared__ __align__(16) float sW [32 * 136];
    __shared__ __align__(16) float sU1[64 * 68];   // phase2 input; reused as sHT
    __shared__ float sB1n[64];

    const int tid  = threadIdx.x;
    const int brow = blockIdx.x * 64;
    const int cg = tid & 15, rg = tid >> 4;
    const int c0 = cg * 4,   r0 = rg * 4;

    const int lrow = tid >> 2;
    const int lcol = (tid & 3) * 4;
    const int grow = brow + lrow;
    const int kr = tid >> 4;
    const int wc = (tid & 15) * 4;

    float acc[4][4];
#pragma unroll
    for (int i = 0; i < 4; i++)
#pragma unroll
        for (int j = 0; j < 4; j++)
            acc[i][j] = b1[c0 + j];

#pragma unroll
    for (int p = 0; p < 2; p++) {
        const float* A = p ? agg : h_in;
        const float* W = U1 + (long long)p * 64 * 64;
        for (int kc = 0; kc < 64; kc += 32) {
#pragma unroll
            for (int q = 0; q < 2; q++) {
                const int col = lcol + 16 * q;
                float4 av = make_float4(0.f, 0.f, 0.f, 0.f);
                if (grow < M) {
                    av = *(const float4*)(A + (long long)grow * 64 + kc + col);
                    if (p == 1)
                        *(float4*)(agg + (long long)grow * 64 + kc + col) =
                            make_float4(0.f, 0.f, 0.f, 0.f);
                }
                sA[(col + 0) * 64 + lrow] = av.x;
                sA[(col + 1) * 64 + lrow] = av.y;
                sA[(col + 2) * 64 + lrow] = av.z;
                sA[(col + 3) * 64 + lrow] = av.w;
                *(float4*)&sW[(kr + 16 * q) * 64 + wc] =
                    *(const float4*)(W + (long long)(kc + kr + 16 * q) * 64 + wc);
            }
            __syncthreads();
#pragma unroll
            for (int kk = 0; kk < 32; kk++) {
                float4 a = *(const float4*)&sA[kk * 64 + r0];
                float4 w = *(const float4*)&sW[kk * 64 + c0];
                float ar[4] = {a.x, a.y, a.z, a.w};
                float wr[4] = {w.x, w.y, w.z, w.w};
#pragma unroll
                for (int i = 0; i < 4; i++)
#pragma unroll
                    for (int j = 0; j < 4; j++)
                        acc[i][j] = fmaf(ar[i], wr[j], acc[i][j]);
            }
            __syncthreads();
        }
    }

    // u1 = relu(acc) -> smem, k-major
#pragma unroll
    for (int i = 0; i < 4; i++)
#pragma unroll
        for (int j = 0; j < 4; j++)
            sU1[(c0 + j) * 68 + r0 + i] = fmaxf(acc[i][j], 0.0f);
    __syncthreads();

    // phase 2: acc2 = u1 @ U2 + b2
    float acc2[4][4];
#pragma unroll
    for (int i = 0; i < 4; i++)
#pragma unroll
        for (int j = 0; j < 4; j++)
            acc2[i][j] = b2[c0 + j];

    for (int kc = 0; kc < 64; kc += 32) {
#pragma unroll
        for (int q = 0; q < 2; q++)
            *(float4*)&sW[(kr + 16 * q) * 64 + wc] =
                *(const float4*)(U2 + (long long)(kc + kr + 16 * q) * 64 + wc);
        __syncthreads();
#pragma unroll
        for (int kk = 0; kk < 32; kk++) {
            float4 a = *(const float4*)&sU1[(kc + kk) * 68 + r0];
            float4 w = *(const float4*)&sW[kk * 64 + c0];
            float ar[4] = {a.x, a.y, a.z, a.w};
            float wr[4] = {w.x, w.y, w.z, w.w};
#pragma unroll
            for (int i = 0; i < 4; i++)
#pragma unroll
                for (int j = 0; j < 4; j++)
                    acc2[i][j] = fmaf(ar[i], wr[j], acc2[i][j]);
        }
        __syncthreads();
    }

    // epilogue: h_new = h_old + relu(acc2); write h_out (+ stage tf32 into sU1)
    uint32_t* sHT = (uint32_t*)sU1;
#pragma unroll
    for (int i = 0; i < 4; i++) {
        const int row = brow + r0 + i;
        const bool v = row < M;
        float hn[4] = {0.f, 0.f, 0.f, 0.f};
        if (v) {
            float4 hh = *(const float4*)(h_out + (long long)row * 64 + c0);
            hn[0] = hh.x + fmaxf(acc2[i][0], 0.f);
            hn[1] = hh.y + fmaxf(acc2[i][1], 0.f);
            hn[2] = hh.z + fmaxf(acc2[i][2], 0.f);
            hn[3] = hh.w + fmaxf(acc2[i][3], 0.f);
            *(float4*)(h_out + (long long)row * 64 + c0) =
                make_float4(hn[0], hn[1], hn[2], hn[3]);
        }
        if (DO_DUAL) {
            uint4 t;
            t.x = f32_to_tf32(hn[0]); t.y = f32_to_tf32(hn[1]);
            t.z = f32_to_tf32(hn[2]); t.w = f32_to_tf32(hn[3]);
            *(uint4*)&sHT[(r0 + i) * 68 + c0] = t;
        }
    }

    if (DO_DUAL)
        dual_phase_mma(sHT, (uint32_t*)sW, W1n, b1n, sB1n, Pab, brow, M, tid);
}

// ---------------- edge kernel: fragment-layout segmented scan ------------------
#define A_STRIDE 68
#define W_STRIDE 72
__global__ __launch_bounds__(256, 3)
void edge_kernel_mma(const float* __restrict__ Pab,
                     const float* __restrict__ W1c,   // 6 x 64
                     const float* __restrict__ W2,    // 64 x 64 (k x n)
                     const float* __restrict__ b2,    // 64
                     float* __restrict__ agg, int E)
{
    extern __shared__ __align__(16) char smem[];
    uint32_t* sA   = (uint32_t*)smem;                       // 8 warps x 16 x 68
    uint32_t* sW2  = (uint32_t*)(smem + 34816);             // 64 x 72 (tf32)
    float*    sW1c = (float*)(smem + 53248);                // 6 x 64
    float*    sB2  = (float*)(smem + 54784);                // 64

    const int tid = threadIdx.x;
    const int w   = tid >> 5;
    const int l   = tid & 31;

    for (int i = tid; i < 64 * 64; i += 256) {
        int k = i >> 6, n = i & 63;
        sW2[k * W_STRIDE + n] = f32_to_tf32(W2[i]);
    }
    for (int i = tid; i < 384; i += 256) sW1c[i] = W1c[i];
    if (tid < 64) sB2[tid] = b2[tid];
    __syncthreads();

    uint32_t* myA = sA + w * 16 * A_STRIDE;
    const int gw = blockIdx.x * 8 + w;
    const int nW = gridDim.x * 8;
    const int nChunks = (E + 15) >> 4;

    const int lg  = l >> 2;       // 0..7 (mma row group)
    const int lt  = l & 3;        // 0..3
    const int er  = l >> 3;       // 0..3 (phase A: edge-in-quad)
    const int c4  = (l & 7) * 4;  // phase A col base
    const int eL  = l & 15;       // edge within chunk

    // prefetch first record (each lane: its eL edge)
    float4 p0 = make_float4(0.f, 0.f, 0.f, 0.f);
    float4 p1 = make_float4(0.f, 0.f, 0.f, __int_as_float(-1));
    if (gw < nChunks) {
        long long eg = ((long long)gw << 4) + eL;
        if (eg < E) {
            const float* r = g_rec + eg * 8;
            p0 = *(const float4*)(r);
            p1 = *(const float4*)(r + 4);
        }
    }

    for (int ch = gw; ch < nChunks; ch += nW) {
        const long long e0 = (long long)ch << 4;

        const float ea0 = p0.x, ea1 = p0.y, ea2 = p0.z, ea3 = p0.w;
        const float ea4 = p1.x, ea5 = p1.y;
        const int src = __float_as_int(p1.z);
        const int dst = __float_as_int(p1.w);

        // prefetch next chunk's record
        {
            const int chn = ch + nW;
            p0 = make_float4(0.f, 0.f, 0.f, 0.f);
            p1 = make_float4(0.f, 0.f, 0.f, __int_as_float(-1));
            if (chn < nChunks) {
                long long eg = ((long long)chn << 4) + eL;
                if (eg < E) {
                    const float* r = g_rec + eg * 8;
                    p0 = *(const float4*)(r);
                    p1 = *(const float4*)(r + 4);
                }
            }
        }

        // ---- phase A: m1, coalesced (4 consecutive edges x 8 lanes per pass) ----
#pragma unroll
        for (int it = 0; it < 4; it++) {
            const int e = 4 * it + er;
            const int de = __shfl_sync(0xffffffffu, dst, e);
            const int se = __shfl_sync(0xffffffffu, src, e);
            float eq[6];
            eq[0] = __shfl_sync(0xffffffffu, ea0, e);
            eq[1] = __shfl_sync(0xffffffffu, ea1, e);
            eq[2] = __shfl_sync(0xffffffffu, ea2, e);
            eq[3] = __shfl_sync(0xffffffffu, ea3, e);
            eq[4] = __shfl_sync(0xffffffffu, ea4, e);
            eq[5] = __shfl_sync(0xffffffffu, ea5, e);
            const bool ev = (e0 + e) < E;
            const float* par = Pab + (long long)de * 128;
            const float* pbr = Pab + (long long)se * 128 + 64;
#pragma unroll
            for (int h = 0; h < 2; h++) {
                const int c = c4 + 32 * h;
                float v0 = 0.f, v1 = 0.f, v2 = 0.f, v3 = 0.f;
                if (ev) {
                    float4 a = *(const float4*)(par + c);
                    float4 b = *(const float4*)(pbr + c);
                    v0 = a.x + b.x; v1 = a.y + b.y; v2 = a.z + b.z; v3 = a.w + b.w;
#pragma unroll
                    for (int q = 0; q < 6; q++) {
                        float4 wv = *(const float4*)(sW1c + q * 64 + c);
                        v0 = fmaf(eq[q], wv.x, v0);
                        v1 = fmaf(eq[q], wv.y, v1);
                        v2 = fmaf(eq[q], wv.z, v2);
                        v3 = fmaf(eq[q], wv.w, v3);
                    }
                }
                uint32_t r0 = f32_to_tf32(fmaxf(v0, 0.f));
                uint32_t r1 = f32_to_tf32(fmaxf(v1, 0.f));
                uint32_t r2 = f32_to_tf32(fmaxf(v2, 0.f));
                uint32_t r3 = f32_to_tf32(fmaxf(v3, 0.f));
                *(uint4*)(myA + e * A_STRIDE + c) = make_uint4(r0, r1, r2, r3);
            }
        }
        __syncwarp();

        // ---- mma: D(16x64) = m1 @ W2 ----
        float acc[8][4];
#pragma unroll
        for (int j = 0; j < 8; j++)
#pragma unroll
            for (int q = 0; q < 4; q++) acc[j][q] = 0.0f;

#pragma unroll
        for (int s = 0; s < 8; s++) {
            const int k0 = 8 * s;
            uint32_t af[4];
            const uint32_t* base = myA + lg * A_STRIDE + k0 + lt;
            af[0] = base[0];
            af[1] = base[8 * A_STRIDE];
            af[2] = base[4];
            af[3] = base[8 * A_STRIDE + 4];
#pragma unroll
            for (int j = 0; j < 8; j++) {
                uint32_t bf[2];
                bf[0] = sW2[(k0 + lt)     * W_STRIDE + 8 * j + lg];
                bf[1] = sW2[(k0 + lt + 4) * W_STRIDE + 8 * j + lg];
                mma_tf32(acc[j], af, bf);
            }
        }
        __syncwarp();   // all lanes done reading myA before next phase A

        // ---- segmented reduction in fragment layout ----
        {
            const bool v0r = (e0 + lg) < E;
            const bool v1r = (e0 + lg + 8) < E;
            const int d0 = __shfl_sync(0xffffffffu, dst, lg);
            const int d1 = __shfl_sync(0xffffffffu, dst, lg + 8);

            const int dprev = __shfl_up_sync(0xffffffffu, dst, 1);
            const bool head = (eL == 0) || (dprev != dst);
            const unsigned hm = __ballot_sync(0xffffffffu, head) & 0xFFFFu;

            const int hs0 = 31 - __clz(hm & ((2u << lg) - 1u));
            const int hs1 = 31 - __clz(hm & ((2u << (lg + 8)) - 1u));
            const int dist0 = lg - hs0;
            const int dist1 = (lg + 8) - hs1;
            const int dd1 = dist1 < lg ? dist1 : lg;
            const bool cross = dist1 >= lg + 1;
            const bool tail0 = ((hm >> (lg + 1)) & 1u) != 0;
            const bool tail1 = (lg == 7) || (((hm >> (lg + 9)) & 1u) != 0);

            // bias + relu (+zero invalid rows)
#pragma unroll
            for (int j = 0; j < 8; j++) {
                float2 bb = *(const float2*)(sB2 + 8 * j + 2 * lt);
                acc[j][0] = v0r ? fmaxf(acc[j][0] + bb.x, 0.f) : 0.f;
                acc[j][1] = v0r ? fmaxf(acc[j][1] + bb.y, 0.f) : 0.f;
                acc[j][2] = v1r ? fmaxf(acc[j][2] + bb.x, 0.f) : 0.f;
                acc[j][3] = v1r ? fmaxf(acc[j][3] + bb.y, 0.f) : 0.f;
            }

            // 3-step segmented inclusive scan within each 8-row half
#pragma unroll
            for (int s = 1; s < 8; s <<= 1) {
#pragma unroll
                for (int j = 0; j < 8; j++) {
                    float y0 = __shfl_up_sync(0xffffffffu, acc[j][0], 4 * s);
                    float y1 = __shfl_up_sync(0xffffffffu, acc[j][1], 4 * s);
                    float y2 = __shfl_up_sync(0xffffffffu, acc[j][2], 4 * s);
                    float y3 = __shfl_up_sync(0xffffffffu, acc[j][3], 4 * s);
                    if (dist0 >= s) { acc[j][0] += y0; acc[j][1] += y1; }
                    if (dd1   >= s) { acc[j][2] += y2; acc[j][3] += y3; }
                }
            }
            // cross-half combine
#pragma unroll
            for (int j = 0; j < 8; j++) {
                float y0 = __shfl_sync(0xffffffffu, acc[j][0], 28 + lt);
                float y1 = __shfl_sync(0xffffffffu, acc[j][1], 28 + lt);
                if (cross) { acc[j][2] += y0; acc[j][3] += y1; }
            }

            // emit tails
            if (tail0 && v0r) {
                float* p = agg + (long long)d0 * 64 + 2 * lt;
#pragma unroll
                for (int j = 0; j < 8; j++)
                    asm volatile("red.global.add.v2.f32 [%0], {%1, %2};"
                                 :: "l"(p + 8 * j), "f"(acc[j][0]), "f"(acc[j][1])
                                 : "memory");
            }
            if (tail1 && v1r) {
                float* p = agg + (long long)d1 * 64 + 2 * lt;
#pragma unroll
                for (int j = 0; j < 8; j++)
                    asm volatile("red.global.add.v2.f32 [%0], {%1, %2};"
                                 :: "l"(p + 8 * j), "f"(acc[j][2]), "f"(acc[j][3])
                                 : "memory");
            }
        }
    }
}

// ---------------- prediction head ---------------------------------------------
__global__ __launch_bounds__(256)
void pred_kernel(const float* __restrict__ h, const float* __restrict__ pw,
                 const float* __restrict__ pb, float* __restrict__ out, int M)
{
    __shared__ float spw[64];
    __shared__ float swarp[8];
    if (threadIdx.x < 64) spw[threadIdx.x] = pw[threadIdx.x];
    __syncthreads();

    float sum = 0.0f;
    for (long long row = (long long)blockIdx.x * blockDim.x + threadIdx.x; row < M;
         row += (long long)gridDim.x * blockDim.x) {
        const float4* hr = (const float4*)(h + row * 64);
#pragma unroll
        for (int u = 0; u < 16; u++) {
            float4 v = hr[u];
            sum = fmaf(v.x, spw[4 * u + 0], sum);
            sum = fmaf(v.y, spw[4 * u + 1], sum);
            sum = fmaf(v.z, spw[4 * u + 2], sum);
            sum = fmaf(v.w, spw[4 * u + 3], sum);
        }
    }
#pragma unroll
    for (int o = 16; o > 0; o >>= 1) sum += __shfl_down_sync(0xffffffffu, sum, o);
    if ((threadIdx.x & 31) == 0) swarp[threadIdx.x >> 5] = sum;
    __syncthreads();
    if (threadIdx.x < 8) {
        float s = swarp[threadIdx.x];
#pragma unroll
        for (int o = 4; o > 0; o >>= 1) s += __shfl_down_sync(0xffu, s, o);
        if (threadIdx.x == 0) {
            if (blockIdx.x == 0) s = fmaf(pb[0], (float)M, s);
            atomicAdd(out, s);
        }
    }
}

// ---------------- launch ------------------------------------------------------
extern "C" void kernel_launch(void* const* d_in, const int* in_sizes, int n_in,
                              void* d_out, int out_size)
{
    const float* x       = (const float*)d_in[0];
    const void*  ei      = d_in[1];
    const float* eattr   = (const float*)d_in[2];
    const float* lin_w   = (const float*)d_in[3];
    const float* lin_b   = (const float*)d_in[4];
    const float* msg_w1  = (const float*)d_in[5];
    const float* msg_b1  = (const float*)d_in[6];
    const float* msg_w2  = (const float*)d_in[7];
    const float* msg_b2  = (const float*)d_in[8];
    const float* upd_w1  = (const float*)d_in[9];
    const float* upd_b1  = (const float*)d_in[10];
    const float* upd_w2  = (const float*)d_in[11];
    const float* upd_b2  = (const float*)d_in[12];
    const float* pred_w  = (const float*)d_in[13];
    const float* pred_b  = (const float*)d_in[14];

    const int M = in_sizes[0] / 128;   // 50000
    const int E = in_sizes[2] / 6;     // 800000

    float *h, *Pab, *agg;
    int* cnt;
    cudaGetSymbolAddress((void**)&h,   g_h);
    cudaGetSymbolAddress((void**)&Pab, g_Pab);
    cudaGetSymbolAddress((void**)&agg, g_agg);
    cudaGetSymbolAddress((void**)&cnt, g_cnt);

    const int gN = (M + 63) / 64;      // 782
    const int SM_EDGE = 55040;
    cudaFuncSetAttribute(edge_kernel_mma,
                         cudaFuncAttributeMaxDynamicSharedMemorySize, SM_EDGE);
    const int nChunks = (E + 15) / 16;
    int gEdge = 148 * 3;
    if (gEdge * 8 > nChunks) gEdge = (nChunks + 7) / 8;
    if (gEdge < 1) gEdge = 1;

    // ---- sort edges by dst (once; reused by all 4 layers) ----
    detect_idx_kernel<<<1, 32>>>((const unsigned int*)ei);
    cudaMemsetAsync(cnt, 0, NSCAN * sizeof(int));
    hist_kernel<<<1024, 256>>>(ei, E);
    scan1_kernel<<<NSCAN / 1024, 1024>>>();
    scan2_kernel<<<1, 64>>>(NSCAN / 1024);
    scan3_kernel<<<NSCAN / 1024, 1024>>>();
    scatter_kernel<<<1024, 256>>>(ei, eattr, E);

    // input projection fused with layer-0 dual
    proj_dual<<<gN, 256>>>(x, lin_w, lin_b,
                           msg_w1, msg_b1, h, Pab, M);

    for (int l = 0; l < 4; l++) {
        const float* W1 = msg_w1 + (size_t)l * 134 * 64;
        edge_kernel_mma<<<gEdge, 256, SM_EDGE>>>(Pab,
                                                 W1 + 128 * 64,
                                                 msg_w2 + (size_t)l * 64 * 64,
                                                 msg_b2 + l * 64, agg, E);
        if (l < 3) {
            const float* W1n = msg_w1 + (size_t)(l + 1) * 134 * 64;
            update_dual<true><<<gN, 256>>>(h, upd_w1 + (size_t)l * 128 * 64,
                                           upd_b1 + l * 64,
                                           upd_w2 + (size_t)l * 64 * 64,
                                           upd_b2 + l * 64, agg, h,
                                           W1n, msg_b1 + (l + 1) * 64, Pab, M);
        } else {
            update_dual<false><<<gN, 256>>>(h, upd_w1 + (size_t)l * 128 * 64,
                                            upd_b1 + l * 64,
                                            upd_w2 + (size_t)l * 64 * 64,
                                            upd_b2 + l * 64, agg, h,
                                            nullptr, nullptr, nullptr, M);
        }
    }

    cudaMemsetAsync(d_out, 0, sizeof(float));
    pred_kernel<<<256, 256>>>(h, pred_w, pred_b, (float*)d_out, M);
}

// round 15
// speedup vs baseline: 1.3010x; 1.0321x over previous
#include <cuda_runtime.h>
#include <cstdint>

#define EMB 64
#define NN_MAX 50000
#define NSCAN 50176          // 49 * 1024
#define NE_MAX 800000
#define NE_PAD (NE_MAX + 64)

// ---------------- scratch (static device memory; no allocations) ----------------
__device__ __align__(128) float g_h  [NN_MAX * EMB];
__device__ __align__(128) float g_Pab[NN_MAX * 128];   // [Pa | Pb] per node
__device__ __align__(128) float g_agg[NN_MAX * EMB];   // zero at launch entry (invariant)
__device__ int g_is64;

// sort scratch
__device__ int   g_cnt [NSCAN];
__device__ int   g_inc [NSCAN];
__device__ int   g_cur [NSCAN];
__device__ int   g_bsum[64];
// packed sorted edge records: {ea0..ea5, src(bits), dst(bits)} per edge (32B)
__device__ __align__(128) float g_rec[NE_PAD * 8];

// ---------------- helpers ------------------------------------------------------
__device__ __forceinline__ uint32_t f32_to_tf32(float f) {
    uint32_t u;
    asm("cvt.rna.tf32.f32 %0, %1;" : "=r"(u) : "f"(f));
    return u;
}
__device__ __forceinline__ void mma_tf32(float* c, const uint32_t* a, const uint32_t* b) {
    asm volatile(
        "mma.sync.aligned.m16n8k8.row.col.f32.tf32.tf32.f32 "
        "{%0,%1,%2,%3}, {%4,%5,%6,%7}, {%8,%9}, {%0,%1,%2,%3};"
        : "+f"(c[0]), "+f"(c[1]), "+f"(c[2]), "+f"(c[3])
        : "r"(a[0]), "r"(a[1]), "r"(a[2]), "r"(a[3]), "r"(b[0]), "r"(b[1]));
}

// ---------------- detect whether edge_index is int64 or int32 ----------------
__global__ void detect_idx_kernel(const unsigned int* __restrict__ p)
{
    if (threadIdx.x == 0 && blockIdx.x == 0) {
        unsigned int v = 0;
#pragma unroll
        for (int k = 0; k < 64; k++) v |= p[2 * k + 1];
        g_is64 = (v == 0) ? 1 : 0;
    }
}

// ---------------- counting sort by dst ----------------------------------------
__global__ void hist_kernel(const void* __restrict__ ei, int E)
{
    const int is64 = g_is64;
    for (long long e = (long long)blockIdx.x * blockDim.x + threadIdx.x; e < E;
         e += (long long)gridDim.x * blockDim.x) {
        int dst = is64 ? (int)((const long long*)ei)[(long long)E + e]
                       : ((const int*)ei)[(long long)E + e];
        atomicAdd(&g_cnt[dst], 1);
    }
}

__global__ __launch_bounds__(1024) void scan1_kernel()
{
    const int t = threadIdx.x, b = blockIdx.x;
    const int i = b * 1024 + t;
    const int lane = t & 31, wid = t >> 5;
    int x = g_cnt[i];
#pragma unroll
    for (int s = 1; s < 32; s <<= 1) {
        int u = __shfl_up_sync(0xffffffffu, x, s);
        if (lane >= s) x += u;
    }
    __shared__ int ws[32];
    if (lane == 31) ws[wid] = x;
    __syncthreads();
    if (wid == 0) {
        int y = ws[lane];
#pragma unroll
        for (int s = 1; s < 32; s <<= 1) {
            int u = __shfl_up_sync(0xffffffffu, y, s);
            if (lane >= s) y += u;
        }
        ws[lane] = y;
    }
    __syncthreads();
    int inc = x + (wid ? ws[wid - 1] : 0);
    g_inc[i] = inc;
    if (t == 1023) g_bsum[b] = inc;
}

// parallel exclusive scan of block sums (nb <= 64)
__global__ __launch_bounds__(64) void scan2_kernel(int nb)
{
    __shared__ int s[64];
    const int t = threadIdx.x;
    const int v = (t < nb) ? g_bsum[t] : 0;
    s[t] = v;
    __syncthreads();
#pragma unroll
    for (int o = 1; o < 64; o <<= 1) {
        int x = (t >= o) ? s[t - o] : 0;
        __syncthreads();
        s[t] += x;
        __syncthreads();
    }
    if (t < nb) g_bsum[t] = s[t] - v;
}

__global__ __launch_bounds__(1024) void scan3_kernel()
{
    const int i = blockIdx.x * 1024 + threadIdx.x;
    g_cur[i] = g_inc[i] - g_cnt[i] + g_bsum[blockIdx.x];
}

__global__ void scatter_kernel(const void* __restrict__ ei,
                               const float* __restrict__ eattr, int E)
{
    const int is64 = g_is64;
    for (long long e = (long long)blockIdx.x * blockDim.x + threadIdx.x; e < E;
         e += (long long)gridDim.x * blockDim.x) {
        int src, dst;
        if (is64) {
            src = (int)((const long long*)ei)[e];
            dst = (int)((const long long*)ei)[(long long)E + e];
        } else {
            src = ((const int*)ei)[e];
            dst = ((const int*)ei)[(long long)E + e];
        }
        float ea[6];
#pragma unroll
        for (int q = 0; q < 6; q++) ea[q] = eattr[e * 6 + q];
        int pos = atomicAdd(&g_cur[dst], 1);
        float* r = g_rec + (long long)pos * 8;
        *(float4*)(r)     = make_float4(ea[0], ea[1], ea[2], ea[3]);
        *(float4*)(r + 4) = make_float4(ea[4], ea[5],
                                        __int_as_float(src), __int_as_float(dst));
    }
}

// ---------------- dual phase (tf32 mma): Pab = [hT@W1a + b1 | hT@W1b] ----------
__device__ __forceinline__ void dual_phase_mma(const uint32_t* __restrict__ sHT,
                                               uint32_t* __restrict__ sWn,
                                               const float* __restrict__ W1n,
                                               const float* __restrict__ b1n,
                                               float* __restrict__ sB1,
                                               float* __restrict__ Pab,
                                               int brow, int M, int tid)
{
    const int w = tid >> 5, l = tid & 31;
    const int lg = l >> 2, lt = l & 3;
    const int rowg = w & 3, half = w >> 2;

    if (tid < 64) sB1[tid] = b1n[tid];

    float acc[8][4];
#pragma unroll
    for (int j = 0; j < 8; j++)
#pragma unroll
        for (int q = 0; q < 4; q++) acc[j][q] = 0.0f;

#pragma unroll
    for (int stage = 0; stage < 2; stage++) {
        const int kc = stage * 32;
        __syncthreads();
#pragma unroll
        for (int s4 = 0; s4 < 4; s4++) {
            const int f = tid * 4 + s4;
            const int kk = f >> 5;
            const int c4 = (f & 31) * 4;
            const float* src = (c4 < 64)
                ? (W1n + (long long)(kc + kk) * 64 + c4)
                : (W1n + (long long)(64 + kc + kk) * 64 + (c4 - 64));
            float4 v = *(const float4*)src;
            uint4 t;
            t.x = f32_to_tf32(v.x); t.y = f32_to_tf32(v.y);
            t.z = f32_to_tf32(v.z); t.w = f32_to_tf32(v.w);
            *(uint4*)&sWn[kk * 136 + c4] = t;
        }
        __syncthreads();
#pragma unroll
        for (int s = 0; s < 4; s++) {
            const int k0 = 8 * s;
            uint32_t af[4];
            const uint32_t* base = sHT + (16 * rowg + lg) * 68 + kc + k0 + lt;
            af[0] = base[0];
            af[1] = base[8 * 68];
            af[2] = base[4];
            af[3] = base[8 * 68 + 4];
#pragma unroll
            for (int j = 0; j < 8; j++) {
                uint32_t bf[2];
                bf[0] = sWn[(k0 + lt)     * 136 + 8 * j + lg + 64 * half];
                bf[1] = sWn[(k0 + lt + 4) * 136 + 8 * j + lg + 64 * half];
                mma_tf32(acc[j], af, bf);
            }
        }
    }

    const bool dob = (half == 0);
#pragma unroll
    for (int j = 0; j < 8; j++) {
        const int col = 64 * half + 8 * j + 2 * lt;
        float b0 = 0.f, b1v = 0.f;
        if (dob) {
            float2 bb = *(const float2*)(sB1 + 8 * j + 2 * lt);
            b0 = bb.x; b1v = bb.y;
        }
        const int r0 = brow + 16 * rowg + lg;
        const int r1 = r0 + 8;
        if (r0 < M)
            *(float2*)(Pab + (long long)r0 * 128 + col) =
                make_float2(acc[j][0] + b0, acc[j][1] + b1v);
        if (r1 < M)
            *(float2*)(Pab + (long long)r1 * 128 + col) =
                make_float2(acc[j][2] + b0, acc[j][3] + b1v);
    }
}

// ---------------- proj_dual: h = x@Win + bin; Pab = dual(h) --------------------
__global__ __launch_bounds__(256)
void proj_dual(const float* __restrict__ x, const float* __restrict__ Win,
               const float* __restrict__ bin,
               const float* __restrict__ W1n, const float* __restrict__ b1n,
               float* __restrict__ h, float* __restrict__ Pab, int M)
{
    __shared__ __align__(16) float    sA[32 * 64];
    __shared__ __align__(16) float    sW[32 * 136];
    __shared__ __align__(16) uint32_t sHT[64 * 68];
    __shared__ float sB1[64];

    const int tid  = threadIdx.x;
    const int brow = blockIdx.x * 64;
    const int cg = tid & 15, rg = tid >> 4;
    const int c0 = cg * 4,   r0 = rg * 4;

    const int lrow = tid >> 2;
    const int lcol = (tid & 3) * 4;
    const int grow = brow + lrow;
    const int kr = tid >> 4;
    const int wc = (tid & 15) * 4;

    float acc[4][4];
#pragma unroll
    for (int i = 0; i < 4; i++)
#pragma unroll
        for (int j = 0; j < 4; j++)
            acc[i][j] = bin[c0 + j];

    for (int kc = 0; kc < 128; kc += 32) {
#pragma unroll
        for (int q = 0; q < 2; q++) {
            const int col = lcol + 16 * q;
            float4 av = make_float4(0.f, 0.f, 0.f, 0.f);
            if (grow < M)
                av = *(const float4*)(x + (long long)grow * 128 + kc + col);
            sA[(col + 0) * 64 + lrow] = av.x;
            sA[(col + 1) * 64 + lrow] = av.y;
            sA[(col + 2) * 64 + lrow] = av.z;
            sA[(col + 3) * 64 + lrow] = av.w;
            *(float4*)&sW[(kr + 16 * q) * 64 + wc] =
                *(const float4*)(Win + (long long)(kc + kr + 16 * q) * 64 + wc);
        }
        __syncthreads();
#pragma unroll
        for (int kk = 0; kk < 32; kk++) {
            float4 a = *(const float4*)&sA[kk * 64 + r0];
            float4 w = *(const float4*)&sW[kk * 64 + c0];
            float ar[4] = {a.x, a.y, a.z, a.w};
            float wr[4] = {w.x, w.y, w.z, w.w};
#pragma unroll
            for (int i = 0; i < 4; i++)
#pragma unroll
                for (int j = 0; j < 4; j++)
                    acc[i][j] = fmaf(ar[i], wr[j], acc[i][j]);
        }
        __syncthreads();
    }

#pragma unroll
    for (int i = 0; i < 4; i++) {
        const int row = brow + r0 + i;
        const bool v = row < M;
        if (v)
            *(float4*)(h + (long long)row * 64 + c0) =
                make_float4(acc[i][0], acc[i][1], acc[i][2], acc[i][3]);
        uint4 t;
        t.x = f32_to_tf32(v ? acc[i][0] : 0.f);
        t.y = f32_to_tf32(v ? acc[i][1] : 0.f);
        t.z = f32_to_tf32(v ? acc[i][2] : 0.f);
        t.w = f32_to_tf32(v ? acc[i][3] : 0.f);
        *(uint4*)&sHT[(r0 + i) * 68 + c0] = t;
    }

    dual_phase_mma(sHT, (uint32_t*)sW, W1n, b1n, sB1, Pab, brow, M, tid);
}

// ---------------- update_dual: h += relu(relu([h|agg]U1+b1)U2+b2); dual --------
template <bool DO_DUAL>
__global__ __launch_bounds__(256)
void update_dual(const float* __restrict__ h_in, const float* __restrict__ U1,
                 const float* __restrict__ b1, const float* __restrict__ U2,
                 const float* __restrict__ b2, float* agg,
                 float* __restrict__ h_out,
                 const float* __restrict__ W1n, const float* __restrict__ b1n,
                 float* __restrict__ Pab, int M)
{
    __shared__ __align__(16) float sA [32 * 64];
    __shared__ __align__(16) float sW [32 * 136];
    __shared__ __align__(16) float sU1[64 * 68];
    __shared__ float sB1n[64];

    const int tid  = threadIdx.x;
    const int brow = blockIdx.x * 64;
    const int cg = tid & 15, rg = tid >> 4;
    const int c0 = cg * 4,   r0 = rg * 4;

    const int lrow = tid >> 2;
    const int lcol = (tid & 3) * 4;
    const int grow = brow + lrow;
    const int kr = tid >> 4;
    const int wc = (tid & 15) * 4;

    float acc[4][4];
#pragma unroll
    for (int i = 0; i < 4; i++)
#pragma unroll
        for (int j = 0; j < 4; j++)
            acc[i][j] = b1[c0 + j];

#pragma unroll
    for (int p = 0; p < 2; p++) {
        const float* A = p ? agg : h_in;
        const float* W = U1 + (long long)p * 64 * 64;
        for (int kc = 0; kc < 64; kc += 32) {
#pragma unroll
            for (int q = 0; q < 2; q++) {
                const int col = lcol + 16 * q;
                float4 av = make_float4(0.f, 0.f, 0.f, 0.f);
                if (grow < M) {
                    av = *(const float4*)(A + (long long)grow * 64 + kc + col);
                    if (p == 1)
                        *(float4*)(agg + (long long)grow * 64 + kc + col) =
                            make_float4(0.f, 0.f, 0.f, 0.f);
                }
                sA[(col + 0) * 64 + lrow] = av.x;
                sA[(col + 1) * 64 + lrow] = av.y;
                sA[(col + 2) * 64 + lrow] = av.z;
                sA[(col + 3) * 64 + lrow] = av.w;
                *(float4*)&sW[(kr + 16 * q) * 64 + wc] =
                    *(const float4*)(W + (long long)(kc + kr + 16 * q) * 64 + wc);
            }
            __syncthreads();
#pragma unroll
            for (int kk = 0; kk < 32; kk++) {
                float4 a = *(const float4*)&sA[kk * 64 + r0];
                float4 w = *(const float4*)&sW[kk * 64 + c0];
                float ar[4] = {a.x, a.y, a.z, a.w};
                float wr[4] = {w.x, w.y, w.z, w.w};
#pragma unroll
                for (int i = 0; i < 4; i++)
#pragma unroll
                    for (int j = 0; j < 4; j++)
                        acc[i][j] = fmaf(ar[i], wr[j], acc[i][j]);
            }
            __syncthreads();
        }
    }

#pragma unroll
    for (int i = 0; i < 4; i++)
#pragma unroll
        for (int j = 0; j < 4; j++)
            sU1[(c0 + j) * 68 + r0 + i] = fmaxf(acc[i][j], 0.0f);
    __syncthreads();

    float acc2[4][4];
#pragma unroll
    for (int i = 0; i < 4; i++)
#pragma unroll
        for (int j = 0; j < 4; j++)
            acc2[i][j] = b2[c0 + j];

    for (int kc = 0; kc < 64; kc += 32) {
#pragma unroll
        for (int q = 0; q < 2; q++)
            *(float4*)&sW[(kr + 16 * q) * 64 + wc] =
                *(const float4*)(U2 + (long long)(kc + kr + 16 * q) * 64 + wc);
        __syncthreads();
#pragma unroll
        for (int kk = 0; kk < 32; kk++) {
            float4 a = *(const float4*)&sU1[(kc + kk) * 68 + r0];
            float4 w = *(const float4*)&sW[kk * 64 + c0];
            float ar[4] = {a.x, a.y, a.z, a.w};
            float wr[4] = {w.x, w.y, w.z, w.w};
#pragma unroll
            for (int i = 0; i < 4; i++)
#pragma unroll
                for (int j = 0; j < 4; j++)
                    acc2[i][j] = fmaf(ar[i], wr[j], acc2[i][j]);
        }
        __syncthreads();
    }

    uint32_t* sHT = (uint32_t*)sU1;
#pragma unroll
    for (int i = 0; i < 4; i++) {
        const int row = brow + r0 + i;
        const bool v = row < M;
        float hn[4] = {0.f, 0.f, 0.f, 0.f};
        if (v) {
            float4 hh = *(const float4*)(h_out + (long long)row * 64 + c0);
            hn[0] = hh.x + fmaxf(acc2[i][0], 0.f);
            hn[1] = hh.y + fmaxf(acc2[i][1], 0.f);
            hn[2] = hh.z + fmaxf(acc2[i][2], 0.f);
            hn[3] = hh.w + fmaxf(acc2[i][3], 0.f);
            *(float4*)(h_out + (long long)row * 64 + c0) =
                make_float4(hn[0], hn[1], hn[2], hn[3]);
        }
        if (DO_DUAL) {
            uint4 t;
            t.x = f32_to_tf32(hn[0]); t.y = f32_to_tf32(hn[1]);
            t.z = f32_to_tf32(hn[2]); t.w = f32_to_tf32(hn[3]);
            *(uint4*)&sHT[(r0 + i) * 68 + c0] = t;
        }
    }

    if (DO_DUAL)
        dual_phase_mma(sHT, (uint32_t*)sW, W1n, b1n, sB1n, Pab, brow, M, tid);
}

// ---------------- edge kernel: 32-edge tiles, fragment-layout segmented scan ---
#define A_STRIDE 68
#define W_STRIDE 72
__global__ __launch_bounds__(256, 2)
void edge_kernel_mma(const float* __restrict__ Pab,
                     const float* __restrict__ W1c,   // 6 x 64
                     const float* __restrict__ W2,    // 64 x 64 (k x n)
                     const float* __restrict__ b2,    // 64
                     float* __restrict__ agg, int E)
{
    extern __shared__ __align__(16) char smem[];
    uint32_t* sA   = (uint32_t*)smem;                       // 8 warps x 32 x 68
    uint32_t* sW2  = (uint32_t*)(smem + 69632);             // 64 x 72 (tf32)
    float*    sW1c = (float*)(smem + 88064);                // 6 x 64
    float*    sB2  = (float*)(smem + 89600);                // 64

    const int tid = threadIdx.x;
    const int w   = tid >> 5;
    const int l   = tid & 31;

    for (int i = tid; i < 64 * 64; i += 256) {
        int k = i >> 6, n = i & 63;
        sW2[k * W_STRIDE + n] = f32_to_tf32(W2[i]);
    }
    for (int i = tid; i < 384; i += 256) sW1c[i] = W1c[i];
    if (tid < 64) sB2[tid] = b2[tid];
    __syncthreads();

    uint32_t* myA = sA + w * 32 * A_STRIDE;
    const int gw = blockIdx.x * 8 + w;
    const int nW = gridDim.x * 8;
    const int nChunks = (E + 31) >> 5;

    const int lg  = l >> 2;       // 0..7
    const int lt  = l & 3;        // 0..3
    const int er  = l >> 3;       // 0..3 (phase A: edge-in-quad)
    const int c4  = (l & 7) * 4;  // phase A col base

    // prefetch first record (lane l -> edge l of chunk)
    float4 p0 = make_float4(0.f, 0.f, 0.f, 0.f);
    float4 p1 = make_float4(0.f, 0.f, 0.f, __int_as_float(-1));
    if (gw < nChunks) {
        long long eg = ((long long)gw << 5) + l;
        if (eg < E) {
            const float* r = g_rec + eg * 8;
            p0 = *(const float4*)(r);
            p1 = *(const float4*)(r + 4);
        }
    }

    for (int ch = gw; ch < nChunks; ch += nW) {
        const long long e0 = (long long)ch << 5;

        const float ea0 = p0.x, ea1 = p0.y, ea2 = p0.z, ea3 = p0.w;
        const float ea4 = p1.x, ea5 = p1.y;
        const int src = __float_as_int(p1.z);
        const int dst = __float_as_int(p1.w);

        // prefetch next chunk's record
        {
            const int chn = ch + nW;
            p0 = make_float4(0.f, 0.f, 0.f, 0.f);
            p1 = make_float4(0.f, 0.f, 0.f, __int_as_float(-1));
            if (chn < nChunks) {
                long long eg = ((long long)chn << 5) + l;
                if (eg < E) {
                    const float* r = g_rec + eg * 8;
                    p0 = *(const float4*)(r);
                    p1 = *(const float4*)(r + 4);
                }
            }
        }

        // ---- phase A: m1 (32 edges: 8 passes of 4 edges x 8 lanes) ----
#pragma unroll
        for (int it = 0; it < 8; it++) {
            const int e = 4 * it + er;
            const int de = __shfl_sync(0xffffffffu, dst, e);
            const int se = __shfl_sync(0xffffffffu, src, e);
            float eq[6];
            eq[0] = __shfl_sync(0xffffffffu, ea0, e);
            eq[1] = __shfl_sync(0xffffffffu, ea1, e);
            eq[2] = __shfl_sync(0xffffffffu, ea2, e);
            eq[3] = __shfl_sync(0xffffffffu, ea3, e);
            eq[4] = __shfl_sync(0xffffffffu, ea4, e);
            eq[5] = __shfl_sync(0xffffffffu, ea5, e);
            const bool ev = (e0 + e) < E;
            const float* par = Pab + (long long)de * 128;
            const float* pbr = Pab + (long long)se * 128 + 64;
#pragma unroll
            for (int h = 0; h < 2; h++) {
                const int c = c4 + 32 * h;
                float v0 = 0.f, v1 = 0.f, v2 = 0.f, v3 = 0.f;
                if (ev) {
                    float4 a = *(const float4*)(par + c);
                    float4 b = *(const float4*)(pbr + c);
                    v0 = a.x + b.x; v1 = a.y + b.y; v2 = a.z + b.z; v3 = a.w + b.w;
#pragma unroll
                    for (int q = 0; q < 6; q++) {
                        float4 wv = *(const float4*)(sW1c + q * 64 + c);
                        v0 = fmaf(eq[q], wv.x, v0);
                        v1 = fmaf(eq[q], wv.y, v1);
                        v2 = fmaf(eq[q], wv.z, v2);
                        v3 = fmaf(eq[q], wv.w, v3);
                    }
                }
                uint32_t r0 = f32_to_tf32(fmaxf(v0, 0.f));
                uint32_t r1 = f32_to_tf32(fmaxf(v1, 0.f));
                uint32_t r2 = f32_to_tf32(fmaxf(v2, 0.f));
                uint32_t r3 = f32_to_tf32(fmaxf(v3, 0.f));
                *(uint4*)(myA + e * A_STRIDE + c) = make_uint4(r0, r1, r2, r3);
            }
        }
        __syncwarp();

        // ---- mma: D(32x64) = m1 @ W2 (bf reused across 2 row groups) ----
        float acc[2][8][4];
#pragma unroll
        for (int g = 0; g < 2; g++)
#pragma unroll
            for (int j = 0; j < 8; j++)
#pragma unroll
                for (int q = 0; q < 4; q++) acc[g][j][q] = 0.0f;

#pragma unroll
        for (int s = 0; s < 8; s++) {
            const int k0 = 8 * s;
            uint32_t bf[8][2];
#pragma unroll
            for (int j = 0; j < 8; j++) {
                bf[j][0] = sW2[(k0 + lt)     * W_STRIDE + 8 * j + lg];
                bf[j][1] = sW2[(k0 + lt + 4) * W_STRIDE + 8 * j + lg];
            }
            uint32_t af[2][4];
#pragma unroll
            for (int g = 0; g < 2; g++) {
                const uint32_t* base = myA + (16 * g + lg) * A_STRIDE + k0 + lt;
                af[g][0] = base[0];
                af[g][1] = base[8 * A_STRIDE];
                af[g][2] = base[4];
                af[g][3] = base[8 * A_STRIDE + 4];
            }
#pragma unroll
            for (int g = 0; g < 2; g++)
#pragma unroll
                for (int j = 0; j < 8; j++)
                    mma_tf32(acc[g][j], af[g], bf[j]);
        }
        __syncwarp();   // myA reads done before next chunk's phase A

        // ---- segmented reduction in fragment layout (32 edges) ----
        {
            // rows owned by this lane: r[i] = lg + 8i, i=0..3
            // vals: acc[i>>1][j][2*(i&1) + {0,1}]
            const int dprev = __shfl_up_sync(0xffffffffu, dst, 1);
            const bool head = (l == 0) || (dprev != dst);
            const unsigned hm = __ballot_sync(0xffffffffu, head);

            int dmy[4]; bool vr[4], tl[4], cross[4]; int dd[4];
#pragma unroll
            for (int i = 0; i < 4; i++) {
                const int r = lg + 8 * i;
                dmy[i] = __shfl_sync(0xffffffffu, dst, r);
                vr[i] = (e0 + r) < E;
                const unsigned below = hm & (unsigned)((2ull << r) - 1ull);
                const int hs = 31 - __clz(below);
                const int dist = r - hs;
                dd[i] = dist < lg ? dist : lg;
                cross[i] = dist > lg;
                tl[i] = (r == 31) || (((hm >> (r + 1)) & 1u) != 0);
            }

            // bias + relu (+zero invalid rows)
#pragma unroll
            for (int j = 0; j < 8; j++) {
                float2 bb = *(const float2*)(sB2 + 8 * j + 2 * lt);
#pragma unroll
                for (int g = 0; g < 2; g++) {
                    acc[g][j][0] = vr[2 * g]     ? fmaxf(acc[g][j][0] + bb.x, 0.f) : 0.f;
                    acc[g][j][1] = vr[2 * g]     ? fmaxf(acc[g][j][1] + bb.y, 0.f) : 0.f;
                    acc[g][j][2] = vr[2 * g + 1] ? fmaxf(acc[g][j][2] + bb.x, 0.f) : 0.f;
                    acc[g][j][3] = vr[2 * g + 1] ? fmaxf(acc[g][j][3] + bb.y, 0.f) : 0.f;
                }
            }

            // intra-8-row segmented scans (3 steps, lanes stride 4)
#pragma unroll
            for (int s = 1; s < 8; s <<= 1) {
#pragma unroll
                for (int g = 0; g < 2; g++)
#pragma unroll
                    for (int j = 0; j < 8; j++) {
                        float y0 = __shfl_up_sync(0xffffffffu, acc[g][j][0], 4 * s);
                        float y1 = __shfl_up_sync(0xffffffffu, acc[g][j][1], 4 * s);
                        float y2 = __shfl_up_sync(0xffffffffu, acc[g][j][2], 4 * s);
                        float y3 = __shfl_up_sync(0xffffffffu, acc[g][j][3], 4 * s);
                        if (dd[2 * g]     >= s) { acc[g][j][0] += y0; acc[g][j][1] += y1; }
                        if (dd[2 * g + 1] >= s) { acc[g][j][2] += y2; acc[g][j][3] += y3; }
                    }
            }
            // serial boundary combines: row7 -> rows 8-15; row15 -> 16-23; row23 -> 24-31
#pragma unroll
            for (int j = 0; j < 8; j++) {
                float y0 = __shfl_sync(0xffffffffu, acc[0][j][0], 28 + lt);
                float y1 = __shfl_sync(0xffffffffu, acc[0][j][1], 28 + lt);
                if (cross[1]) { acc[0][j][2] += y0; acc[0][j][3] += y1; }
            }
#pragma unroll
            for (int j = 0; j < 8; j++) {
                float y0 = __shfl_sync(0xffffffffu, acc[0][j][2], 28 + lt);
                float y1 = __shfl_sync(0xffffffffu, acc[0][j][3], 28 + lt);
                if (cross[2]) { acc[1][j][0] += y0; acc[1][j][1] += y1; }
            }
#pragma unroll
            for (int j = 0; j < 8; j++) {
                float y0 = __shfl_sync(0xffffffffu, acc[1][j][0], 28 + lt);
                float y1 = __shfl_sync(0xffffffffu, acc[1][j][1], 28 + lt);
                if (cross[3]) { acc[1][j][2] += y0; acc[1][j][3] += y1; }
            }

            // emit tails
#pragma unroll
            for (int i = 0; i < 4; i++) {
                if (tl[i] && vr[i]) {
                    float* p = agg + (long long)dmy[i] * 64 + 2 * lt;
                    const int g = i >> 1, o = 2 * (i & 1);
#pragma unroll
                    for (int j = 0; j < 8; j++)
                        asm volatile("red.global.add.v2.f32 [%0], {%1, %2};"
                                     :: "l"(p + 8 * j),
                                        "f"(acc[g][j][o]), "f"(acc[g][j][o + 1])
                                     : "memory");
                }
            }
        }
    }
}

// ---------------- prediction head ---------------------------------------------
__global__ __launch_bounds__(256)
void pred_kernel(const float* __restrict__ h, const float* __restrict__ pw,
                 const float* __restrict__ pb, float* __restrict__ out, int M)
{
    __shared__ float spw[64];
    __shared__ float swarp[8];
    if (threadIdx.x < 64) spw[threadIdx.x] = pw[threadIdx.x];
    __syncthreads();

    float sum = 0.0f;
    for (long long row = (long long)blockIdx.x * blockDim.x + threadIdx.x; row < M;
         row += (long long)gridDim.x * blockDim.x) {
        const float4* hr = (const float4*)(h + row * 64);
#pragma unroll
        for (int u = 0; u < 16; u++) {
            float4 v = hr[u];
            sum = fmaf(v.x, spw[4 * u + 0], sum);
            sum = fmaf(v.y, spw[4 * u + 1], sum);
            sum = fmaf(v.z, spw[4 * u + 2], sum);
            sum = fmaf(v.w, spw[4 * u + 3], sum);
        }
    }
#pragma unroll
    for (int o = 16; o > 0; o >>= 1) sum += __shfl_down_sync(0xffffffffu, sum, o);
    if ((threadIdx.x & 31) == 0) swarp[threadIdx.x >> 5] = sum;
    __syncthreads();
    if (threadIdx.x < 8) {
        float s = swarp[threadIdx.x];
#pragma unroll
        for (int o = 4; o > 0; o >>= 1) s += __shfl_down_sync(0xffu, s, o);
        if (threadIdx.x == 0) {
            if (blockIdx.x == 0) s = fmaf(pb[0], (float)M, s);
            atomicAdd(out, s);
        }
    }
}

// ---------------- launch ------------------------------------------------------
extern "C" void kernel_launch(void* const* d_in, const int* in_sizes, int n_in,
                              void* d_out, int out_size)
{
    const float* x       = (const float*)d_in[0];
    const void*  ei      = d_in[1];
    const float* eattr   = (const float*)d_in[2];
    const float* lin_w   = (const float*)d_in[3];
    const float* lin_b   = (const float*)d_in[4];
    const float* msg_w1  = (const float*)d_in[5];
    const float* msg_b1  = (const float*)d_in[6];
    const float* msg_w2  = (const float*)d_in[7];
    const float* msg_b2  = (const float*)d_in[8];
    const float* upd_w1  = (const float*)d_in[9];
    const float* upd_b1  = (const float*)d_in[10];
    const float* upd_w2  = (const float*)d_in[11];
    const float* upd_b2  = (const float*)d_in[12];
    const float* pred_w  = (const float*)d_in[13];
    const float* pred_b  = (const float*)d_in[14];

    const int M = in_sizes[0] / 128;   // 50000
    const int E = in_sizes[2] / 6;     // 800000

    float *h, *Pab, *agg;
    int* cnt;
    cudaGetSymbolAddress((void**)&h,   g_h);
    cudaGetSymbolAddress((void**)&Pab, g_Pab);
    cudaGetSymbolAddress((void**)&agg, g_agg);
    cudaGetSymbolAddress((void**)&cnt, g_cnt);

    const int gN = (M + 63) / 64;      // 782
    const int SM_EDGE = 90112;
    cudaFuncSetAttribute(edge_kernel_mma,
                         cudaFuncAttributeMaxDynamicSharedMemorySize, SM_EDGE);
    const int nChunks = (E + 31) / 32;
    int gEdge = 148 * 2;
    if (gEdge * 8 > nChunks) gEdge = (nChunks + 7) / 8;
    if (gEdge < 1) gEdge = 1;

    // ---- sort edges by dst (once; reused by all 4 layers) ----
    detect_idx_kernel<<<1, 32>>>((const unsigned int*)ei);
    cudaMemsetAsync(cnt, 0, NSCAN * sizeof(int));
    hist_kernel<<<1024, 256>>>(ei, E);
    scan1_kernel<<<NSCAN / 1024, 1024>>>();
    scan2_kernel<<<1, 64>>>(NSCAN / 1024);
    scan3_kernel<<<NSCAN / 1024, 1024>>>();
    scatter_kernel<<<1024, 256>>>(ei, eattr, E);

    // input projection fused with layer-0 dual
    proj_dual<<<gN, 256>>>(x, lin_w, lin_b,
                           msg_w1, msg_b1, h, Pab, M);

    for (int l = 0; l < 4; l++) {
        const float* W1 = msg_w1 + (size_t)l * 134 * 64;
        edge_kernel_mma<<<gEdge, 256, SM_EDGE>>>(Pab,
                                                 W1 + 128 * 64,
                                                 msg_w2 + (size_t)l * 64 * 64,
                                                 msg_b2 + l * 64, agg, E);
        if (l < 3) {
            const float* W1n = msg_w1 + (size_t)(l + 1) * 134 * 64;
            update_dual<true><<<gN, 256>>>(h, upd_w1 + (size_t)l * 128 * 64,
                                           upd_b1 + l * 64,
                                           upd_w2 + (size_t)l * 64 * 64,
                                           upd_b2 + l * 64, agg, h,
                                           W1n, msg_b1 + (l + 1) * 64, Pab, M);
        } else {
            update_dual<false><<<gN, 256>>>(h, upd_w1 + (size_t)l * 128 * 64,
                                            upd_b1 + l * 64,
                                            upd_w2 + (size_t)l * 64 * 64,
                                            upd_b2 + l * 64, agg, h,
                                            nullptr, nullptr, nullptr, M);
        }
    }

    cudaMemsetAsync(d_out, 0, sizeof(float));
    pred_kernel<<<256, 256>>>(h, pred_w, pred_b, (float*)d_out, M);
}

// round 16
// speedup vs baseline: 1.3053x; 1.0033x over previous
#include <cuda_runtime.h>
#include <cstdint>

#define EMB 64
#define NN_MAX 50000
#define NSCAN 50176          // 49 * 1024
#define NE_MAX 800000
#define NE_PAD (NE_MAX + 64)

// ---------------- scratch (static device memory; no allocations) ----------------
__device__ __align__(128) float g_h  [NN_MAX * EMB];
__device__ __align__(128) float g_Pab[NN_MAX * 128];   // [Pa | Pb] per node
__device__ __align__(128) float g_agg[NN_MAX * EMB];   // zero at launch entry (invariant)
__device__ int g_is64;

// sort scratch
__device__ int   g_cnt [NSCAN];
__device__ int   g_inc [NSCAN];
__device__ int   g_cur [NSCAN];
__device__ int   g_bsum[64];
// packed sorted edge records: {ea0..ea5, src(bits), dst(bits)} per edge (32B)
__device__ __align__(128) float g_rec[NE_PAD * 8];

// ---------------- helpers ------------------------------------------------------
__device__ __forceinline__ uint32_t f32_to_tf32(float f) {
    uint32_t u;
    asm("cvt.rna.tf32.f32 %0, %1;" : "=r"(u) : "f"(f));
    return u;
}
__device__ __forceinline__ void mma_tf32(float* c, const uint32_t* a, const uint32_t* b) {
    asm volatile(
        "mma.sync.aligned.m16n8k8.row.col.f32.tf32.tf32.f32 "
        "{%0,%1,%2,%3}, {%4,%5,%6,%7}, {%8,%9}, {%0,%1,%2,%3};"
        : "+f"(c[0]), "+f"(c[1]), "+f"(c[2]), "+f"(c[3])
        : "r"(a[0]), "r"(a[1]), "r"(a[2]), "r"(a[3]), "r"(b[0]), "r"(b[1]));
}

// ---------------- detect whether edge_index is int64 or int32 ----------------
__global__ void detect_idx_kernel(const unsigned int* __restrict__ p)
{
    if (threadIdx.x == 0 && blockIdx.x == 0) {
        unsigned int v = 0;
#pragma unroll
        for (int k = 0; k < 64; k++) v |= p[2 * k + 1];
        g_is64 = (v == 0) ? 1 : 0;
    }
}

// ---------------- counting sort by dst ----------------------------------------
__global__ void hist_kernel(const void* __restrict__ ei, int E)
{
    const int is64 = g_is64;
    for (long long e = (long long)blockIdx.x * blockDim.x + threadIdx.x; e < E;
         e += (long long)gridDim.x * blockDim.x) {
        int dst = is64 ? (int)((const long long*)ei)[(long long)E + e]
                       : ((const int*)ei)[(long long)E + e];
        atomicAdd(&g_cnt[dst], 1);
    }
}

__global__ __launch_bounds__(1024) void scan1_kernel()
{
    const int t = threadIdx.x, b = blockIdx.x;
    const int i = b * 1024 + t;
    const int lane = t & 31, wid = t >> 5;
    int x = g_cnt[i];
#pragma unroll
    for (int s = 1; s < 32; s <<= 1) {
        int u = __shfl_up_sync(0xffffffffu, x, s);
        if (lane >= s) x += u;
    }
    __shared__ int ws[32];
    if (lane == 31) ws[wid] = x;
    __syncthreads();
    if (wid == 0) {
        int y = ws[lane];
#pragma unroll
        for (int s = 1; s < 32; s <<= 1) {
            int u = __shfl_up_sync(0xffffffffu, y, s);
            if (lane >= s) y += u;
        }
        ws[lane] = y;
    }
    __syncthreads();
    int inc = x + (wid ? ws[wid - 1] : 0);
    g_inc[i] = inc;
    if (t == 1023) g_bsum[b] = inc;
}

// scan3 with inline exclusive block-prefix (scan2 folded in)
__global__ __launch_bounds__(1024) void scan3_kernel()
{
    __shared__ int base;
    if (threadIdx.x == 0) {
        int s = 0;
        for (int j = 0; j < blockIdx.x; j++) s += g_bsum[j];
        base = s;
    }
    __syncthreads();
    const int i = blockIdx.x * 1024 + threadIdx.x;
    g_cur[i] = g_inc[i] - g_cnt[i] + base;
}

__global__ void scatter_kernel(const void* __restrict__ ei,
                               const float* __restrict__ eattr, int E)
{
    const int is64 = g_is64;
    for (long long e = (long long)blockIdx.x * blockDim.x + threadIdx.x; e < E;
         e += (long long)gridDim.x * blockDim.x) {
        int src, dst;
        if (is64) {
            src = (int)((const long long*)ei)[e];
            dst = (int)((const long long*)ei)[(long long)E + e];
        } else {
            src = ((const int*)ei)[e];
            dst = ((const int*)ei)[(long long)E + e];
        }
        float ea[6];
#pragma unroll
        for (int q = 0; q < 6; q++) ea[q] = eattr[e * 6 + q];
        int pos = atomicAdd(&g_cur[dst], 1);
        float* r = g_rec + (long long)pos * 8;
        *(float4*)(r)     = make_float4(ea[0], ea[1], ea[2], ea[3]);
        *(float4*)(r + 4) = make_float4(ea[4], ea[5],
                                        __int_as_float(src), __int_as_float(dst));
    }
}

// ---------------- dual phase (tf32 mma): Pab = [hT@W1a + b1 | hT@W1b] ----------
__device__ __forceinline__ void dual_phase_mma(const uint32_t* __restrict__ sHT,
                                               uint32_t* __restrict__ sWn,
                                               const float* __restrict__ W1n,
                                               const float* __restrict__ b1n,
                                               float* __restrict__ sB1,
                                               float* __restrict__ Pab,
                                               int brow, int M, int tid)
{
    const int w = tid >> 5, l = tid & 31;
    const int lg = l >> 2, lt = l & 3;
    const int rowg = w & 3, half = w >> 2;

    if (tid < 64) sB1[tid] = b1n[tid];

    float acc[8][4];
#pragma unroll
    for (int j = 0; j < 8; j++)
#pragma unroll
        for (int q = 0; q < 4; q++) acc[j][q] = 0.0f;

#pragma unroll
    for (int stage = 0; stage < 2; stage++) {
        const int kc = stage * 32;
        __syncthreads();
#pragma unroll
        for (int s4 = 0; s4 < 4; s4++) {
            const int f = tid * 4 + s4;
            const int kk = f >> 5;
            const int c4 = (f & 31) * 4;
            const float* src = (c4 < 64)
                ? (W1n + (long long)(kc + kk) * 64 + c4)
                : (W1n + (long long)(64 + kc + kk) * 64 + (c4 - 64));
            float4 v = *(const float4*)src;
            uint4 t;
            t.x = f32_to_tf32(v.x); t.y = f32_to_tf32(v.y);
            t.z = f32_to_tf32(v.z); t.w = f32_to_tf32(v.w);
            *(uint4*)&sWn[kk * 136 + c4] = t;
        }
        __syncthreads();
#pragma unroll
        for (int s = 0; s < 4; s++) {
            const int k0 = 8 * s;
            uint32_t af[4];
            const uint32_t* base = sHT + (16 * rowg + lg) * 68 + kc + k0 + lt;
            af[0] = base[0];
            af[1] = base[8 * 68];
            af[2] = base[4];
            af[3] = base[8 * 68 + 4];
#pragma unroll
            for (int j = 0; j < 8; j++) {
                uint32_t bf[2];
                bf[0] = sWn[(k0 + lt)     * 136 + 8 * j + lg + 64 * half];
                bf[1] = sWn[(k0 + lt + 4) * 136 + 8 * j + lg + 64 * half];
                mma_tf32(acc[j], af, bf);
            }
        }
    }

    const bool dob = (half == 0);
#pragma unroll
    for (int j = 0; j < 8; j++) {
        const int col = 64 * half + 8 * j + 2 * lt;
        float b0 = 0.f, b1v = 0.f;
        if (dob) {
            float2 bb = *(const float2*)(sB1 + 8 * j + 2 * lt);
            b0 = bb.x; b1v = bb.y;
        }
        const int r0 = brow + 16 * rowg + lg;
        const int r1 = r0 + 8;
        if (r0 < M)
            *(float2*)(Pab + (long long)r0 * 128 + col) =
                make_float2(acc[j][0] + b0, acc[j][1] + b1v);
        if (r1 < M)
            *(float2*)(Pab + (long long)r1 * 128 + col) =
                make_float2(acc[j][2] + b0, acc[j][3] + b1v);
    }
}

// ---------------- proj_dual: h = x@Win + bin; Pab = dual(h) --------------------
__global__ __launch_bounds__(256)
void proj_dual(const float* __restrict__ x, const float* __restrict__ Win,
               const float* __restrict__ bin,
               const float* __restrict__ W1n, const float* __restrict__ b1n,
               float* __restrict__ h, float* __restrict__ Pab, int M)
{
    __shared__ __align__(16) float    sA[32 * 64];
    __shared__ __align__(16) float    sW[32 * 136];
    __shared__ __align__(16) uint32_t sHT[64 * 68];
    __shared__ float sB1[64];

    const int tid  = threadIdx.x;
    const int brow = blockIdx.x * 64;
    const int cg = tid & 15, rg = tid >> 4;
    const int c0 = cg * 4,   r0 = rg * 4;

    const int lrow = tid >> 2;
    const int lcol = (tid & 3) * 4;
    const int grow = brow + lrow;
    const int kr = tid >> 4;
    const int wc = (tid & 15) * 4;

    float acc[4][4];
#pragma unroll
    for (int i = 0; i < 4; i++)
#pragma unroll
        for (int j = 0; j < 4; j++)
            acc[i][j] = bin[c0 + j];

    for (int kc = 0; kc < 128; kc += 32) {
#pragma unroll
        for (int q = 0; q < 2; q++) {
            const int col = lcol + 16 * q;
            float4 av = make_float4(0.f, 0.f, 0.f, 0.f);
            if (grow < M)
                av = *(const float4*)(x + (long long)grow * 128 + kc + col);
            sA[(col + 0) * 64 + lrow] = av.x;
            sA[(col + 1) * 64 + lrow] = av.y;
            sA[(col + 2) * 64 + lrow] = av.z;
            sA[(col + 3) * 64 + lrow] = av.w;
            *(float4*)&sW[(kr + 16 * q) * 64 + wc] =
                *(const float4*)(Win + (long long)(kc + kr + 16 * q) * 64 + wc);
        }
        __syncthreads();
#pragma unroll
        for (int kk = 0; kk < 32; kk++) {
            float4 a = *(const float4*)&sA[kk * 64 + r0];
            float4 w = *(const float4*)&sW[kk * 64 + c0];
            float ar[4] = {a.x, a.y, a.z, a.w};
            float wr[4] = {w.x, w.y, w.z, w.w};
#pragma unroll
            for (int i = 0; i < 4; i++)
#pragma unroll
                for (int j = 0; j < 4; j++)
                    acc[i][j] = fmaf(ar[i], wr[j], acc[i][j]);
        }
        __syncthreads();
    }

#pragma unroll
    for (int i = 0; i < 4; i++) {
        const int row = brow + r0 + i;
        const bool v = row < M;
        if (v)
            *(float4*)(h + (long long)row * 64 + c0) =
                make_float4(acc[i][0], acc[i][1], acc[i][2], acc[i][3]);
        uint4 t;
        t.x = f32_to_tf32(v ? acc[i][0] : 0.f);
        t.y = f32_to_tf32(v ? acc[i][1] : 0.f);
        t.z = f32_to_tf32(v ? acc[i][2] : 0.f);
        t.w = f32_to_tf32(v ? acc[i][3] : 0.f);
        *(uint4*)&sHT[(r0 + i) * 68 + c0] = t;
    }

    dual_phase_mma(sHT, (uint32_t*)sW, W1n, b1n, sB1, Pab, brow, M, tid);
}

// ---------------- update_dual: h += relu(relu([h|agg]U1+b1)U2+b2); dual --------
template <bool DO_DUAL>
__global__ __launch_bounds__(256)
void update_dual(const float* __restrict__ h_in, const float* __restrict__ U1,
                 const float* __restrict__ b1, const float* __restrict__ U2,
                 const float* __restrict__ b2, float* agg,
                 float* __restrict__ h_out,
                 const float* __restrict__ W1n, const float* __restrict__ b1n,
                 float* __restrict__ Pab, int M)
{
    __shared__ __align__(16) float sA [32 * 64];
    __shared__ __align__(16) float sW [32 * 136];
    __shared__ __align__(16) float sU1[64 * 68];
    __shared__ float sB1n[64];

    const int tid  = threadIdx.x;
    const int brow = blockIdx.x * 64;
    const int cg = tid & 15, rg = tid >> 4;
    const int c0 = cg * 4,   r0 = rg * 4;

    const int lrow = tid >> 2;
    const int lcol = (tid & 3) * 4;
    const int grow = brow + lrow;
    const int kr = tid >> 4;
    const int wc = (tid & 15) * 4;

    float acc[4][4];
#pragma unroll
    for (int i = 0; i < 4; i++)
#pragma unroll
        for (int j = 0; j < 4; j++)
            acc[i][j] = b1[c0 + j];

#pragma unroll
    for (int p = 0; p < 2; p++) {
        const float* A = p ? agg : h_in;
        const float* W = U1 + (long long)p * 64 * 64;
        for (int kc = 0; kc < 64; kc += 32) {
#pragma unroll
            for (int q = 0; q < 2; q++) {
                const int col = lcol + 16 * q;
                float4 av = make_float4(0.f, 0.f, 0.f, 0.f);
                if (grow < M) {
                    av = *(const float4*)(A + (long long)grow * 64 + kc + col);
                    if (p == 1)
                        *(float4*)(agg + (long long)grow * 64 + kc + col) =
                            make_float4(0.f, 0.f, 0.f, 0.f);
                }
                sA[(col + 0) * 64 + lrow] = av.x;
                sA[(col + 1) * 64 + lrow] = av.y;
                sA[(col + 2) * 64 + lrow] = av.z;
                sA[(col + 3) * 64 + lrow] = av.w;
                *(float4*)&sW[(kr + 16 * q) * 64 + wc] =
                    *(const float4*)(W + (long long)(kc + kr + 16 * q) * 64 + wc);
            }
            __syncthreads();
#pragma unroll
            for (int kk = 0; kk < 32; kk++) {
                float4 a = *(const float4*)&sA[kk * 64 + r0];
                float4 w = *(const float4*)&sW[kk * 64 + c0];
                float ar[4] = {a.x, a.y, a.z, a.w};
                float wr[4] = {w.x, w.y, w.z, w.w};
#pragma unroll
                for (int i = 0; i < 4; i++)
#pragma unroll
                    for (int j = 0; j < 4; j++)
                        acc[i][j] = fmaf(ar[i], wr[j], acc[i][j]);
            }
            __syncthreads();
        }
    }

#pragma unroll
    for (int i = 0; i < 4; i++)
#pragma unroll
        for (int j = 0; j < 4; j++)
            sU1[(c0 + j) * 68 + r0 + i] = fmaxf(acc[i][j], 0.0f);
    __syncthreads();

    float acc2[4][4];
#pragma unroll
    for (int i = 0; i < 4; i++)
#pragma unroll
        for (int j = 0; j < 4; j++)
            acc2[i][j] = b2[c0 + j];

    for (int kc = 0; kc < 64; kc += 32) {
#pragma unroll
        for (int q = 0; q < 2; q++)
            *(float4*)&sW[(kr + 16 * q) * 64 + wc] =
                *(const float4*)(U2 + (long long)(kc + kr + 16 * q) * 64 + wc);
        __syncthreads();
#pragma unroll
        for (int kk = 0; kk < 32; kk++) {
            float4 a = *(const float4*)&sU1[(kc + kk) * 68 + r0];
            float4 w = *(const float4*)&sW[kk * 64 + c0];
            float ar[4] = {a.x, a.y, a.z, a.w};
            float wr[4] = {w.x, w.y, w.z, w.w};
#pragma unroll
            for (int i = 0; i < 4; i++)
#pragma unroll
                for (int j = 0; j < 4; j++)
                    acc2[i][j] = fmaf(ar[i], wr[j], acc2[i][j]);
        }
        __syncthreads();
    }

    uint32_t* sHT = (uint32_t*)sU1;
#pragma unroll
    for (int i = 0; i < 4; i++) {
        const int row = brow + r0 + i;
        const bool v = row < M;
        float hn[4] = {0.f, 0.f, 0.f, 0.f};
        if (v) {
            float4 hh = *(const float4*)(h_out + (long long)row * 64 + c0);
            hn[0] = hh.x + fmaxf(acc2[i][0], 0.f);
            hn[1] = hh.y + fmaxf(acc2[i][1], 0.f);
            hn[2] = hh.z + fmaxf(acc2[i][2], 0.f);
            hn[3] = hh.w + fmaxf(acc2[i][3], 0.f);
            *(float4*)(h_out + (long long)row * 64 + c0) =
                make_float4(hn[0], hn[1], hn[2], hn[3]);
        }
        if (DO_DUAL) {
            uint4 t;
            t.x = f32_to_tf32(hn[0]); t.y = f32_to_tf32(hn[1]);
            t.z = f32_to_tf32(hn[2]); t.w = f32_to_tf32(hn[3]);
            *(uint4*)&sHT[(r0 + i) * 68 + c0] = t;
        }
    }

    if (DO_DUAL)
        dual_phase_mma(sHT, (uint32_t*)sW, W1n, b1n, sB1n, Pab, brow, M, tid);
}

// ---------------- edge kernel: 32-edge tiles, vectorized B, fragment scan ------
#define A_STRIDE 68
__global__ __launch_bounds__(256, 2)
void edge_kernel_mma(const float* __restrict__ Pab,
                     const float* __restrict__ W1c,   // 6 x 64
                     const float* __restrict__ W2,    // 64 x 64 (k x n)
                     const float* __restrict__ b2,    // 64
                     float* __restrict__ agg, int E)
{
    extern __shared__ __align__(16) char smem[];
    uint32_t* sA   = (uint32_t*)smem;                       // 8 warps x 32 x 68 (69632 B)
    uint32_t* sW2v = (uint32_t*)(smem + 69632);             // 64 x 104 words (26624 B)
    float*    sW1c = (float*)(smem + 96256);                // 6 x 64 (1536 B)
    float*    sB2  = (float*)(smem + 97792);                // 64 (256 B)

    const int tid = threadIdx.x;
    const int w   = tid >> 5;
    const int l   = tid & 31;

    // stage W2 (tf32) in vector-friendly layout: word k*104 + (n&7)*12 + (n>>3)
    for (int i = tid; i < 64 * 64; i += 256) {
        int k = i >> 6, n = i & 63;
        sW2v[k * 104 + (n & 7) * 12 + (n >> 3)] = f32_to_tf32(W2[i]);
    }
    for (int i = tid; i < 384; i += 256) sW1c[i] = W1c[i];
    if (tid < 64) sB2[tid] = b2[tid];
    __syncthreads();

    uint32_t* myA = sA + w * 32 * A_STRIDE;
    const int gw = blockIdx.x * 8 + w;
    const int nW = gridDim.x * 8;
    const int nChunks = (E + 31) >> 5;

    const int lg  = l >> 2;       // 0..7
    const int lt  = l & 3;        // 0..3
    const int er  = l >> 3;       // 0..3 (phase A: edge-in-quad)
    const int c4  = (l & 7) * 4;  // phase A col base

    // prefetch first record (lane l -> edge l of chunk)
    float4 p0 = make_float4(0.f, 0.f, 0.f, 0.f);
    float4 p1 = make_float4(0.f, 0.f, 0.f, __int_as_float(-1));
    if (gw < nChunks) {
        long long eg = ((long long)gw << 5) + l;
        if (eg < E) {
            const float* r = g_rec + eg * 8;
            p0 = *(const float4*)(r);
            p1 = *(const float4*)(r + 4);
        }
    }

    for (int ch = gw; ch < nChunks; ch += nW) {
        const long long e0 = (long long)ch << 5;

        const float ea0 = p0.x, ea1 = p0.y, ea2 = p0.z, ea3 = p0.w;
        const float ea4 = p1.x, ea5 = p1.y;
        const int src = __float_as_int(p1.z);
        const int dst = __float_as_int(p1.w);

        // prefetch next chunk's record
        {
            const int chn = ch + nW;
            p0 = make_float4(0.f, 0.f, 0.f, 0.f);
            p1 = make_float4(0.f, 0.f, 0.f, __int_as_float(-1));
            if (chn < nChunks) {
                long long eg = ((long long)chn << 5) + l;
                if (eg < E) {
                    const float* r = g_rec + eg * 8;
                    p0 = *(const float4*)(r);
                    p1 = *(const float4*)(r + 4);
                }
            }
        }

        // ---- phase A: m1 (32 edges: 8 passes of 4 edges x 8 lanes) ----
#pragma unroll
        for (int it = 0; it < 8; it++) {
            const int e = 4 * it + er;
            const int de = __shfl_sync(0xffffffffu, dst, e);
            const int se = __shfl_sync(0xffffffffu, src, e);
            float eq[6];
            eq[0] = __shfl_sync(0xffffffffu, ea0, e);
            eq[1] = __shfl_sync(0xffffffffu, ea1, e);
            eq[2] = __shfl_sync(0xffffffffu, ea2, e);
            eq[3] = __shfl_sync(0xffffffffu, ea3, e);
            eq[4] = __shfl_sync(0xffffffffu, ea4, e);
            eq[5] = __shfl_sync(0xffffffffu, ea5, e);
            const bool ev = (e0 + e) < E;
            const float* par = Pab + (long long)de * 128;
            const float* pbr = Pab + (long long)se * 128 + 64;
#pragma unroll
            for (int h = 0; h < 2; h++) {
                const int c = c4 + 32 * h;
                float v0 = 0.f, v1 = 0.f, v2 = 0.f, v3 = 0.f;
                if (ev) {
                    float4 a = *(const float4*)(par + c);
                    float4 b = *(const float4*)(pbr + c);
                    v0 = a.x + b.x; v1 = a.y + b.y; v2 = a.z + b.z; v3 = a.w + b.w;
#pragma unroll
                    for (int q = 0; q < 6; q++) {
                        float4 wv = *(const float4*)(sW1c + q * 64 + c);
                        v0 = fmaf(eq[q], wv.x, v0);
                        v1 = fmaf(eq[q], wv.y, v1);
                        v2 = fmaf(eq[q], wv.z, v2);
                        v3 = fmaf(eq[q], wv.w, v3);
                    }
                }
                uint32_t r0 = f32_to_tf32(fmaxf(v0, 0.f));
                uint32_t r1 = f32_to_tf32(fmaxf(v1, 0.f));
                uint32_t r2 = f32_to_tf32(fmaxf(v2, 0.f));
                uint32_t r3 = f32_to_tf32(fmaxf(v3, 0.f));
                *(uint4*)(myA + e * A_STRIDE + c) = make_uint4(r0, r1, r2, r3);
            }
        }
        __syncwarp();

        // ---- mma: D(32x64) = m1 @ W2 (vectorized B loads) ----
        float acc[2][8][4];
#pragma unroll
        for (int g = 0; g < 2; g++)
#pragma unroll
            for (int j = 0; j < 8; j++)
#pragma unroll
                for (int q = 0; q < 4; q++) acc[g][j][q] = 0.0f;

#pragma unroll
        for (int s = 0; s < 8; s++) {
            const int k0 = 8 * s;
            const uint32_t* bp = sW2v + (k0 + lt) * 104 + lg * 12;
            uint4 bA = *(const uint4*)(bp);
            uint4 bB = *(const uint4*)(bp + 4);
            uint4 bC = *(const uint4*)(bp + 4 * 104);
            uint4 bD = *(const uint4*)(bp + 4 * 104 + 4);
            uint32_t bf0[8] = {bA.x, bA.y, bA.z, bA.w, bB.x, bB.y, bB.z, bB.w};
            uint32_t bf1[8] = {bC.x, bC.y, bC.z, bC.w, bD.x, bD.y, bD.z, bD.w};
            uint32_t af[2][4];
#pragma unroll
            for (int g = 0; g < 2; g++) {
                const uint32_t* base = myA + (16 * g + lg) * A_STRIDE + k0 + lt;
                af[g][0] = base[0];
                af[g][1] = base[8 * A_STRIDE];
                af[g][2] = base[4];
                af[g][3] = base[8 * A_STRIDE + 4];
            }
#pragma unroll
            for (int g = 0; g < 2; g++)
#pragma unroll
                for (int j = 0; j < 8; j++) {
                    uint32_t bf[2] = {bf0[j], bf1[j]};
                    mma_tf32(acc[g][j], af[g], bf);
                }
        }
        __syncwarp();   // myA reads done before next chunk's phase A

        // ---- segmented reduction in fragment layout (32 edges) ----
        {
            const int dprev = __shfl_up_sync(0xffffffffu, dst, 1);
            const bool head = (l == 0) || (dprev != dst);
            const unsigned hm = __ballot_sync(0xffffffffu, head);

            int dmy[4]; bool vr[4], tl[4], cross[4]; int dd[4];
#pragma unroll
            for (int i = 0; i < 4; i++) {
                const int r = lg + 8 * i;
                dmy[i] = __shfl_sync(0xffffffffu, dst, r);
                vr[i] = (e0 + r) < E;
                const unsigned below = hm & (unsigned)((2ull << r) - 1ull);
                const int hs = 31 - __clz(below);
                const int dist = r - hs;
                dd[i] = dist < lg ? dist : lg;
                cross[i] = dist > lg;
                tl[i] = (r == 31) || (((hm >> (r + 1)) & 1u) != 0);
            }

            // bias + relu (+zero invalid rows)
#pragma unroll
            for (int j = 0; j < 8; j++) {
                float2 bb = *(const float2*)(sB2 + 8 * j + 2 * lt);
#pragma unroll
                for (int g = 0; g < 2; g++) {
                    acc[g][j][0] = vr[2 * g]     ? fmaxf(acc[g][j][0] + bb.x, 0.f) : 0.f;
                    acc[g][j][1] = vr[2 * g]     ? fmaxf(acc[g][j][1] + bb.y, 0.f) : 0.f;
                    acc[g][j][2] = vr[2 * g + 1] ? fmaxf(acc[g][j][2] + bb.x, 0.f) : 0.f;
                    acc[g][j][3] = vr[2 * g + 1] ? fmaxf(acc[g][j][3] + bb.y, 0.f) : 0.f;
                }
            }

            // intra-8-row segmented scans (3 steps, lanes stride 4)
#pragma unroll
            for (int s = 1; s < 8; s <<= 1) {
#pragma unroll
                for (int g = 0; g < 2; g++)
#pragma unroll
                    for (int j = 0; j < 8; j++) {
                        float y0 = __shfl_up_sync(0xffffffffu, acc[g][j][0], 4 * s);
                        float y1 = __shfl_up_sync(0xffffffffu, acc[g][j][1], 4 * s);
                        float y2 = __shfl_up_sync(0xffffffffu, acc[g][j][2], 4 * s);
                        float y3 = __shfl_up_sync(0xffffffffu, acc[g][j][3], 4 * s);
                        if (dd[2 * g]     >= s) { acc[g][j][0] += y0; acc[g][j][1] += y1; }
                        if (dd[2 * g + 1] >= s) { acc[g][j][2] += y2; acc[g][j][3] += y3; }
                    }
            }
            // serial boundary combines
#pragma unroll
            for (int j = 0; j < 8; j++) {
                float y0 = __shfl_sync(0xffffffffu, acc[0][j][0], 28 + lt);
                float y1 = __shfl_sync(0xffffffffu, acc[0][j][1], 28 + lt);
                if (cross[1]) { acc[0][j][2] += y0; acc[0][j][3] += y1; }
            }
#pragma unroll
            for (int j = 0; j < 8; j++) {
                float y0 = __shfl_sync(0xffffffffu, acc[0][j][2], 28 + lt);
                float y1 = __shfl_sync(0xffffffffu, acc[0][j][3], 28 + lt);
                if (cross[2]) { acc[1][j][0] += y0; acc[1][j][1] += y1; }
            }
#pragma unroll
            for (int j = 0; j < 8; j++) {
                float y0 = __shfl_sync(0xffffffffu, acc[1][j][0], 28 + lt);
                float y1 = __shfl_sync(0xffffffffu, acc[1][j][1], 28 + lt);
                if (cross[3]) { acc[1][j][2] += y0; acc[1][j][3] += y1; }
            }

            // emit tails
#pragma unroll
            for (int i = 0; i < 4; i++) {
                if (tl[i] && vr[i]) {
                    float* p = agg + (long long)dmy[i] * 64 + 2 * lt;
                    const int g = i >> 1, o = 2 * (i & 1);
#pragma unroll
                    for (int j = 0; j < 8; j++)
                        asm volatile("red.global.add.v2.f32 [%0], {%1, %2};"
                                     :: "l"(p + 8 * j),
                                        "f"(acc[g][j][o]), "f"(acc[g][j][o + 1])
                                     : "memory");
                }
            }
        }
    }
}

// ---------------- prediction head ---------------------------------------------
__global__ __launch_bounds__(256)
void pred_kernel(const float* __restrict__ h, const float* __restrict__ pw,
                 const float* __restrict__ pb, float* __restrict__ out, int M)
{
    __shared__ float spw[64];
    __shared__ float swarp[8];
    if (threadIdx.x < 64) spw[threadIdx.x] = pw[threadIdx.x];
    __syncthreads();

    float sum = 0.0f;
    for (long long row = (long long)blockIdx.x * blockDim.x + threadIdx.x; row < M;
         row += (long long)gridDim.x * blockDim.x) {
        const float4* hr = (const float4*)(h + row * 64);
#pragma unroll
        for (int u = 0; u < 16; u++) {
            float4 v = hr[u];
            sum = fmaf(v.x, spw[4 * u + 0], sum);
            sum = fmaf(v.y, spw[4 * u + 1], sum);
            sum = fmaf(v.z, spw[4 * u + 2], sum);
            sum = fmaf(v.w, spw[4 * u + 3], sum);
        }
    }
#pragma unroll
    for (int o = 16; o > 0; o >>= 1) sum += __shfl_down_sync(0xffffffffu, sum, o);
    if ((threadIdx.x & 31) == 0) swarp[threadIdx.x >> 5] = sum;
    __syncthreads();
    if (threadIdx.x < 8) {
        float s = swarp[threadIdx.x];
#pragma unroll
        for (int o = 4; o > 0; o >>= 1) s += __shfl_down_sync(0xffu, s, o);
        if (threadIdx.x == 0) {
            if (blockIdx.x == 0) s = fmaf(pb[0], (float)M, s);
            atomicAdd(out, s);
        }
    }
}

// ---------------- launch ------------------------------------------------------
extern "C" void kernel_launch(void* const* d_in, const int* in_sizes, int n_in,
                              void* d_out, int out_size)
{
    const float* x       = (const float*)d_in[0];
    const void*  ei      = d_in[1];
    const float* eattr   = (const float*)d_in[2];
    const float* lin_w   = (const float*)d_in[3];
    const float* lin_b   = (const float*)d_in[4];
    const float* msg_w1  = (const float*)d_in[5];
    const float* msg_b1  = (const float*)d_in[6];
    const float* msg_w2  = (const float*)d_in[7];
    const float* msg_b2  = (const float*)d_in[8];
    const float* upd_w1  = (const float*)d_in[9];
    const float* upd_b1  = (const float*)d_in[10];
    const float* upd_w2  = (const float*)d_in[11];
    const float* upd_b2  = (const float*)d_in[12];
    const float* pred_w  = (const float*)d_in[13];
    const float* pred_b  = (const float*)d_in[14];

    const int M = in_sizes[0] / 128;   // 50000
    const int E = in_sizes[2] / 6;     // 800000

    float *h, *Pab, *agg;
    int* cnt;
    cudaGetSymbolAddress((void**)&h,   g_h);
    cudaGetSymbolAddress((void**)&Pab, g_Pab);
    cudaGetSymbolAddress((void**)&agg, g_agg);
    cudaGetSymbolAddress((void**)&cnt, g_cnt);

    const int gN = (M + 63) / 64;      // 782
    const int SM_EDGE = 98048;
    cudaFuncSetAttribute(edge_kernel_mma,
                         cudaFuncAttributeMaxDynamicSharedMemorySize, SM_EDGE);
    const int nChunks = (E + 31) / 32;
    int gEdge = 148 * 2;
    if (gEdge * 8 > nChunks) gEdge = (nChunks + 7) / 8;
    if (gEdge < 1) gEdge = 1;

    // ---- sort edges by dst (once; reused by all 4 layers) ----
    detect_idx_kernel<<<1, 32>>>((const unsigned int*)ei);
    cudaMemsetAsync(cnt, 0, NSCAN * sizeof(int));
    hist_kernel<<<1024, 256>>>(ei, E);
    scan1_kernel<<<NSCAN / 1024, 1024>>>();
    scan3_kernel<<<NSCAN / 1024, 1024>>>();
    scatter_kernel<<<1024, 256>>>(ei, eattr, E);

    // input projection fused with layer-0 dual
    proj_dual<<<gN, 256>>>(x, lin_w, lin_b,
                           msg_w1, msg_b1, h, Pab, M);

    for (int l = 0; l < 4; l++) {
        const float* W1 = msg_w1 + (size_t)l * 134 * 64;
        edge_kernel_mma<<<gEdge, 256, SM_EDGE>>>(Pab,
                                                 W1 + 128 * 64,
                                                 msg_w2 + (size_t)l * 64 * 64,
                                                 msg_b2 + l * 64, agg, E);
        if (l < 3) {
            const float* W1n = msg_w1 + (size_t)(l + 1) * 134 * 64;
            update_dual<true><<<gN, 256>>>(h, upd_w1 + (size_t)l * 128 * 64,
                                           upd_b1 + l * 64,
                                           upd_w2 + (size_t)l * 64 * 64,
                                           upd_b2 + l * 64, agg, h,
                                           W1n, msg_b1 + (l + 1) * 64, Pab, M);
        } else {
            update_dual<false><<<gN, 256>>>(h, upd_w1 + (size_t)l * 128 * 64,
                                            upd_b1 + l * 64,
                                            upd_w2 + (size_t)l * 64 * 64,
                                            upd_b2 + l * 64, agg, h,
                                            nullptr, nullptr, nullptr, M);
        }
    }

    cudaMemsetAsync(d_out, 0, sizeof(float));
    pred_kernel<<<256, 256>>>(h, pred_w, pred_b, (float*)d_out, M);
}

// round 17
// speedup vs baseline: 1.3140x; 1.0067x over previous
#include <cuda_runtime.h>
#include <cstdint>

#define EMB 64
#define NN_MAX 50000
#define NSCAN 50176          // 49 * 1024
#define NE_MAX 800000
#define NE_PAD (NE_MAX + 64)

// ---------------- scratch (static device memory; no allocations) ----------------
__device__ __align__(128) float g_h  [NN_MAX * EMB];
__device__ __align__(128) float g_Pab[NN_MAX * 128];   // [Pa | Pb] per node
__device__ __align__(128) float g_agg[NN_MAX * EMB];   // zero at launch entry (invariant)
__device__ int g_is64;

// sort scratch
__device__ int   g_cnt [NSCAN];
__device__ int   g_inc [NSCAN];
__device__ int   g_cur [NSCAN];
__device__ int   g_bsum[64];
// packed sorted edge records: {ea0..ea5, src(bits), dst(bits)} per edge (32B)
__device__ __align__(128) float g_rec[NE_PAD * 8];

// ---------------- helpers ------------------------------------------------------
__device__ __forceinline__ uint32_t f32_to_tf32(float f) {
    uint32_t u;
    asm("cvt.rna.tf32.f32 %0, %1;" : "=r"(u) : "f"(f));
    return u;
}
__device__ __forceinline__ void mma_tf32(float* c, const uint32_t* a, const uint32_t* b) {
    asm volatile(
        "mma.sync.aligned.m16n8k8.row.col.f32.tf32.tf32.f32 "
        "{%0,%1,%2,%3}, {%4,%5,%6,%7}, {%8,%9}, {%0,%1,%2,%3};"
        : "+f"(c[0]), "+f"(c[1]), "+f"(c[2]), "+f"(c[3])
        : "r"(a[0]), "r"(a[1]), "r"(a[2]), "r"(a[3]), "r"(b[0]), "r"(b[1]));
}

// ---------------- detect whether edge_index is int64 or int32 ----------------
__global__ void detect_idx_kernel(const unsigned int* __restrict__ p)
{
    if (threadIdx.x == 0 && blockIdx.x == 0) {
        unsigned int v = 0;
#pragma unroll
        for (int k = 0; k < 64; k++) v |= p[2 * k + 1];
        g_is64 = (v == 0) ? 1 : 0;
    }
}

// ---------------- counting sort by dst ----------------------------------------
__global__ void hist_kernel(const void* __restrict__ ei, int E)
{
    const int is64 = g_is64;
    for (long long e = (long long)blockIdx.x * blockDim.x + threadIdx.x; e < E;
         e += (long long)gridDim.x * blockDim.x) {
        int dst = is64 ? (int)((const long long*)ei)[(long long)E + e]
                       : ((const int*)ei)[(long long)E + e];
        atomicAdd(&g_cnt[dst], 1);
    }
}

__global__ __launch_bounds__(1024) void scan1_kernel()
{
    const int t = threadIdx.x, b = blockIdx.x;
    const int i = b * 1024 + t;
    const int lane = t & 31, wid = t >> 5;
    int x = g_cnt[i];
#pragma unroll
    for (int s = 1; s < 32; s <<= 1) {
        int u = __shfl_up_sync(0xffffffffu, x, s);
        if (lane >= s) x += u;
    }
    __shared__ int ws[32];
    if (lane == 31) ws[wid] = x;
    __syncthreads();
    if (wid == 0) {
        int y = ws[lane];
#pragma unroll
        for (int s = 1; s < 32; s <<= 1) {
            int u = __shfl_up_sync(0xffffffffu, y, s);
            if (lane >= s) y += u;
        }
        ws[lane] = y;
    }
    __syncthreads();
    int inc = x + (wid ? ws[wid - 1] : 0);
    g_inc[i] = inc;
    if (t == 1023) g_bsum[b] = inc;
}

// scan3 with inline exclusive block-prefix (scan2 folded in)
__global__ __launch_bounds__(1024) void scan3_kernel()
{
    __shared__ int base;
    if (threadIdx.x == 0) {
        int s = 0;
        for (int j = 0; j < blockIdx.x; j++) s += g_bsum[j];
        base = s;
    }
    __syncthreads();
    const int i = blockIdx.x * 1024 + threadIdx.x;
    g_cur[i] = g_inc[i] - g_cnt[i] + base;
}

__global__ void scatter_kernel(const void* __restrict__ ei,
                               const float* __restrict__ eattr, int E)
{
    const int is64 = g_is64;
    for (long long e = (long long)blockIdx.x * blockDim.x + threadIdx.x; e < E;
         e += (long long)gridDim.x * blockDim.x) {
        int src, dst;
        if (is64) {
            src = (int)((const long long*)ei)[e];
            dst = (int)((const long long*)ei)[(long long)E + e];
        } else {
            src = ((const int*)ei)[e];
            dst = ((const int*)ei)[(long long)E + e];
        }
        float ea[6];
#pragma unroll
        for (int q = 0; q < 6; q++) ea[q] = eattr[e * 6 + q];
        int pos = atomicAdd(&g_cur[dst], 1);
        float* r = g_rec + (long long)pos * 8;
        *(float4*)(r)     = make_float4(ea[0], ea[1], ea[2], ea[3]);
        *(float4*)(r + 4) = make_float4(ea[4], ea[5],
                                        __int_as_float(src), __int_as_float(dst));
    }
}

// ---------------- dual phase (tf32 mma): Pab = [hT@W1a + b1 | hT@W1b] ----------
__device__ __forceinline__ void dual_phase_mma(const uint32_t* __restrict__ sHT,
                                               uint32_t* __restrict__ sWn,
                                               const float* __restrict__ W1n,
                                               const float* __restrict__ b1n,
                                               float* __restrict__ sB1,
                                               float* __restrict__ Pab,
                                               int brow, int M, int tid)
{
    const int w = tid >> 5, l = tid & 31;
    const int lg = l >> 2, lt = l & 3;
    const int rowg = w & 3, half = w >> 2;

    if (tid < 64) sB1[tid] = b1n[tid];

    float acc[8][4];
#pragma unroll
    for (int j = 0; j < 8; j++)
#pragma unroll
        for (int q = 0; q < 4; q++) acc[j][q] = 0.0f;

#pragma unroll
    for (int stage = 0; stage < 2; stage++) {
        const int kc = stage * 32;
        __syncthreads();
#pragma unroll
        for (int s4 = 0; s4 < 4; s4++) {
            const int f = tid * 4 + s4;
            const int kk = f >> 5;
            const int c4 = (f & 31) * 4;
            const float* src = (c4 < 64)
                ? (W1n + (long long)(kc + kk) * 64 + c4)
                : (W1n + (long long)(64 + kc + kk) * 64 + (c4 - 64));
            float4 v = *(const float4*)src;
            uint4 t;
            t.x = f32_to_tf32(v.x); t.y = f32_to_tf32(v.y);
            t.z = f32_to_tf32(v.z); t.w = f32_to_tf32(v.w);
            *(uint4*)&sWn[kk * 136 + c4] = t;
        }
        __syncthreads();
#pragma unroll
        for (int s = 0; s < 4; s++) {
            const int k0 = 8 * s;
            uint32_t af[4];
            const uint32_t* base = sHT + (16 * rowg + lg) * 68 + kc + k0 + lt;
            af[0] = base[0];
            af[1] = base[8 * 68];
            af[2] = base[4];
            af[3] = base[8 * 68 + 4];
#pragma unroll
            for (int j = 0; j < 8; j++) {
                uint32_t bf[2];
                bf[0] = sWn[(k0 + lt)     * 136 + 8 * j + lg + 64 * half];
                bf[1] = sWn[(k0 + lt + 4) * 136 + 8 * j + lg + 64 * half];
                mma_tf32(acc[j], af, bf);
            }
        }
    }

    const bool dob = (half == 0);
#pragma unroll
    for (int j = 0; j < 8; j++) {
        const int col = 64 * half + 8 * j + 2 * lt;
        float b0 = 0.f, b1v = 0.f;
        if (dob) {
            float2 bb = *(const float2*)(sB1 + 8 * j + 2 * lt);
            b0 = bb.x; b1v = bb.y;
        }
        const int r0 = brow + 16 * rowg + lg;
        const int r1 = r0 + 8;
        if (r0 < M)
            *(float2*)(Pab + (long long)r0 * 128 + col) =
                make_float2(acc[j][0] + b0, acc[j][1] + b1v);
        if (r1 < M)
            *(float2*)(Pab + (long long)r1 * 128 + col) =
                make_float2(acc[j][2] + b0, acc[j][3] + b1v);
    }
}

// ---------------- proj_dual: h = x@Win + bin; Pab = dual(h) --------------------
__global__ __launch_bounds__(256)
void proj_dual(const float* __restrict__ x, const float* __restrict__ Win,
               const float* __restrict__ bin,
               const float* __restrict__ W1n, const float* __restrict__ b1n,
               float* __restrict__ h, float* __restrict__ Pab, int M)
{
    __shared__ __align__(16) float    sA[32 * 64];
    __shared__ __align__(16) float    sW[32 * 136];
    __shared__ __align__(16) uint32_t sHT[64 * 68];
    __shared__ float sB1[64];

    const int tid  = threadIdx.x;
    const int brow = blockIdx.x * 64;
    const int cg = tid & 15, rg = tid >> 4;
    const int c0 = cg * 4,   r0 = rg * 4;

    const int lrow = tid >> 2;
    const int lcol = (tid & 3) * 4;
    const int grow = brow + lrow;
    const int kr = tid >> 4;
    const int wc = (tid & 15) * 4;

    float acc[4][4];
#pragma unroll
    for (int i = 0; i < 4; i++)
#pragma unroll
        for (int j = 0; j < 4; j++)
            acc[i][j] = bin[c0 + j];

    for (int kc = 0; kc < 128; kc += 32) {
#pragma unroll
        for (int q = 0; q < 2; q++) {
            const int col = lcol + 16 * q;
            float4 av = make_float4(0.f, 0.f, 0.f, 0.f);
            if (grow < M)
                av = *(const float4*)(x + (long long)grow * 128 + kc + col);
            sA[(col + 0) * 64 + lrow] = av.x;
            sA[(col + 1) * 64 + lrow] = av.y;
            sA[(col + 2) * 64 + lrow] = av.z;
            sA[(col + 3) * 64 + lrow] = av.w;
            *(float4*)&sW[(kr + 16 * q) * 64 + wc] =
                *(const float4*)(Win + (long long)(kc + kr + 16 * q) * 64 + wc);
        }
        __syncthreads();
#pragma unroll
        for (int kk = 0; kk < 32; kk++) {
            float4 a = *(const float4*)&sA[kk * 64 + r0];
            float4 w = *(const float4*)&sW[kk * 64 + c0];
            float ar[4] = {a.x, a.y, a.z, a.w};
            float wr[4] = {w.x, w.y, w.z, w.w};
#pragma unroll
            for (int i = 0; i < 4; i++)
#pragma unroll
                for (int j = 0; j < 4; j++)
                    acc[i][j] = fmaf(ar[i], wr[j], acc[i][j]);
        }
        __syncthreads();
    }

#pragma unroll
    for (int i = 0; i < 4; i++) {
        const int row = brow + r0 + i;
        const bool v = row < M;
        if (v)
            *(float4*)(h + (long long)row * 64 + c0) =
                make_float4(acc[i][0], acc[i][1], acc[i][2], acc[i][3]);
        uint4 t;
        t.x = f32_to_tf32(v ? acc[i][0] : 0.f);
        t.y = f32_to_tf32(v ? acc[i][1] : 0.f);
        t.z = f32_to_tf32(v ? acc[i][2] : 0.f);
        t.w = f32_to_tf32(v ? acc[i][3] : 0.f);
        *(uint4*)&sHT[(r0 + i) * 68 + c0] = t;
    }

    dual_phase_mma(sHT, (uint32_t*)sW, W1n, b1n, sB1, Pab, brow, M, tid);
}

// ---------------- update_dual: h += relu(relu([h|agg]U1+b1)U2+b2); dual --------
template <bool DO_DUAL>
__global__ __launch_bounds__(256)
void update_dual(const float* __restrict__ h_in, const float* __restrict__ U1,
                 const float* __restrict__ b1, const float* __restrict__ U2,
                 const float* __restrict__ b2, float* agg,
                 float* __restrict__ h_out,
                 const float* __restrict__ W1n, const float* __restrict__ b1n,
                 float* __restrict__ Pab, int M)
{
    __shared__ __align__(16) float sA [32 * 64];
    __shared__ __align__(16) float sW [32 * 136];
    __shared__ __align__(16) float sU1[64 * 68];
    __shared__ float sB1n[64];

    const int tid  = threadIdx.x;
    const int brow = blockIdx.x * 64;
    const int cg = tid & 15, rg = tid >> 4;
    const int c0 = cg * 4,   r0 = rg * 4;

    const int lrow = tid >> 2;
    const int lcol = (tid & 3) * 4;
    const int grow = brow + lrow;
    const int kr = tid >> 4;
    const int wc = (tid & 15) * 4;

    float acc[4][4];
#pragma unroll
    for (int i = 0; i < 4; i++)
#pragma unroll
        for (int j = 0; j < 4; j++)
            acc[i][j] = b1[c0 + j];

#pragma unroll
    for (int p = 0; p < 2; p++) {
        const float* A = p ? agg : h_in;
        const float* W = U1 + (long long)p * 64 * 64;
        for (int kc = 0; kc < 64; kc += 32) {
#pragma unroll
            for (int q = 0; q < 2; q++) {
                const int col = lcol + 16 * q;
                float4 av = make_float4(0.f, 0.f, 0.f, 0.f);
                if (grow < M) {
                    av = *(const float4*)(A + (long long)grow * 64 + kc + col);
                    if (p == 1)
                        *(float4*)(agg + (long long)grow * 64 + kc + col) =
                            make_float4(0.f, 0.f, 0.f, 0.f);
                }
                sA[(col + 0) * 64 + lrow] = av.x;
                sA[(col + 1) * 64 + lrow] = av.y;
                sA[(col + 2) * 64 + lrow] = av.z;
                sA[(col + 3) * 64 + lrow] = av.w;
                *(float4*)&sW[(kr + 16 * q) * 64 + wc] =
                    *(const float4*)(W + (long long)(kc + kr + 16 * q) * 64 + wc);
            }
            __syncthreads();
#pragma unroll
            for (int kk = 0; kk < 32; kk++) {
                float4 a = *(const float4*)&sA[kk * 64 + r0];
                float4 w = *(const float4*)&sW[kk * 64 + c0];
                float ar[4] = {a.x, a.y, a.z, a.w};
                float wr[4] = {w.x, w.y, w.z, w.w};
#pragma unroll
                for (int i = 0; i < 4; i++)
#pragma unroll
                    for (int j = 0; j < 4; j++)
                        acc[i][j] = fmaf(ar[i], wr[j], acc[i][j]);
            }
            __syncthreads();
        }
    }

#pragma unroll
    for (int i = 0; i < 4; i++)
#pragma unroll
        for (int j = 0; j < 4; j++)
            sU1[(c0 + j) * 68 + r0 + i] = fmaxf(acc[i][j], 0.0f);
    __syncthreads();

    float acc2[4][4];
#pragma unroll
    for (int i = 0; i < 4; i++)
#pragma unroll
        for (int j = 0; j < 4; j++)
            acc2[i][j] = b2[c0 + j];

    for (int kc = 0; kc < 64; kc += 32) {
#pragma unroll
        for (int q = 0; q < 2; q++)
            *(float4*)&sW[(kr + 16 * q) * 64 + wc] =
                *(const float4*)(U2 + (long long)(kc + kr + 16 * q) * 64 + wc);
        __syncthreads();
#pragma unroll
        for (int kk = 0; kk < 32; kk++) {
            float4 a = *(const float4*)&sU1[(kc + kk) * 68 + r0];
            float4 w = *(const float4*)&sW[kk * 64 + c0];
            float ar[4] = {a.x, a.y, a.z, a.w};
            float wr[4] = {w.x, w.y, w.z, w.w};
#pragma unroll
            for (int i = 0; i < 4; i++)
#pragma unroll
                for (int j = 0; j < 4; j++)
                    acc2[i][j] = fmaf(ar[i], wr[j], acc2[i][j]);
        }
        __syncthreads();
    }

    uint32_t* sHT = (uint32_t*)sU1;
#pragma unroll
    for (int i = 0; i < 4; i++) {
        const int row = brow + r0 + i;
        const bool v = row < M;
        float hn[4] = {0.f, 0.f, 0.f, 0.f};
        if (v) {
            float4 hh = *(const float4*)(h_out + (long long)row * 64 + c0);
            hn[0] = hh.x + fmaxf(acc2[i][0], 0.f);
            hn[1] = hh.y + fmaxf(acc2[i][1], 0.f);
            hn[2] = hh.z + fmaxf(acc2[i][2], 0.f);
            hn[3] = hh.w + fmaxf(acc2[i][3], 0.f);
            *(float4*)(h_out + (long long)row * 64 + c0) =
                make_float4(hn[0], hn[1], hn[2], hn[3]);
        }
        if (DO_DUAL) {
            uint4 t;
            t.x = f32_to_tf32(hn[0]); t.y = f32_to_tf32(hn[1]);
            t.z = f32_to_tf32(hn[2]); t.w = f32_to_tf32(hn[3]);
            *(uint4*)&sHT[(r0 + i) * 68 + c0] = t;
        }
    }

    if (DO_DUAL)
        dual_phase_mma(sHT, (uint32_t*)sW, W1n, b1n, sB1n, Pab, brow, M, tid);
}

// ---------------- edge kernel: batched gather, vectorized B, fragment scan -----
#define A_STRIDE 68
__global__ __launch_bounds__(256, 2)
void edge_kernel_mma(const float* __restrict__ Pab,
                     const float* __restrict__ W1c,   // 6 x 64
                     const float* __restrict__ W2,    // 64 x 64 (k x n)
                     const float* __restrict__ b2,    // 64
                     float* __restrict__ agg, int E)
{
    extern __shared__ __align__(16) char smem[];
    uint32_t* sA   = (uint32_t*)smem;                       // 8 warps x 32 x 68 (69632 B)
    uint32_t* sW2v = (uint32_t*)(smem + 69632);             // 64 x 104 words (26624 B)
    float*    sW1c = (float*)(smem + 96256);                // 6 x 64 (1536 B)
    float*    sB2  = (float*)(smem + 97792);                // 64 (256 B)

    const int tid = threadIdx.x;
    const int w   = tid >> 5;
    const int l   = tid & 31;

    for (int i = tid; i < 64 * 64; i += 256) {
        int k = i >> 6, n = i & 63;
        sW2v[k * 104 + (n & 7) * 12 + (n >> 3)] = f32_to_tf32(W2[i]);
    }
    for (int i = tid; i < 384; i += 256) sW1c[i] = W1c[i];
    if (tid < 64) sB2[tid] = b2[tid];
    __syncthreads();

    uint32_t* myA = sA + w * 32 * A_STRIDE;
    const int gw = blockIdx.x * 8 + w;
    const int nW = gridDim.x * 8;
    const int nChunks = (E + 31) >> 5;

    const int lg  = l >> 2;       // 0..7
    const int lt  = l & 3;        // 0..3
    const int er  = l >> 3;       // 0..3 (phase A: edge-in-quad)
    const int c4  = (l & 7) * 4;  // phase A col base

    // prefetch first record (lane l -> edge l of chunk)
    float4 p0 = make_float4(0.f, 0.f, 0.f, 0.f);
    float4 p1 = make_float4(0.f, 0.f, 0.f, __int_as_float(-1));
    if (gw < nChunks) {
        long long eg = ((long long)gw << 5) + l;
        if (eg < E) {
            const float* r = g_rec + eg * 8;
            p0 = *(const float4*)(r);
            p1 = *(const float4*)(r + 4);
        }
    }

    for (int ch = gw; ch < nChunks; ch += nW) {
        const long long e0 = (long long)ch << 5;

        const float ea0 = p0.x, ea1 = p0.y, ea2 = p0.z, ea3 = p0.w;
        const float ea4 = p1.x, ea5 = p1.y;
        const int src = __float_as_int(p1.z);
        const int dst = __float_as_int(p1.w);

        // prefetch next chunk's record
        {
            const int chn = ch + nW;
            p0 = make_float4(0.f, 0.f, 0.f, 0.f);
            p1 = make_float4(0.f, 0.f, 0.f, __int_as_float(-1));
            if (chn < nChunks) {
                long long eg = ((long long)chn << 5) + l;
                if (eg < E) {
                    const float* r = g_rec + eg * 8;
                    p0 = *(const float4*)(r);
                    p1 = *(const float4*)(r + 4);
                }
            }
        }

        // ---- phase A: m1, 2 batches of 4 its; all 16 gathers issued up front --
#pragma unroll
        for (int b = 0; b < 2; b++) {
            float4 ld[4][4];   // [u][par_h0, pbr_h0, par_h1, pbr_h1]
#pragma unroll
            for (int u = 0; u < 4; u++) {
                const int e = 4 * (4 * b + u) + er;
                const bool ev = (e0 + e) < E;
                int de = __shfl_sync(0xffffffffu, dst, e);
                int se = __shfl_sync(0xffffffffu, src, e);
                de = ev ? de : 0;
                se = ev ? se : 0;
                const float* par = Pab + (long long)de * 128;
                const float* pbr = Pab + (long long)se * 128 + 64;
                ld[u][0] = *(const float4*)(par + c4);
                ld[u][1] = *(const float4*)(pbr + c4);
                ld[u][2] = *(const float4*)(par + c4 + 32);
                ld[u][3] = *(const float4*)(pbr + c4 + 32);
            }
#pragma unroll
            for (int u = 0; u < 4; u++) {
                const int e = 4 * (4 * b + u) + er;
                const bool ev = (e0 + e) < E;
                float eq[6];
                eq[0] = __shfl_sync(0xffffffffu, ea0, e);
                eq[1] = __shfl_sync(0xffffffffu, ea1, e);
                eq[2] = __shfl_sync(0xffffffffu, ea2, e);
                eq[3] = __shfl_sync(0xffffffffu, ea3, e);
                eq[4] = __shfl_sync(0xffffffffu, ea4, e);
                eq[5] = __shfl_sync(0xffffffffu, ea5, e);
#pragma unroll
                for (int h = 0; h < 2; h++) {
                    const int c = c4 + 32 * h;
                    float v0 = 0.f, v1 = 0.f, v2 = 0.f, v3 = 0.f;
                    if (ev) {
                        float4 a = ld[u][2 * h];
                        float4 bb = ld[u][2 * h + 1];
                        v0 = a.x + bb.x; v1 = a.y + bb.y;
                        v2 = a.z + bb.z; v3 = a.w + bb.w;
#pragma unroll
                        for (int q = 0; q < 6; q++) {
                            float4 wv = *(const float4*)(sW1c + q * 64 + c);
                            v0 = fmaf(eq[q], wv.x, v0);
                            v1 = fmaf(eq[q], wv.y, v1);
                            v2 = fmaf(eq[q], wv.z, v2);
                            v3 = fmaf(eq[q], wv.w, v3);
                        }
                    }
                    uint32_t r0 = f32_to_tf32(fmaxf(v0, 0.f));
                    uint32_t r1 = f32_to_tf32(fmaxf(v1, 0.f));
                    uint32_t r2 = f32_to_tf32(fmaxf(v2, 0.f));
                    uint32_t r3 = f32_to_tf32(fmaxf(v3, 0.f));
                    *(uint4*)(myA + e * A_STRIDE + c) = make_uint4(r0, r1, r2, r3);
                }
            }
        }
        __syncwarp();

        // ---- mma: D(32x64) = m1 @ W2 (vectorized B loads) ----
        float acc[2][8][4];
#pragma unroll
        for (int g = 0; g < 2; g++)
#pragma unroll
            for (int j = 0; j < 8; j++)
#pragma unroll
                for (int q = 0; q < 4; q++) acc[g][j][q] = 0.0f;

#pragma unroll
        for (int s = 0; s < 8; s++) {
            const int k0 = 8 * s;
            const uint32_t* bp = sW2v + (k0 + lt) * 104 + lg * 12;
            uint4 bA = *(const uint4*)(bp);
            uint4 bB = *(const uint4*)(bp + 4);
            uint4 bC = *(const uint4*)(bp + 4 * 104);
            uint4 bD = *(const uint4*)(bp + 4 * 104 + 4);
            uint32_t bf0[8] = {bA.x, bA.y, bA.z, bA.w, bB.x, bB.y, bB.z, bB.w};
            uint32_t bf1[8] = {bC.x, bC.y, bC.z, bC.w, bD.x, bD.y, bD.z, bD.w};
            uint32_t af[2][4];
#pragma unroll
            for (int g = 0; g < 2; g++) {
                const uint32_t* base = myA + (16 * g + lg) * A_STRIDE + k0 + lt;
                af[g][0] = base[0];
                af[g][1] = base[8 * A_STRIDE];
                af[g][2] = base[4];
                af[g][3] = base[8 * A_STRIDE + 4];
            }
#pragma unroll
            for (int g = 0; g < 2; g++)
#pragma unroll
                for (int j = 0; j < 8; j++) {
                    uint32_t bf[2] = {bf0[j], bf1[j]};
                    mma_tf32(acc[g][j], af[g], bf);
                }
        }
        __syncwarp();   // myA reads done before next chunk's phase A

        // ---- segmented reduction in fragment layout (32 edges) ----
        {
            const int dprev = __shfl_up_sync(0xffffffffu, dst, 1);
            const bool head = (l == 0) || (dprev != dst);
            const unsigned hm = __ballot_sync(0xffffffffu, head);

            int dmy[4]; bool vr[4], tl[4], cross[4]; int dd[4];
#pragma unroll
            for (int i = 0; i < 4; i++) {
                const int r = lg + 8 * i;
                dmy[i] = __shfl_sync(0xffffffffu, dst, r);
                vr[i] = (e0 + r) < E;
                const unsigned below = hm & (unsigned)((2ull << r) - 1ull);
                const int hs = 31 - __clz(below);
                const int dist = r - hs;
                dd[i] = dist < lg ? dist : lg;
                cross[i] = dist > lg;
                tl[i] = (r == 31) || (((hm >> (r + 1)) & 1u) != 0);
            }

            // bias + relu (+zero invalid rows)
#pragma unroll
            for (int j = 0; j < 8; j++) {
                float2 bb = *(const float2*)(sB2 + 8 * j + 2 * lt);
#pragma unroll
                for (int g = 0; g < 2; g++) {
                    acc[g][j][0] = vr[2 * g]     ? fmaxf(acc[g][j][0] + bb.x, 0.f) : 0.f;
                    acc[g][j][1] = vr[2 * g]     ? fmaxf(acc[g][j][1] + bb.y, 0.f) : 0.f;
                    acc[g][j][2] = vr[2 * g + 1] ? fmaxf(acc[g][j][2] + bb.x, 0.f) : 0.f;
                    acc[g][j][3] = vr[2 * g + 1] ? fmaxf(acc[g][j][3] + bb.y, 0.f) : 0.f;
                }
            }

            // intra-8-row segmented scans (3 steps, lanes stride 4)
#pragma unroll
            for (int s = 1; s < 8; s <<= 1) {
#pragma unroll
                for (int g = 0; g < 2; g++)
#pragma unroll
                    for (int j = 0; j < 8; j++) {
                        float y0 = __shfl_up_sync(0xffffffffu, acc[g][j][0], 4 * s);
                        float y1 = __shfl_up_sync(0xffffffffu, acc[g][j][1], 4 * s);
                        float y2 = __shfl_up_sync(0xffffffffu, acc[g][j][2], 4 * s);
                        float y3 = __shfl_up_sync(0xffffffffu, acc[g][j][3], 4 * s);
                        if (dd[2 * g]     >= s) { acc[g][j][0] += y0; acc[g][j][1] += y1; }
                        if (dd[2 * g + 1] >= s) { acc[g][j][2] += y2; acc[g][j][3] += y3; }
                    }
            }
            // serial boundary combines
#pragma unroll
            for (int j = 0; j < 8; j++) {
                float y0 = __shfl_sync(0xffffffffu, acc[0][j][0], 28 + lt);
                float y1 = __shfl_sync(0xffffffffu, acc[0][j][1], 28 + lt);
                if (cross[1]) { acc[0][j][2] += y0; acc[0][j][3] += y1; }
            }
#pragma unroll
            for (int j = 0; j < 8; j++) {
                float y0 = __shfl_sync(0xffffffffu, acc[0][j][2], 28 + lt);
                float y1 = __shfl_sync(0xffffffffu, acc[0][j][3], 28 + lt);
                if (cross[2]) { acc[1][j][0] += y0; acc[1][j][1] += y1; }
            }
#pragma unroll
            for (int j = 0; j < 8; j++) {
                float y0 = __shfl_sync(0xffffffffu, acc[1][j][0], 28 + lt);
                float y1 = __shfl_sync(0xffffffffu, acc[1][j][1], 28 + lt);
                if (cross[3]) { acc[1][j][2] += y0; acc[1][j][3] += y1; }
            }

            // emit tails
#pragma unroll
            for (int i = 0; i < 4; i++) {
                if (tl[i] && vr[i]) {
                    float* p = agg + (long long)dmy[i] * 64 + 2 * lt;
                    const int g = i >> 1, o = 2 * (i & 1);
#pragma unroll
                    for (int j = 0; j < 8; j++)
                        asm volatile("red.global.add.v2.f32 [%0], {%1, %2};"
                                     :: "l"(p + 8 * j),
                                        "f"(acc[g][j][o]), "f"(acc[g][j][o + 1])
                                     : "memory");
                }
            }
        }
    }
}

// ---------------- prediction head ---------------------------------------------
__global__ __launch_bounds__(256)
void pred_kernel(const float* __restrict__ h, const float* __restrict__ pw,
                 const float* __restrict__ pb, float* __restrict__ out, int M)
{
    __shared__ float spw[64];
    __shared__ float swarp[8];
    if (threadIdx.x < 64) spw[threadIdx.x] = pw[threadIdx.x];
    __syncthreads();

    float sum = 0.0f;
    for (long long row = (long long)blockIdx.x * blockDim.x + threadIdx.x; row < M;
         row += (long long)gridDim.x * blockDim.x) {
        const float4* hr = (const float4*)(h + row * 64);
#pragma unroll
        for (int u = 0; u < 16; u++) {
            float4 v = hr[u];
            sum = fmaf(v.x, spw[4 * u + 0], sum);
            sum = fmaf(v.y, spw[4 * u + 1], sum);
            sum = fmaf(v.z, spw[4 * u + 2], sum);
            sum = fmaf(v.w, spw[4 * u + 3], sum);
        }
    }
#pragma unroll
    for (int o = 16; o > 0; o >>= 1) sum += __shfl_down_sync(0xffffffffu, sum, o);
    if ((threadIdx.x & 31) == 0) swarp[threadIdx.x >> 5] = sum;
    __syncthreads();
    if (threadIdx.x < 8) {
        float s = swarp[threadIdx.x];
#pragma unroll
        for (int o = 4; o > 0; o >>= 1) s += __shfl_down_sync(0xffu, s, o);
        if (threadIdx.x == 0) {
            if (blockIdx.x == 0) s = fmaf(pb[0], (float)M, s);
            atomicAdd(out, s);
        }
    }
}

// ---------------- launch ------------------------------------------------------
extern "C" void kernel_launch(void* const* d_in, const int* in_sizes, int n_in,
                              void* d_out, int out_size)
{
    const float* x       = (const float*)d_in[0];
    const void*  ei      = d_in[1];
    const float* eattr   = (const float*)d_in[2];
    const float* lin_w   = (const float*)d_in[3];
    const float* lin_b   = (const float*)d_in[4];
    const float* msg_w1  = (const float*)d_in[5];
    const float* msg_b1  = (const float*)d_in[6];
    const float* msg_w2  = (const float*)d_in[7];
    const float* msg_b2  = (const float*)d_in[8];
    const float* upd_w1  = (const float*)d_in[9];
    const float* upd_b1  = (const float*)d_in[10];
    const float* upd_w2  = (const float*)d_in[11];
    const float* upd_b2  = (const float*)d_in[12];
    const float* pred_w  = (const float*)d_in[13];
    const float* pred_b  = (const float*)d_in[14];

    const int M = in_sizes[0] / 128;   // 50000
    const int E = in_sizes[2] / 6;     // 800000

    float *h, *Pab, *agg;
    int* cnt;
    cudaGetSymbolAddress((void**)&h,   g_h);
    cudaGetSymbolAddress((void**)&Pab, g_Pab);
    cudaGetSymbolAddress((void**)&agg, g_agg);
    cudaGetSymbolAddress((void**)&cnt, g_cnt);

    const int gN = (M + 63) / 64;      // 782
    const int SM_EDGE = 98048;
    cudaFuncSetAttribute(edge_kernel_mma,
                         cudaFuncAttributeMaxDynamicSharedMemorySize, SM_EDGE);
    const int nChunks = (E + 31) / 32;
    int gEdge = 148 * 2;
    if (gEdge * 8 > nChunks) gEdge = (nChunks + 7) / 8;
    if (gEdge < 1) gEdge = 1;

    // ---- sort edges by dst (once; reused by all 4 layers) ----
    detect_idx_kernel<<<1, 32>>>((const unsigned int*)ei);
    cudaMemsetAsync(cnt, 0, NSCAN * sizeof(int));
    hist_kernel<<<1024, 256>>>(ei, E);
    scan1_kernel<<<NSCAN / 1024, 1024>>>();
    scan3_kernel<<<NSCAN / 1024, 1024>>>();
    scatter_kernel<<<1024, 256>>>(ei, eattr, E);

    // input projection fused with layer-0 dual
    proj_dual<<<gN, 256>>>(x, lin_w, lin_b,
                           msg_w1, msg_b1, h, Pab, M);

    for (int l = 0; l < 4; l++) {
        const float* W1 = msg_w1 + (size_t)l * 134 * 64;
        edge_kernel_mma<<<gEdge, 256, SM_EDGE>>>(Pab,
                                                 W1 + 128 * 64,
                                                 msg_w2 + (size_t)l * 64 * 64,
                                                 msg_b2 + l * 64, agg, E);
        if (l < 3) {
            const float* W1n = msg_w1 + (size_t)(l + 1) * 134 * 64;
            update_dual<true><<<gN, 256>>>(h, upd_w1 + (size_t)l * 128 * 64,
                                           upd_b1 + l * 64,
                                           upd_w2 + (size_t)l * 64 * 64,
                                           upd_b2 + l * 64, agg, h,
                                           W1n, msg_b1 + (l + 1) * 64, Pab, M);
        } else {
            update_dual<false><<<gN, 256>>>(h, upd_w1 + (size_t)l * 128 * 64,
                                            upd_b1 + l * 64,
                                            upd_w2 + (size_t)l * 64 * 64,
                                            upd_b2 + l * 64, agg, h,
                                            nullptr, nullptr, nullptr, M);
        }
    }

    cudaMemsetAsync(d_out, 0, sizeof(float));
    pred_kernel<<<256, 256>>>(h, pred_w, pred_b, (float*)d_out, M);
}